// round 7
// baseline (speedup 1.0000x reference)
#include <cuda_runtime.h>
#include <math.h>
#include <stdint.h>

#define HDIM 128
#define WDIM 128
#define HW (HDIM*WDIM)
#define CDIM 256
#define BDIM 4
#define NHEAD 16
#define EPS 1e-5f

// ---------------- scratch ----------------------------------------------------
__device__ float g_qh  [BDIM*CDIM*HW];
__device__ float g_kh  [BDIM*CDIM*HW];
__device__ float g_high[BDIM*CDIM*HW];
__device__ float g_qkv [BDIM*3*CDIM*HW];
__device__ float g_low [BDIM*CDIM*HW];
__device__ float g_mix [BDIM*CDIM*HW];
__device__ float g_sm  [BDIM*CDIM*HW];
__device__ float g_dw  [BDIM*CDIM*HW];
__device__ float g_pool[BDIM*2*HW];
__device__ float g_sig [BDIM*2*HW];
// pre-rounded / transformed operands
__device__ float g_xr  [BDIM*CDIM*HW];
__device__ float g_w5t [CDIM*CDIM*25];
__device__ float g_w3t [CDIM*CDIM*9];
__device__ float g_wq  [3*CDIM*CDIM];
__device__ float g_w2  [CDIM*CDIM];
__device__ float g_wp  [CDIM*CDIM];

// ---------------- tf32 / cp.async helpers ------------------------------------
__device__ __forceinline__ float f2tf(float f) {
    uint32_t u;
    asm("cvt.rna.tf32.f32 %0, %1;" : "=r"(u) : "f"(f));
    return __uint_as_float(u);
}

__device__ __forceinline__ void cp16(float* dst, const float* src) {
    uint32_t d = (uint32_t)__cvta_generic_to_shared(dst);
    asm volatile("cp.async.cg.shared.global [%0], [%1], 16;" :: "r"(d), "l"(src));
}
__device__ __forceinline__ void cp4z(float* dst, const float* src, bool pred) {
    uint32_t d = (uint32_t)__cvta_generic_to_shared(dst);
    int sz = pred ? 4 : 0;
    asm volatile("cp.async.ca.shared.global [%0], [%1], 4, %2;" :: "r"(d), "l"(src), "r"(sz));
}
__device__ __forceinline__ void cp_commit() {
    asm volatile("cp.async.commit_group;");
}
__device__ __forceinline__ void cp_wait1() {
    asm volatile("cp.async.wait_group 1;");
}

__device__ __forceinline__ void mma_tf32(float* d, uint32_t a0, uint32_t a1,
                                         uint32_t a2, uint32_t a3,
                                         uint32_t b0, uint32_t b1) {
    asm volatile(
        "mma.sync.aligned.m16n8k8.row.col.f32.tf32.tf32.f32 "
        "{%0,%1,%2,%3}, {%4,%5,%6,%7}, {%8,%9}, {%0,%1,%2,%3};"
        : "+f"(d[0]), "+f"(d[1]), "+f"(d[2]), "+f"(d[3])
        : "r"(a0), "r"(a1), "r"(a2), "r"(a3), "r"(b0), "r"(b1));
}

// ---------------- pre-pass kernels -------------------------------------------
__global__ void round_copy(const float* __restrict__ in, float* __restrict__ out, int n)
{
    int i = blockIdx.x * 256 + threadIdx.x;
    if (i < n) out[i] = f2tf(in[i]);
}

template<int KKS>
__global__ void wtransform(const float* __restrict__ wgt, float* __restrict__ dst)
{
    int tid = blockIdx.x * 256 + threadIdx.x;
    int total = 4 * 32 * KKS * 512;
    if (tid >= total) return;
    int ic  = tid & 7;
    int oc  = (tid >> 3) & 63;
    int tap = (tid >> 9) % KKS;
    int ics = (tid / (512 * KKS)) & 31;
    int ocT = tid / (512 * KKS * 32);
    dst[tid] = f2tf(wgt[((size_t)((ocT * 64 + oc) * 256 + ics * 8 + ic)) * KKS + tap]);
}

// ---------------- 1x1 conv as tf32 GEMM, cp.async double-buffered ------------
#define XSTR 264
#define WSTR 36
#define GEM_XF (32*XSTR)
#define GEM_WF (64*WSTR)
#define GEM_STG (GEM_XF+GEM_WF)

__global__ __launch_bounds__(256, 2)
void gemm1x1_mma(const float* __restrict__ in, const float* __restrict__ w,
                 const float* __restrict__ bng, const float* __restrict__ bnb,
                 const float* __restrict__ bnm, const float* __restrict__ bnv,
                 float* __restrict__ out, int OC)
{
    extern __shared__ float smem[];

    const int bb  = blockIdx.z;
    const int ocT = blockIdx.y;
    const int p0  = blockIdx.x * 256;
    const int t   = threadIdx.x;
    const int warp = t >> 5, lane = t & 31;
    const int g = lane >> 2, tg = lane & 3;
    const int wm = warp >> 2;
    const int wn = warp & 3;

    const float* inb = in + (size_t)bb * CDIM * HW;

    auto load = [&](int s, int ic0) {
        float* sX = smem + s * GEM_STG;
        float* sW = sX + GEM_XF;
#pragma unroll
        for (int j = 0; j < 8; j++) {
            int idx = j * 256 + t;
            int ic = idx >> 6, px4 = idx & 63;
            cp16(&sX[ic * XSTR + px4 * 4], &inb[(ic0 + ic) * HW + p0 + px4 * 4]);
        }
#pragma unroll
        for (int j = 0; j < 2; j++) {
            int idx = j * 256 + t;
            int oc = idx >> 3, icq = idx & 7;
            cp16(&sW[oc * WSTR + icq * 4], &w[(size_t)(ocT * 64 + oc) * CDIM + ic0 + icq * 4]);
        }
    };

    float acc[2][8][4];
#pragma unroll
    for (int i = 0; i < 2; i++)
#pragma unroll
        for (int j = 0; j < 8; j++)
#pragma unroll
            for (int c = 0; c < 4; c++) acc[i][j][c] = 0.f;

    load(0, 0);
    cp_commit();

    for (int ic0 = 0; ic0 < CDIM; ic0 += 32) {
        int cur = (ic0 >> 5) & 1;
        if (ic0 + 32 < CDIM) load(cur ^ 1, ic0 + 32);
        cp_commit();
        cp_wait1();
        __syncthreads();

        float* sX = smem + cur * GEM_STG;
        float* sW = sX + GEM_XF;
#pragma unroll
        for (int ks = 0; ks < 4; ks++) {
            int kk = ks * 8;
            uint32_t a[2][4];
#pragma unroll
            for (int i = 0; i < 2; i++) {
                int row = wm * 32 + i * 16 + g;
                a[i][0] = __float_as_uint(sW[row * WSTR + kk + tg]);
                a[i][1] = __float_as_uint(sW[(row + 8) * WSTR + kk + tg]);
                a[i][2] = __float_as_uint(sW[row * WSTR + kk + tg + 4]);
                a[i][3] = __float_as_uint(sW[(row + 8) * WSTR + kk + tg + 4]);
            }
#pragma unroll
            for (int j = 0; j < 8; j++) {
                int px = wn * 64 + j * 8 + g;
                uint32_t b0 = __float_as_uint(sX[(kk + tg) * XSTR + px]);
                uint32_t b1 = __float_as_uint(sX[(kk + tg + 4) * XSTR + px]);
                mma_tf32(acc[0][j], a[0][0], a[0][1], a[0][2], a[0][3], b0, b1);
                mma_tf32(acc[1][j], a[1][0], a[1][1], a[1][2], a[1][3], b0, b1);
            }
        }
        __syncthreads();
    }

#pragma unroll
    for (int i = 0; i < 2; i++) {
        int oc_lo = ocT * 64 + wm * 32 + i * 16 + g;
        int oc_hi = oc_lo + 8;
        float sc0 = 1.f, sh0 = 0.f, sc1 = 1.f, sh1 = 0.f;
        if (bng) {
            sc0 = bng[oc_lo] * rsqrtf(bnv[oc_lo] + EPS); sh0 = bnb[oc_lo] - bnm[oc_lo] * sc0;
            sc1 = bng[oc_hi] * rsqrtf(bnv[oc_hi] + EPS); sh1 = bnb[oc_hi] - bnm[oc_hi] * sc1;
        }
#pragma unroll
        for (int j = 0; j < 8; j++) {
            int px = p0 + wn * 64 + j * 8 + 2 * tg;
            float* o0 = &out[((size_t)bb * OC + oc_lo) * HW + px];
            float* o1 = &out[((size_t)bb * OC + oc_hi) * HW + px];
            o0[0] = acc[i][j][0] * sc0 + sh0;
            o0[1] = acc[i][j][1] * sc0 + sh0;
            o1[0] = acc[i][j][2] * sc1 + sh1;
            o1[1] = acc[i][j][3] * sc1 + sh1;
        }
    }
}

// ---------------- KxK conv via tf32 MMA, 8h x 64w tile, double-buffered ------
// weights pre-transformed: [(ocT*32+ics)*KKS + tap][64oc*8ic] contiguous
// ky loop deliberately NOT unrolled (compile-pressure cap).
template<int KS, bool ADD_HIGH>
__global__ __launch_bounds__(256, 1)
void conv_mma(const float* __restrict__ in, const float* __restrict__ wt,
              const float* __restrict__ bng, const float* __restrict__ bnb,
              const float* __restrict__ bnm, const float* __restrict__ bnv,
              float* __restrict__ out,
              const float* __restrict__ khbuf, float* __restrict__ out2)
{
    constexpr int PAD = KS / 2;
    constexpr int TW = 64;
    constexpr int PH = 8 + KS - 1;
    constexpr int PW = TW + KS - 1;
    constexpr int PWS = (KS == 5) ? 70 : 68;   // PH*PWS % 32 == 8
    constexpr int KKS = KS * KS;
    constexpr int PATCHF = 8 * PH * PWS;
    constexpr int WGTF = KKS * 512;
    constexpr int STG = PATCHF + WGTF;

    extern __shared__ float smem[];

    const int w0 = blockIdx.x * TW;
    const int h0 = blockIdx.y * 8;
    const int bb  = blockIdx.z >> 2;
    const int ocT = blockIdx.z & 3;
    const int t = threadIdx.x;
    const int warp = t >> 5, lane = t & 31;
    const int g = lane >> 2, tg = lane & 3;
    const int wm = warp >> 2;
    const int wn = warp & 3;

    auto load = [&](int s, int ic0) {
        float* sP = smem + s * STG;
        float* sW = sP + PATCHF;
        for (int e = t; e < 8 * PH * PW; e += 256) {
            int ic = e / (PH * PW), rem = e % (PH * PW);
            int row = rem / PW, cc = rem % PW;
            int h = h0 + row - PAD, w = w0 + cc - PAD;
            bool ok = ((unsigned)h < HDIM) && ((unsigned)w < WDIM);
            const float* src = in + ((size_t)(bb * CDIM + ic0 + ic) * HDIM + (ok ? h : 0)) * WDIM + (ok ? w : 0);
            cp4z(&sP[ic * PH * PWS + row * PWS + cc], src, ok);
        }
        const float* base = wt + (size_t)(ocT * 32 + (ic0 >> 3)) * WGTF;
        for (int e = t * 4; e < WGTF; e += 1024)
            cp16(&sW[e], &base[e]);
    };

    float acc[2][16][4];
#pragma unroll
    for (int i = 0; i < 2; i++)
#pragma unroll
        for (int j = 0; j < 16; j++)
#pragma unroll
            for (int c = 0; c < 4; c++) acc[i][j][c] = 0.f;

    load(0, 0);
    cp_commit();

    for (int ic0 = 0; ic0 < CDIM; ic0 += 8) {
        int cur = (ic0 >> 3) & 1;
        if (ic0 + 8 < CDIM) load(cur ^ 1, ic0 + 8);
        cp_commit();
        cp_wait1();
        __syncthreads();

        float* sP = smem + cur * STG;
        float* sW = sP + PATCHF;
#pragma unroll 1
        for (int ky = 0; ky < KS; ky++) {
#pragma unroll
            for (int kx = 0; kx < KS; kx++) {
                const int tap = ky * KS + kx;
                uint32_t a[2][4];
#pragma unroll
                for (int i = 0; i < 2; i++) {
                    int row = wm * 32 + i * 16 + g;
                    a[i][0] = __float_as_uint(sW[tap * 512 + row * 8 + tg]);
                    a[i][1] = __float_as_uint(sW[tap * 512 + (row + 8) * 8 + tg]);
                    a[i][2] = __float_as_uint(sW[tap * 512 + row * 8 + tg + 4]);
                    a[i][3] = __float_as_uint(sW[tap * 512 + (row + 8) * 8 + tg + 4]);
                }
#pragma unroll
                for (int j = 0; j < 16; j++) {
                    int hr = wn * 2 + (j >> 3) + ky;
                    int wc = (j & 7) * 8 + kx + g;
                    uint32_t b0 = __float_as_uint(sP[tg * PH * PWS + hr * PWS + wc]);
                    uint32_t b1 = __float_as_uint(sP[(tg + 4) * PH * PWS + hr * PWS + wc]);
                    mma_tf32(acc[0][j], a[0][0], a[0][1], a[0][2], a[0][3], b0, b1);
                    mma_tf32(acc[1][j], a[1][0], a[1][1], a[1][2], a[1][3], b0, b1);
                }
            }
        }
        __syncthreads();
    }

#pragma unroll
    for (int i = 0; i < 2; i++) {
        int oc_lo = ocT * 64 + wm * 32 + i * 16 + g;
        int oc_hi = oc_lo + 8;
        float sc0 = bng[oc_lo] * rsqrtf(bnv[oc_lo] + EPS);
        float sh0 = bnb[oc_lo] - bnm[oc_lo] * sc0;
        float sc1 = bng[oc_hi] * rsqrtf(bnv[oc_hi] + EPS);
        float sh1 = bnb[oc_hi] - bnm[oc_hi] * sc1;
#pragma unroll
        for (int j = 0; j < 16; j++) {
            int h = h0 + wn * 2 + (j >> 3);
            int w = w0 + (j & 7) * 8 + 2 * tg;
            size_t i0 = ((size_t)(bb * CDIM + oc_lo) * HDIM + h) * WDIM + w;
            size_t i1 = ((size_t)(bb * CDIM + oc_hi) * HDIM + h) * WDIM + w;
            float v00 = acc[i][j][0] * sc0 + sh0;
            float v01 = acc[i][j][1] * sc0 + sh0;
            float v10 = acc[i][j][2] * sc1 + sh1;
            float v11 = acc[i][j][3] * sc1 + sh1;
            out[i0] = v00; out[i0 + 1] = v01;
            out[i1] = v10; out[i1 + 1] = v11;
            if (ADD_HIGH) {
                out2[i0] = v00 + khbuf[i0]; out2[i0 + 1] = v01 + khbuf[i0 + 1];
                out2[i1] = v10 + khbuf[i1]; out2[i1 + 1] = v11 + khbuf[i1 + 1];
            }
        }
    }
}

// ---------------- window attention (R6 version, unchanged) -------------------
__global__ __launch_bounds__(64)
void attn_kernel(const float* __restrict__ qkv, const float* __restrict__ qh,
                 const float* __restrict__ kh, const float* __restrict__ rel_table,
                 float* __restrict__ low)
{
    __shared__ float sQ [16 * 64];
    __shared__ float sK [16 * 64];
    __shared__ float sV [16 * 64];
    __shared__ float sQH[16 * 64];
    __shared__ float sKH[16 * 64];
    __shared__ float sRT[225];

    const int wi = blockIdx.x;
    const int head = blockIdx.y;
    const int bb = blockIdx.z;
    const int hh = wi >> 4, ww = wi & 15;
    const int n = threadIdx.x;
    const int rn = n >> 3, cn = n & 7;

    for (int u = n; u < 1280; u += 64) {
        int a = u >> 8;
        int unit = u & 255;
        int ch = unit >> 4, px4 = unit & 15;
        int row = px4 >> 1, col = (px4 & 1) * 4;
        const float* gsrc;
        if (a < 3)
            gsrc = qkv + ((size_t)(bb * 768 + a * 256 + head * 16 + ch) * HDIM + hh * 8 + row) * WDIM + ww * 8 + col;
        else if (a == 3)
            gsrc = qh  + ((size_t)(bb * CDIM + head * 16 + ch) * HDIM + hh * 8 + row) * WDIM + ww * 8 + col;
        else
            gsrc = kh  + ((size_t)(bb * CDIM + head * 16 + ch) * HDIM + hh * 8 + row) * WDIM + ww * 8 + col;
        float4 v = *reinterpret_cast<const float4*>(gsrc);
        float* dst = (a == 0) ? sQ : (a == 1) ? sK : (a == 2) ? sV : (a == 3) ? sQH : sKH;
        *reinterpret_cast<float4*>(&dst[ch * 64 + px4 * 4]) = v;
    }
    for (int i = n; i < 225; i += 64) sRT[i] = rel_table[i * NHEAD + head];
    __syncthreads();

    float qr[16], qhr[16];
#pragma unroll
    for (int d = 0; d < 16; d++) {
        qr[d]  = sQ [d * 64 + n];
        qhr[d] = sQH[d * 64 + n];
    }

    const float scale = 0.25f;
    float dots[64];
#pragma unroll
    for (int m = 0; m < 64; m++) dots[m] = 0.f;
#pragma unroll
    for (int d = 0; d < 16; d++) {
        float qd = qr[d], qhd = qhr[d];
        const float4* k4  = reinterpret_cast<const float4*>(&sK [d * 64]);
        const float4* kh4 = reinterpret_cast<const float4*>(&sKH[d * 64]);
#pragma unroll
        for (int m4 = 0; m4 < 16; m4++) {
            float4 kv = k4[m4], khv = kh4[m4];
            dots[m4 * 4 + 0] += qd * kv.x + qhd * khv.x;
            dots[m4 * 4 + 1] += qd * kv.y + qhd * khv.y;
            dots[m4 * 4 + 2] += qd * kv.z + qhd * khv.z;
            dots[m4 * 4 + 3] += qd * kv.w + qhd * khv.w;
        }
    }
#pragma unroll
    for (int m = 0; m < 64; m++) {
        int rm = m >> 3, cm = m & 7;
        int idx = (rn - rm + 7) * 15 + (cn - cm + 7);
        dots[m] = dots[m] * scale + sRT[idx];
    }
    float mx = -1e30f;
#pragma unroll
    for (int m = 0; m < 64; m++) mx = fmaxf(mx, dots[m]);
    float sum = 0.f;
#pragma unroll
    for (int m = 0; m < 64; m++) { float e = __expf(dots[m] - mx); sum += e; dots[m] = e; }
    float inv = 1.f / sum;
#pragma unroll
    for (int m = 0; m < 64; m++) dots[m] *= inv;

    float o[16];
#pragma unroll
    for (int d = 0; d < 16; d++) {
        const float4* v4 = reinterpret_cast<const float4*>(&sV[d * 64]);
        float a0 = 0.f;
#pragma unroll
        for (int m4 = 0; m4 < 16; m4++) {
            float4 vv = v4[m4];
            a0 += dots[m4 * 4 + 0] * vv.x + dots[m4 * 4 + 1] * vv.y
                + dots[m4 * 4 + 2] * vv.z + dots[m4 * 4 + 3] * vv.w;
        }
        o[d] = a0;
    }

    __syncthreads();
#pragma unroll
    for (int d = 0; d < 16; d++) sQ[d * 64 + n] = o[d];
    __syncthreads();
    for (int u = n; u < 256; u += 64) {
        int ch = u >> 4, px4 = u & 15;
        int row = px4 >> 1, col = (px4 & 1) * 4;
        float4 v = *reinterpret_cast<const float4*>(&sQ[ch * 64 + px4 * 4]);
        *reinterpret_cast<float4*>(
            &low[((size_t)(bb * CDIM + head * 16 + ch) * HDIM + hh * 8 + row) * WDIM + ww * 8 + col]) = v;
    }
}

// ---------------- channel mean/max pool --------------------------------------
__global__ void pool_kernel(const float* __restrict__ low, const float* __restrict__ high,
                            float* __restrict__ pool)
{
    int p = blockIdx.x * 256 + threadIdx.x;
    int bb = blockIdx.y;
    const float* lb = low  + (size_t)bb * CDIM * HW;
    const float* hb = high + (size_t)bb * CDIM * HW;
    float s = 0.f, mx = -1e30f;
    for (int c = 0; c < CDIM; c++) {
        float v = lb[c * HW + p] + hb[c * HW + p];
        s += v; mx = fmaxf(mx, v);
    }
    pool[(bb * 2 + 0) * HW + p] = s * (1.f / 256.f);
    pool[(bb * 2 + 1) * HW + p] = mx;
}

// ---------------- hybrid 7x7 conv (2->2) + sigmoid ---------------------------
__global__ void hybrid_kernel(const float* __restrict__ pool, const float* __restrict__ hw,
                              const float* __restrict__ hb, float* __restrict__ sig)
{
    __shared__ float sw[196];
    __shared__ float sb[2];
    int t = threadIdx.x;
    if (t < 196) sw[t] = hw[t];
    if (t < 2) sb[t] = hb[t];
    __syncthreads();
    int p = blockIdx.x * 256 + t;
    int bb = blockIdx.y;
    int h = p >> 7, w = p & 127;
#pragma unroll
    for (int oc = 0; oc < 2; oc++) {
        float acc = sb[oc];
#pragma unroll
        for (int ic = 0; ic < 2; ic++)
            for (int ky = 0; ky < 7; ky++) {
                int hy = h + ky - 3;
                if (hy < 0 || hy >= HDIM) continue;
                for (int kx = 0; kx < 7; kx++) {
                    int wx = w + kx - 3;
                    if (wx < 0 || wx >= WDIM) continue;
                    acc += pool[(bb * 2 + ic) * HW + hy * WDIM + wx] * sw[((oc * 2 + ic) * 7 + ky) * 7 + kx];
                }
            }
        sig[(bb * 2 + oc) * HW + p] = 1.f / (1.f + __expf(-acc));
    }
}

// ---------------- mix (tf32-rounded: feeds smooth conv) ----------------------
__global__ void mix_kernel(const float* __restrict__ low, const float* __restrict__ high,
                           const float* __restrict__ sig, float* __restrict__ out)
{
    int idx = blockIdx.x * 256 + threadIdx.x;
    int p = idx & (HW - 1);
    int bb = idx >> 22;
    float s0 = sig[(bb * 2 + 0) * HW + p];
    float s1 = sig[(bb * 2 + 1) * HW + p];
    out[idx] = f2tf(low[idx] * s0 + high[idx] * s1);
}

// ---------------- depthwise 7x7 + BN (tf32-rounded: feeds pw GEMM) -----------
__global__ void dw_kernel(const float* __restrict__ in, const float* __restrict__ w,
                          const float* __restrict__ bng, const float* __restrict__ bnb,
                          const float* __restrict__ bnm, const float* __restrict__ bnv,
                          float* __restrict__ out)
{
    __shared__ float sT[14 * 38];
    __shared__ float sWc[49];
    const int w0 = blockIdx.x * 32;
    const int h0 = blockIdx.y * 8;
    const int bc = blockIdx.z;
    const int c = bc & 255;
    const int tx = threadIdx.x, ty = threadIdx.y;
    const int t = ty * 32 + tx;
    if (t < 49) sWc[t] = w[c * 49 + t];
    const float* inb = in + (size_t)bc * HW;
    for (int e = t; e < 14 * 38; e += 256) {
        int row = e / 38, cc = e % 38;
        int h = h0 + row - 3, ww = w0 + cc - 3;
        float v = 0.f;
        if (h >= 0 && h < HDIM && ww >= 0 && ww < WDIM) v = inb[h * WDIM + ww];
        sT[e] = v;
    }
    __syncthreads();
    float acc = 0.f;
#pragma unroll
    for (int ky = 0; ky < 7; ky++)
#pragma unroll
        for (int kx = 0; kx < 7; kx++)
            acc += sT[(ty + ky) * 38 + tx + kx] * sWc[ky * 7 + kx];
    float sc = bng[c] * rsqrtf(bnv[c] + EPS);
    float sh = bnb[c] - bnm[c] * sc;
    out[(size_t)bc * HW + (h0 + ty) * WDIM + w0 + tx] = f2tf(acc * sc + sh);
}

// ---------------- launch ------------------------------------------------------
extern "C" void kernel_launch(void* const* d_in, const int* in_sizes, int n_in,
                              void* d_out, int out_size)
{
    const float* x        = (const float*)d_in[0];
    const float* qkv_w    = (const float*)d_in[1];
    const float* local1_w = (const float*)d_in[2];
    const float* l1g = (const float*)d_in[3];
    const float* l1b = (const float*)d_in[4];
    const float* l1m = (const float*)d_in[5];
    const float* l1v = (const float*)d_in[6];
    const float* local2_w = (const float*)d_in[7];
    const float* l2g = (const float*)d_in[8];
    const float* l2b = (const float*)d_in[9];
    const float* l2m = (const float*)d_in[10];
    const float* l2v = (const float*)d_in[11];
    const float* rel_table = (const float*)d_in[12];
    const float* hybrid_w  = (const float*)d_in[13];
    const float* hybrid_b  = (const float*)d_in[14];
    const float* smooth_w  = (const float*)d_in[15];
    const float* smg = (const float*)d_in[16];
    const float* smb = (const float*)d_in[17];
    const float* smm = (const float*)d_in[18];
    const float* smv = (const float*)d_in[19];
    const float* proj_dw_w = (const float*)d_in[20];
    const float* prg = (const float*)d_in[21];
    const float* prb = (const float*)d_in[22];
    const float* prm = (const float*)d_in[23];
    const float* prv = (const float*)d_in[24];
    const float* proj_pw_w = (const float*)d_in[25];

    float *p_qh, *p_kh, *p_high, *p_qkv, *p_low, *p_mix, *p_sm, *p_dw, *p_pool, *p_sig;
    float *p_xr, *p_w5t, *p_w3t, *p_wq, *p_w2, *p_wp;
    cudaGetSymbolAddress((void**)&p_qh,   g_qh);
    cudaGetSymbolAddress((void**)&p_kh,   g_kh);
    cudaGetSymbolAddress((void**)&p_high, g_high);
    cudaGetSymbolAddress((void**)&p_qkv,  g_qkv);
    cudaGetSymbolAddress((void**)&p_low,  g_low);
    cudaGetSymbolAddress((void**)&p_mix,  g_mix);
    cudaGetSymbolAddress((void**)&p_sm,   g_sm);
    cudaGetSymbolAddress((void**)&p_dw,   g_dw);
    cudaGetSymbolAddress((void**)&p_pool, g_pool);
    cudaGetSymbolAddress((void**)&p_sig,  g_sig);
    cudaGetSymbolAddress((void**)&p_xr,   g_xr);
    cudaGetSymbolAddress((void**)&p_w5t,  g_w5t);
    cudaGetSymbolAddress((void**)&p_w3t,  g_w3t);
    cudaGetSymbolAddress((void**)&p_wq,   g_wq);
    cudaGetSymbolAddress((void**)&p_w2,   g_w2);
    cudaGetSymbolAddress((void**)&p_wp,   g_wp);

    const int smem3 = (2 * (8 * 10 * 68 + 9  * 512)) * 4;   // 80384 B
    const int smem5 = (2 * (8 * 12 * 70 + 25 * 512)) * 4;   // 156160 B
    const int smemG = (2 * (GEM_XF + GEM_WF)) * 4;          // 86016 B
    cudaFuncSetAttribute(conv_mma<5, false>, cudaFuncAttributeMaxDynamicSharedMemorySize, smem5);
    cudaFuncSetAttribute(conv_mma<3, true>,  cudaFuncAttributeMaxDynamicSharedMemorySize, smem3);
    cudaFuncSetAttribute(gemm1x1_mma,        cudaFuncAttributeMaxDynamicSharedMemorySize, smemG);

    // ---- pre-pass ----
    int nx = BDIM * CDIM * HW;
    round_copy<<<(nx + 255) / 256, 256>>>(x, p_xr, nx);
    round_copy<<<(3 * CDIM * CDIM + 255) / 256, 256>>>(qkv_w, p_wq, 3 * CDIM * CDIM);
    round_copy<<<(CDIM * CDIM + 255) / 256, 256>>>(local2_w, p_w2, CDIM * CDIM);
    round_copy<<<(CDIM * CDIM + 255) / 256, 256>>>(proj_pw_w, p_wp, CDIM * CDIM);
    wtransform<9><<<(CDIM * CDIM * 9 + 255) / 256, 256>>>(local1_w, p_w3t);
    wtransform<25><<<(CDIM * CDIM * 25 + 255) / 256, 256>>>(smooth_w, p_w5t);

    // ---- main chain ----
    gemm1x1_mma<<<dim3(64, 12, 4), 256, smemG>>>(p_xr, p_wq, nullptr, nullptr, nullptr, nullptr, p_qkv, 768);
    gemm1x1_mma<<<dim3(64, 4, 4), 256, smemG>>>(p_xr, p_w2, l2g, l2b, l2m, l2v, p_kh, 256);
    conv_mma<3, true><<<dim3(2, 16, 16), 256, smem3>>>(p_xr, p_w3t, l1g, l1b, l1m, l1v,
                                                       p_qh, p_kh, p_high);
    attn_kernel<<<dim3(256, 16, 4), 64>>>(p_qkv, p_qh, p_kh, rel_table, p_low);
    pool_kernel<<<dim3(64, 4), 256>>>(p_low, p_high, p_pool);
    hybrid_kernel<<<dim3(64, 4), 256>>>(p_pool, hybrid_w, hybrid_b, p_sig);
    mix_kernel<<<dim3(BDIM * CDIM * HW / 256), 256>>>(p_low, p_high, p_sig, p_mix);
    conv_mma<5, false><<<dim3(2, 16, 16), 256, smem5>>>(p_mix, p_w5t, smg, smb, smm, smv,
                                                        p_sm, nullptr, nullptr);
    dw_kernel<<<dim3(4, 16, 1024), dim3(32, 8)>>>(p_sm, proj_dw_w, prg, prb, prm, prv, p_dw);
    gemm1x1_mma<<<dim3(64, 4, 4), 256, smemG>>>(p_dw, p_wp, nullptr, nullptr, nullptr, nullptr,
                                                (float*)d_out, 256);
}

// round 8
// speedup vs baseline: 1.0541x; 1.0541x over previous
#include <cuda_runtime.h>
#include <math.h>
#include <stdint.h>

#define HDIM 128
#define WDIM 128
#define HW (HDIM*WDIM)
#define CDIM 256
#define BDIM 4
#define NHEAD 16
#define EPS 1e-5f

// ---------------- scratch ----------------------------------------------------
__device__ float g_qh  [BDIM*CDIM*HW];
__device__ float g_kh  [BDIM*CDIM*HW];
__device__ float g_high[BDIM*CDIM*HW];
__device__ float g_qkv [BDIM*3*CDIM*HW];
__device__ float g_low [BDIM*CDIM*HW];
__device__ float g_mix [BDIM*CDIM*HW];
__device__ float g_sm  [BDIM*CDIM*HW];
__device__ float g_dw  [BDIM*CDIM*HW];
__device__ float g_pool[BDIM*2*HW];
__device__ float g_sig [BDIM*2*HW];
// pre-rounded / transformed operands
__device__ float g_xr  [BDIM*CDIM*HW];
__device__ float g_w5t [CDIM*CDIM*25];
__device__ float g_w3t [CDIM*CDIM*9];
__device__ float g_wq  [3*CDIM*CDIM];
__device__ float g_w2  [CDIM*CDIM];
__device__ float g_wp  [CDIM*CDIM];

// ---------------- tf32 / cp.async helpers ------------------------------------
__device__ __forceinline__ float f2tf(float f) {
    uint32_t u;
    asm("cvt.rna.tf32.f32 %0, %1;" : "=r"(u) : "f"(f));
    return __uint_as_float(u);
}

__device__ __forceinline__ void cp16(float* dst, const float* src) {
    uint32_t d = (uint32_t)__cvta_generic_to_shared(dst);
    asm volatile("cp.async.cg.shared.global [%0], [%1], 16;" :: "r"(d), "l"(src));
}
__device__ __forceinline__ void cp4z(float* dst, const float* src, bool pred) {
    uint32_t d = (uint32_t)__cvta_generic_to_shared(dst);
    int sz = pred ? 4 : 0;
    asm volatile("cp.async.ca.shared.global [%0], [%1], 4, %2;" :: "r"(d), "l"(src), "r"(sz));
}
__device__ __forceinline__ void cp_commit() {
    asm volatile("cp.async.commit_group;");
}
__device__ __forceinline__ void cp_wait1() {
    asm volatile("cp.async.wait_group 1;");
}

__device__ __forceinline__ void mma_tf32(float* d, uint32_t a0, uint32_t a1,
                                         uint32_t a2, uint32_t a3,
                                         uint32_t b0, uint32_t b1) {
    asm volatile(
        "mma.sync.aligned.m16n8k8.row.col.f32.tf32.tf32.f32 "
        "{%0,%1,%2,%3}, {%4,%5,%6,%7}, {%8,%9}, {%0,%1,%2,%3};"
        : "+f"(d[0]), "+f"(d[1]), "+f"(d[2]), "+f"(d[3])
        : "r"(a0), "r"(a1), "r"(a2), "r"(a3), "r"(b0), "r"(b1));
}

// ---------------- pre-pass kernels -------------------------------------------
__global__ void round_copy(const float* __restrict__ in, float* __restrict__ out, int n)
{
    int i = blockIdx.x * 256 + threadIdx.x;
    if (i < n) out[i] = f2tf(in[i]);
}

template<int KKS>
__global__ void wtransform(const float* __restrict__ wgt, float* __restrict__ dst)
{
    int tid = blockIdx.x * 256 + threadIdx.x;
    int total = 4 * 32 * KKS * 512;
    if (tid >= total) return;
    int ic  = tid & 7;
    int oc  = (tid >> 3) & 63;
    int tap = (tid >> 9) % KKS;
    int ics = (tid / (512 * KKS)) & 31;
    int ocT = tid / (512 * KKS * 32);
    dst[tid] = f2tf(wgt[((size_t)((ocT * 64 + oc) * 256 + ics * 8 + ic)) * KKS + tap]);
}

// ---------------- 1x1 conv as tf32 GEMM: 128oc x 256px, 512 threads ----------
#define XSTR 264
#define WSTR 36
#define GEM_XF (32*XSTR)     // 8448 floats
#define GEM_WF (128*WSTR)    // 4608 floats
#define GEM_STG (GEM_XF+GEM_WF)

__global__ __launch_bounds__(512, 1)
void gemm1x1_mma(const float* __restrict__ in, const float* __restrict__ w,
                 const float* __restrict__ bng, const float* __restrict__ bnb,
                 const float* __restrict__ bnm, const float* __restrict__ bnv,
                 float* __restrict__ out, int OC)
{
    extern __shared__ float smem[];

    const int bb  = blockIdx.z;
    const int ocT = blockIdx.y;
    const int p0  = blockIdx.x * 256;
    const int t   = threadIdx.x;
    const int warp = t >> 5, lane = t & 31;
    const int g = lane >> 2, tg = lane & 3;
    const int wm = warp >> 2;          // 0..3 -> oc base wm*32
    const int wn = warp & 3;           // 0..3 -> px base wn*64

    const float* inb = in + (size_t)bb * CDIM * HW;

    auto load = [&](int s, int ic0) {
        float* sX = smem + s * GEM_STG;
        float* sW = sX + GEM_XF;
        // X chunk: 32 ic x 256 px = 2048 float4 units; 512 thr x 4 iters
#pragma unroll
        for (int j = 0; j < 4; j++) {
            int idx = j * 512 + t;
            int ic = idx >> 6, px4 = idx & 63;
            cp16(&sX[ic * XSTR + px4 * 4], &inb[(ic0 + ic) * HW + p0 + px4 * 4]);
        }
        // W chunk: 128 oc x 32 ic = 1024 float4 units; 512 thr x 2 iters
#pragma unroll
        for (int j = 0; j < 2; j++) {
            int idx = j * 512 + t;
            int oc = idx >> 3, icq = idx & 7;
            cp16(&sW[oc * WSTR + icq * 4], &w[(size_t)(ocT * 128 + oc) * CDIM + ic0 + icq * 4]);
        }
    };

    float acc[2][8][4];
#pragma unroll
    for (int i = 0; i < 2; i++)
#pragma unroll
        for (int j = 0; j < 8; j++)
#pragma unroll
            for (int c = 0; c < 4; c++) acc[i][j][c] = 0.f;

    load(0, 0);
    cp_commit();

    for (int ic0 = 0; ic0 < CDIM; ic0 += 32) {
        int cur = (ic0 >> 5) & 1;
        if (ic0 + 32 < CDIM) load(cur ^ 1, ic0 + 32);
        cp_commit();
        cp_wait1();
        __syncthreads();

        float* sX = smem + cur * GEM_STG;
        float* sW = sX + GEM_XF;
#pragma unroll
        for (int ks = 0; ks < 4; ks++) {
            int kk = ks * 8;
            uint32_t a[2][4];
#pragma unroll
            for (int i = 0; i < 2; i++) {
                int row = wm * 32 + i * 16 + g;
                a[i][0] = __float_as_uint(sW[row * WSTR + kk + tg]);
                a[i][1] = __float_as_uint(sW[(row + 8) * WSTR + kk + tg]);
                a[i][2] = __float_as_uint(sW[row * WSTR + kk + tg + 4]);
                a[i][3] = __float_as_uint(sW[(row + 8) * WSTR + kk + tg + 4]);
            }
#pragma unroll
            for (int j = 0; j < 8; j++) {
                int px = wn * 64 + j * 8 + g;
                uint32_t b0 = __float_as_uint(sX[(kk + tg) * XSTR + px]);
                uint32_t b1 = __float_as_uint(sX[(kk + tg + 4) * XSTR + px]);
                mma_tf32(acc[0][j], a[0][0], a[0][1], a[0][2], a[0][3], b0, b1);
                mma_tf32(acc[1][j], a[1][0], a[1][1], a[1][2], a[1][3], b0, b1);
            }
        }
        __syncthreads();
    }

#pragma unroll
    for (int i = 0; i < 2; i++) {
        int oc_lo = ocT * 128 + wm * 32 + i * 16 + g;
        int oc_hi = oc_lo + 8;
        float sc0 = 1.f, sh0 = 0.f, sc1 = 1.f, sh1 = 0.f;
        if (bng) {
            sc0 = bng[oc_lo] * rsqrtf(bnv[oc_lo] + EPS); sh0 = bnb[oc_lo] - bnm[oc_lo] * sc0;
            sc1 = bng[oc_hi] * rsqrtf(bnv[oc_hi] + EPS); sh1 = bnb[oc_hi] - bnm[oc_hi] * sc1;
        }
#pragma unroll
        for (int j = 0; j < 8; j++) {
            int px = p0 + wn * 64 + j * 8 + 2 * tg;
            float* o0 = &out[((size_t)bb * OC + oc_lo) * HW + px];
            float* o1 = &out[((size_t)bb * OC + oc_hi) * HW + px];
            o0[0] = acc[i][j][0] * sc0 + sh0;
            o0[1] = acc[i][j][1] * sc0 + sh0;
            o1[0] = acc[i][j][2] * sc1 + sh1;
            o1[1] = acc[i][j][3] * sc1 + sh1;
        }
    }
}

// ---------------- KxK conv via tf32 MMA (R3 known-good config) ---------------
// weights pre-transformed: [(ocT*32+ics)*KKS + tap][64oc*8ic] contiguous
template<int KS, bool ADD_HIGH>
__global__ __launch_bounds__(256, (KS == 3 ? 2 : 1))
void conv_mma(const float* __restrict__ in, const float* __restrict__ wt,
              const float* __restrict__ bng, const float* __restrict__ bnb,
              const float* __restrict__ bnm, const float* __restrict__ bnv,
              float* __restrict__ out,
              const float* __restrict__ khbuf, float* __restrict__ out2)
{
    constexpr int PAD = KS / 2;
    constexpr int PH = 8 + KS - 1;
    constexpr int PW = 32 + KS - 1;
    constexpr int PWS = PW + 2;               // 38 / 36 ; PH*PWS % 32 == 8
    constexpr int KKS = KS * KS;
    constexpr int PATCHF = 8 * PH * PWS;
    constexpr int WGTF = KKS * 512;
    constexpr int STG = PATCHF + WGTF;

    extern __shared__ float smem[];

    const int w0 = blockIdx.x * 32;
    const int h0 = blockIdx.y * 8;
    const int bb  = blockIdx.z >> 2;
    const int ocT = blockIdx.z & 3;
    const int t = threadIdx.x;
    const int warp = t >> 5, lane = t & 31;
    const int g = lane >> 2, tg = lane & 3;
    const int wm = warp >> 2;
    const int wn = warp & 3;

    auto load = [&](int s, int ic0) {
        float* sP = smem + s * STG;
        float* sW = sP + PATCHF;
        for (int e = t; e < 8 * PH * PW; e += 256) {
            int ic = e / (PH * PW), rem = e % (PH * PW);
            int row = rem / PW, cc = rem % PW;
            int h = h0 + row - PAD, w = w0 + cc - PAD;
            bool ok = ((unsigned)h < HDIM) && ((unsigned)w < WDIM);
            const float* src = in + ((size_t)(bb * CDIM + ic0 + ic) * HDIM + (ok ? h : 0)) * WDIM + (ok ? w : 0);
            cp4z(&sP[ic * PH * PWS + row * PWS + cc], src, ok);
        }
        const float* base = wt + (size_t)(ocT * 32 + (ic0 >> 3)) * WGTF;
        for (int e = t * 4; e < WGTF; e += 1024)
            cp16(&sW[e], &base[e]);
    };

    float acc[2][8][4];
#pragma unroll
    for (int i = 0; i < 2; i++)
#pragma unroll
        for (int j = 0; j < 8; j++)
#pragma unroll
            for (int c = 0; c < 4; c++) acc[i][j][c] = 0.f;

    load(0, 0);
    cp_commit();

    for (int ic0 = 0; ic0 < CDIM; ic0 += 8) {
        int cur = (ic0 >> 3) & 1;
        if (ic0 + 8 < CDIM) load(cur ^ 1, ic0 + 8);
        cp_commit();
        cp_wait1();
        __syncthreads();

        float* sP = smem + cur * STG;
        float* sW = sP + PATCHF;
#pragma unroll
        for (int ky = 0; ky < KS; ky++)
#pragma unroll
            for (int kx = 0; kx < KS; kx++) {
                const int tap = ky * KS + kx;
                uint32_t a[2][4];
#pragma unroll
                for (int i = 0; i < 2; i++) {
                    int row = wm * 32 + i * 16 + g;
                    a[i][0] = __float_as_uint(sW[tap * 512 + row * 8 + tg]);
                    a[i][1] = __float_as_uint(sW[tap * 512 + (row + 8) * 8 + tg]);
                    a[i][2] = __float_as_uint(sW[tap * 512 + row * 8 + tg + 4]);
                    a[i][3] = __float_as_uint(sW[tap * 512 + (row + 8) * 8 + tg + 4]);
                }
#pragma unroll
                for (int j = 0; j < 8; j++) {
                    int hr = wn * 2 + (j >> 2) + ky;
                    int wc = (j & 3) * 8 + kx + g;
                    uint32_t b0 = __float_as_uint(sP[tg * PH * PWS + hr * PWS + wc]);
                    uint32_t b1 = __float_as_uint(sP[(tg + 4) * PH * PWS + hr * PWS + wc]);
                    mma_tf32(acc[0][j], a[0][0], a[0][1], a[0][2], a[0][3], b0, b1);
                    mma_tf32(acc[1][j], a[1][0], a[1][1], a[1][2], a[1][3], b0, b1);
                }
            }
        __syncthreads();
    }

#pragma unroll
    for (int i = 0; i < 2; i++) {
        int oc_lo = ocT * 64 + wm * 32 + i * 16 + g;
        int oc_hi = oc_lo + 8;
        float sc0 = bng[oc_lo] * rsqrtf(bnv[oc_lo] + EPS);
        float sh0 = bnb[oc_lo] - bnm[oc_lo] * sc0;
        float sc1 = bng[oc_hi] * rsqrtf(bnv[oc_hi] + EPS);
        float sh1 = bnb[oc_hi] - bnm[oc_hi] * sc1;
#pragma unroll
        for (int j = 0; j < 8; j++) {
            int h = h0 + wn * 2 + (j >> 2);
            int w = w0 + (j & 3) * 8 + 2 * tg;
            size_t i0 = ((size_t)(bb * CDIM + oc_lo) * HDIM + h) * WDIM + w;
            size_t i1 = ((size_t)(bb * CDIM + oc_hi) * HDIM + h) * WDIM + w;
            float v00 = acc[i][j][0] * sc0 + sh0;
            float v01 = acc[i][j][1] * sc0 + sh0;
            float v10 = acc[i][j][2] * sc1 + sh1;
            float v11 = acc[i][j][3] * sc1 + sh1;
            out[i0] = v00; out[i0 + 1] = v01;
            out[i1] = v10; out[i1 + 1] = v11;
            if (ADD_HIGH) {
                out2[i0] = v00 + khbuf[i0]; out2[i0 + 1] = v01 + khbuf[i0 + 1];
                out2[i1] = v10 + khbuf[i1]; out2[i1 + 1] = v11 + khbuf[i1 + 1];
            }
        }
    }
}

// ---------------- window attention (R6 version) ------------------------------
__global__ __launch_bounds__(64)
void attn_kernel(const float* __restrict__ qkv, const float* __restrict__ qh,
                 const float* __restrict__ kh, const float* __restrict__ rel_table,
                 float* __restrict__ low)
{
    __shared__ float sQ [16 * 64];
    __shared__ float sK [16 * 64];
    __shared__ float sV [16 * 64];
    __shared__ float sQH[16 * 64];
    __shared__ float sKH[16 * 64];
    __shared__ float sRT[225];

    const int wi = blockIdx.x;
    const int head = blockIdx.y;
    const int bb = blockIdx.z;
    const int hh = wi >> 4, ww = wi & 15;
    const int n = threadIdx.x;
    const int rn = n >> 3, cn = n & 7;

    for (int u = n; u < 1280; u += 64) {
        int a = u >> 8;
        int unit = u & 255;
        int ch = unit >> 4, px4 = unit & 15;
        int row = px4 >> 1, col = (px4 & 1) * 4;
        const float* gsrc;
        if (a < 3)
            gsrc = qkv + ((size_t)(bb * 768 + a * 256 + head * 16 + ch) * HDIM + hh * 8 + row) * WDIM + ww * 8 + col;
        else if (a == 3)
            gsrc = qh  + ((size_t)(bb * CDIM + head * 16 + ch) * HDIM + hh * 8 + row) * WDIM + ww * 8 + col;
        else
            gsrc = kh  + ((size_t)(bb * CDIM + head * 16 + ch) * HDIM + hh * 8 + row) * WDIM + ww * 8 + col;
        float4 v = *reinterpret_cast<const float4*>(gsrc);
        float* dst = (a == 0) ? sQ : (a == 1) ? sK : (a == 2) ? sV : (a == 3) ? sQH : sKH;
        *reinterpret_cast<float4*>(&dst[ch * 64 + px4 * 4]) = v;
    }
    for (int i = n; i < 225; i += 64) sRT[i] = rel_table[i * NHEAD + head];
    __syncthreads();

    float qr[16], qhr[16];
#pragma unroll
    for (int d = 0; d < 16; d++) {
        qr[d]  = sQ [d * 64 + n];
        qhr[d] = sQH[d * 64 + n];
    }

    const float scale = 0.25f;
    float dots[64];
#pragma unroll
    for (int m = 0; m < 64; m++) dots[m] = 0.f;
#pragma unroll
    for (int d = 0; d < 16; d++) {
        float qd = qr[d], qhd = qhr[d];
        const float4* k4  = reinterpret_cast<const float4*>(&sK [d * 64]);
        const float4* kh4 = reinterpret_cast<const float4*>(&sKH[d * 64]);
#pragma unroll
        for (int m4 = 0; m4 < 16; m4++) {
            float4 kv = k4[m4], khv = kh4[m4];
            dots[m4 * 4 + 0] += qd * kv.x + qhd * khv.x;
            dots[m4 * 4 + 1] += qd * kv.y + qhd * khv.y;
            dots[m4 * 4 + 2] += qd * kv.z + qhd * khv.z;
            dots[m4 * 4 + 3] += qd * kv.w + qhd * khv.w;
        }
    }
#pragma unroll
    for (int m = 0; m < 64; m++) {
        int rm = m >> 3, cm = m & 7;
        int idx = (rn - rm + 7) * 15 + (cn - cm + 7);
        dots[m] = dots[m] * scale + sRT[idx];
    }
    float mx = -1e30f;
#pragma unroll
    for (int m = 0; m < 64; m++) mx = fmaxf(mx, dots[m]);
    float sum = 0.f;
#pragma unroll
    for (int m = 0; m < 64; m++) { float e = __expf(dots[m] - mx); sum += e; dots[m] = e; }
    float inv = 1.f / sum;
#pragma unroll
    for (int m = 0; m < 64; m++) dots[m] *= inv;

    float o[16];
#pragma unroll
    for (int d = 0; d < 16; d++) {
        const float4* v4 = reinterpret_cast<const float4*>(&sV[d * 64]);
        float a0 = 0.f;
#pragma unroll
        for (int m4 = 0; m4 < 16; m4++) {
            float4 vv = v4[m4];
            a0 += dots[m4 * 4 + 0] * vv.x + dots[m4 * 4 + 1] * vv.y
                + dots[m4 * 4 + 2] * vv.z + dots[m4 * 4 + 3] * vv.w;
        }
        o[d] = a0;
    }

    __syncthreads();
#pragma unroll
    for (int d = 0; d < 16; d++) sQ[d * 64 + n] = o[d];
    __syncthreads();
    for (int u = n; u < 256; u += 64) {
        int ch = u >> 4, px4 = u & 15;
        int row = px4 >> 1, col = (px4 & 1) * 4;
        float4 v = *reinterpret_cast<const float4*>(&sQ[ch * 64 + px4 * 4]);
        *reinterpret_cast<float4*>(
            &low[((size_t)(bb * CDIM + head * 16 + ch) * HDIM + hh * 8 + row) * WDIM + ww * 8 + col]) = v;
    }
}

// ---------------- channel mean/max pool --------------------------------------
__global__ void pool_kernel(const float* __restrict__ low, const float* __restrict__ high,
                            float* __restrict__ pool)
{
    int p = blockIdx.x * 256 + threadIdx.x;
    int bb = blockIdx.y;
    const float* lb = low  + (size_t)bb * CDIM * HW;
    const float* hb = high + (size_t)bb * CDIM * HW;
    float s = 0.f, mx = -1e30f;
    for (int c = 0; c < CDIM; c++) {
        float v = lb[c * HW + p] + hb[c * HW + p];
        s += v; mx = fmaxf(mx, v);
    }
    pool[(bb * 2 + 0) * HW + p] = s * (1.f / 256.f);
    pool[(bb * 2 + 1) * HW + p] = mx;
}

// ---------------- hybrid 7x7 conv (2->2) + sigmoid ---------------------------
__global__ void hybrid_kernel(const float* __restrict__ pool, const float* __restrict__ hw,
                              const float* __restrict__ hb, float* __restrict__ sig)
{
    __shared__ float sw[196];
    __shared__ float sb[2];
    int t = threadIdx.x;
    if (t < 196) sw[t] = hw[t];
    if (t < 2) sb[t] = hb[t];
    __syncthreads();
    int p = blockIdx.x * 256 + t;
    int bb = blockIdx.y;
    int h = p >> 7, w = p & 127;
#pragma unroll
    for (int oc = 0; oc < 2; oc++) {
        float acc = sb[oc];
#pragma unroll
        for (int ic = 0; ic < 2; ic++)
            for (int ky = 0; ky < 7; ky++) {
                int hy = h + ky - 3;
                if (hy < 0 || hy >= HDIM) continue;
                for (int kx = 0; kx < 7; kx++) {
                    int wx = w + kx - 3;
                    if (wx < 0 || wx >= WDIM) continue;
                    acc += pool[(bb * 2 + ic) * HW + hy * WDIM + wx] * sw[((oc * 2 + ic) * 7 + ky) * 7 + kx];
                }
            }
        sig[(bb * 2 + oc) * HW + p] = 1.f / (1.f + __expf(-acc));
    }
}

// ---------------- mix (tf32-rounded: feeds smooth conv) ----------------------
__global__ void mix_kernel(const float* __restrict__ low, const float* __restrict__ high,
                           const float* __restrict__ sig, float* __restrict__ out)
{
    int idx = blockIdx.x * 256 + threadIdx.x;
    int p = idx & (HW - 1);
    int bb = idx >> 22;
    float s0 = sig[(bb * 2 + 0) * HW + p];
    float s1 = sig[(bb * 2 + 1) * HW + p];
    out[idx] = f2tf(low[idx] * s0 + high[idx] * s1);
}

// ---------------- depthwise 7x7 + BN (tf32-rounded: feeds pw GEMM) -----------
__global__ void dw_kernel(const float* __restrict__ in, const float* __restrict__ w,
                          const float* __restrict__ bng, const float* __restrict__ bnb,
                          const float* __restrict__ bnm, const float* __restrict__ bnv,
                          float* __restrict__ out)
{
    __shared__ float sT[14 * 38];
    __shared__ float sWc[49];
    const int w0 = blockIdx.x * 32;
    const int h0 = blockIdx.y * 8;
    const int bc = blockIdx.z;
    const int c = bc & 255;
    const int tx = threadIdx.x, ty = threadIdx.y;
    const int t = ty * 32 + tx;
    if (t < 49) sWc[t] = w[c * 49 + t];
    const float* inb = in + (size_t)bc * HW;
    for (int e = t; e < 14 * 38; e += 256) {
        int row = e / 38, cc = e % 38;
        int h = h0 + row - 3, ww = w0 + cc - 3;
        float v = 0.f;
        if (h >= 0 && h < HDIM && ww >= 0 && ww < WDIM) v = inb[h * WDIM + ww];
        sT[e] = v;
    }
    __syncthreads();
    float acc = 0.f;
#pragma unroll
    for (int ky = 0; ky < 7; ky++)
#pragma unroll
        for (int kx = 0; kx < 7; kx++)
            acc += sT[(ty + ky) * 38 + tx + kx] * sWc[ky * 7 + kx];
    float sc = bng[c] * rsqrtf(bnv[c] + EPS);
    float sh = bnb[c] - bnm[c] * sc;
    out[(size_t)bc * HW + (h0 + ty) * WDIM + w0 + tx] = f2tf(acc * sc + sh);
}

// ---------------- launch ------------------------------------------------------
extern "C" void kernel_launch(void* const* d_in, const int* in_sizes, int n_in,
                              void* d_out, int out_size)
{
    const float* x        = (const float*)d_in[0];
    const float* qkv_w    = (const float*)d_in[1];
    const float* local1_w = (const float*)d_in[2];
    const float* l1g = (const float*)d_in[3];
    const float* l1b = (const float*)d_in[4];
    const float* l1m = (const float*)d_in[5];
    const float* l1v = (const float*)d_in[6];
    const float* local2_w = (const float*)d_in[7];
    const float* l2g = (const float*)d_in[8];
    const float* l2b = (const float*)d_in[9];
    const float* l2m = (const float*)d_in[10];
    const float* l2v = (const float*)d_in[11];
    const float* rel_table = (const float*)d_in[12];
    const float* hybrid_w  = (const float*)d_in[13];
    const float* hybrid_b  = (const float*)d_in[14];
    const float* smooth_w  = (const float*)d_in[15];
    const float* smg = (const float*)d_in[16];
    const float* smb = (const float*)d_in[17];
    const float* smm = (const float*)d_in[18];
    const float* smv = (const float*)d_in[19];
    const float* proj_dw_w = (const float*)d_in[20];
    const float* prg = (const float*)d_in[21];
    const float* prb = (const float*)d_in[22];
    const float* prm = (const float*)d_in[23];
    const float* prv = (const float*)d_in[24];
    const float* proj_pw_w = (const float*)d_in[25];

    float *p_qh, *p_kh, *p_high, *p_qkv, *p_low, *p_mix, *p_sm, *p_dw, *p_pool, *p_sig;
    float *p_xr, *p_w5t, *p_w3t, *p_wq, *p_w2, *p_wp;
    cudaGetSymbolAddress((void**)&p_qh,   g_qh);
    cudaGetSymbolAddress((void**)&p_kh,   g_kh);
    cudaGetSymbolAddress((void**)&p_high, g_high);
    cudaGetSymbolAddress((void**)&p_qkv,  g_qkv);
    cudaGetSymbolAddress((void**)&p_low,  g_low);
    cudaGetSymbolAddress((void**)&p_mix,  g_mix);
    cudaGetSymbolAddress((void**)&p_sm,   g_sm);
    cudaGetSymbolAddress((void**)&p_dw,   g_dw);
    cudaGetSymbolAddress((void**)&p_pool, g_pool);
    cudaGetSymbolAddress((void**)&p_sig,  g_sig);
    cudaGetSymbolAddress((void**)&p_xr,   g_xr);
    cudaGetSymbolAddress((void**)&p_w5t,  g_w5t);
    cudaGetSymbolAddress((void**)&p_w3t,  g_w3t);
    cudaGetSymbolAddress((void**)&p_wq,   g_wq);
    cudaGetSymbolAddress((void**)&p_w2,   g_w2);
    cudaGetSymbolAddress((void**)&p_wp,   g_wp);

    const int smem3 = (2 * (8 * 10 * 36 + 9  * 512)) * 4;   // 59904 B
    const int smem5 = (2 * (8 * 12 * 38 + 25 * 512)) * 4;   // 131584 B
    const int smemG = (2 * (GEM_XF + GEM_WF)) * 4;          // 104448 B
    cudaFuncSetAttribute(conv_mma<5, false>, cudaFuncAttributeMaxDynamicSharedMemorySize, smem5);
    cudaFuncSetAttribute(conv_mma<3, true>,  cudaFuncAttributeMaxDynamicSharedMemorySize, smem3);
    cudaFuncSetAttribute(gemm1x1_mma,        cudaFuncAttributeMaxDynamicSharedMemorySize, smemG);

    // ---- pre-pass ----
    int nx = BDIM * CDIM * HW;
    round_copy<<<(nx + 255) / 256, 256>>>(x, p_xr, nx);
    round_copy<<<(3 * CDIM * CDIM + 255) / 256, 256>>>(qkv_w, p_wq, 3 * CDIM * CDIM);
    round_copy<<<(CDIM * CDIM + 255) / 256, 256>>>(local2_w, p_w2, CDIM * CDIM);
    round_copy<<<(CDIM * CDIM + 255) / 256, 256>>>(proj_pw_w, p_wp, CDIM * CDIM);
    wtransform<9><<<(CDIM * CDIM * 9 + 255) / 256, 256>>>(local1_w, p_w3t);
    wtransform<25><<<(CDIM * CDIM * 25 + 255) / 256, 256>>>(smooth_w, p_w5t);

    // ---- main chain ----
    gemm1x1_mma<<<dim3(64, 6, 4), 512, smemG>>>(p_xr, p_wq, nullptr, nullptr, nullptr, nullptr, p_qkv, 768);
    gemm1x1_mma<<<dim3(64, 2, 4), 512, smemG>>>(p_xr, p_w2, l2g, l2b, l2m, l2v, p_kh, 256);
    conv_mma<3, true><<<dim3(4, 16, 16), 256, smem3>>>(p_xr, p_w3t, l1g, l1b, l1m, l1v,
                                                       p_qh, p_kh, p_high);
    attn_kernel<<<dim3(256, 16, 4), 64>>>(p_qkv, p_qh, p_kh, rel_table, p_low);
    pool_kernel<<<dim3(64, 4), 256>>>(p_low, p_high, p_pool);
    hybrid_kernel<<<dim3(64, 4), 256>>>(p_pool, hybrid_w, hybrid_b, p_sig);
    mix_kernel<<<dim3(BDIM * CDIM * HW / 256), 256>>>(p_low, p_high, p_sig, p_mix);
    conv_mma<5, false><<<dim3(4, 16, 16), 256, smem5>>>(p_mix, p_w5t, smg, smb, smm, smv,
                                                        p_sm, nullptr, nullptr);
    dw_kernel<<<dim3(4, 16, 1024), dim3(32, 8)>>>(p_sm, proj_dw_w, prg, prb, prm, prv, p_dw);
    gemm1x1_mma<<<dim3(64, 2, 4), 512, smemG>>>(p_dw, p_wp, nullptr, nullptr, nullptr, nullptr,
                                                (float*)d_out, 256);
}

// round 9
// speedup vs baseline: 1.6429x; 1.5586x over previous
#include <cuda_runtime.h>
#include <cuda_fp16.h>
#include <math.h>
#include <stdint.h>

#define HDIM 128
#define WDIM 128
#define HW (HDIM*WDIM)
#define CDIM 256
#define BDIM 4
#define NHEAD 16
#define EPS 1e-5f

// ---------------- scratch ----------------------------------------------------
__device__ float  g_qh  [BDIM*CDIM*HW];
__device__ float  g_kh  [BDIM*CDIM*HW];
__device__ float  g_high[BDIM*CDIM*HW];
__device__ float  g_qkv [BDIM*3*CDIM*HW];
__device__ float  g_low [BDIM*CDIM*HW];
__device__ float  g_sm  [BDIM*CDIM*HW];
__device__ float  g_pool[BDIM*2*HW];
__device__ float  g_sig [BDIM*2*HW];
// half activations (channel-pair interleaved [C/2][H][W][2])
__device__ __half g_xh  [BDIM*CDIM*HW];
__device__ __half g_mixh[BDIM*CDIM*HW];
__device__ __half g_dwh [BDIM*CDIM*HW];
// half weights
__device__ __half g_w5t [CDIM*CDIM*25];
__device__ __half g_w3t [CDIM*CDIM*9];
__device__ __half g_wq  [3*CDIM*CDIM];
__device__ __half g_w2  [CDIM*CDIM];
__device__ __half g_wp  [CDIM*CDIM];

// ---------------- helpers ----------------------------------------------------
__device__ __forceinline__ void cp16(void* dst, const void* src) {
    uint32_t d = (uint32_t)__cvta_generic_to_shared(dst);
    asm volatile("cp.async.cg.shared.global [%0], [%1], 16;" :: "r"(d), "l"(src));
}
__device__ __forceinline__ void cp4z(void* dst, const void* src, bool pred) {
    uint32_t d = (uint32_t)__cvta_generic_to_shared(dst);
    int sz = pred ? 4 : 0;
    asm volatile("cp.async.ca.shared.global [%0], [%1], 4, %2;" :: "r"(d), "l"(src), "r"(sz));
}
__device__ __forceinline__ void cp_commit() { asm volatile("cp.async.commit_group;"); }
__device__ __forceinline__ void cp_wait1()  { asm volatile("cp.async.wait_group 1;"); }

__device__ __forceinline__ void mma_f16(float* d, uint32_t a0, uint32_t a1,
                                        uint32_t a2, uint32_t a3,
                                        uint32_t b0, uint32_t b1) {
    asm volatile(
        "mma.sync.aligned.m16n8k16.row.col.f32.f16.f16.f32 "
        "{%0,%1,%2,%3}, {%4,%5,%6,%7}, {%8,%9}, {%0,%1,%2,%3};"
        : "+f"(d[0]), "+f"(d[1]), "+f"(d[2]), "+f"(d[3])
        : "r"(a0), "r"(a1), "r"(a2), "r"(a3), "r"(b0), "r"(b1));
}

// ---------------- pre-pass kernels -------------------------------------------
// x (float [C][HW]) -> half2 interleaved [C/2][HW]
__global__ void interleave_h(const float* __restrict__ in, __half* __restrict__ out)
{
    int i = blockIdx.x * 256 + threadIdx.x;            // over BDIM*128*HW
    int p = i & (HW - 1);
    int rest = i >> 14;
    int cp = rest & 127;
    int b = rest >> 7;
    const float* base = in + ((size_t)(b * CDIM + 2 * cp)) * HW + p;
    reinterpret_cast<__half2*>(out)[i] = __floats2half2_rn(base[0], base[HW]);
}

__global__ void roundw_h(const float* __restrict__ in, __half* __restrict__ out, int n)
{
    int i = blockIdx.x * 256 + threadIdx.x;
    if (i < n) out[i] = __float2half_rn(in[i]);
}

// conv weights -> [ocT][chunk16][tap][64oc][16ic] half
template<int KKS>
__global__ void wtransform_h(const float* __restrict__ wgt, __half* __restrict__ dst)
{
    int tid = blockIdx.x * 256 + threadIdx.x;
    int total = 4 * 16 * KKS * 1024;
    if (tid >= total) return;
    int ic  = tid & 15;
    int oc  = (tid >> 4) & 63;
    int tap = (tid >> 10) % KKS;
    int ics = (tid / (1024 * KKS)) & 15;
    int ocT = tid / (1024 * KKS * 16);
    dst[tid] = __float2half_rn(wgt[((size_t)((ocT * 64 + oc) * 256 + ics * 16 + ic)) * KKS + tap]);
}

// ---------------- 1x1 conv as fp16 GEMM, cp.async double-buffered ------------
// units = half2 (4B). X: [16 icpair][264], W: [64 oc][20].
#define XSTR2 264
#define WSTR2 20
#define GEM_XF2 (16*XSTR2)
#define GEM_WF2 (64*WSTR2)
#define GEM_STG2 (GEM_XF2+GEM_WF2)

__global__ __launch_bounds__(256, 2)
void gemm1x1_h(const __half* __restrict__ in, const __half* __restrict__ w,
               const float* __restrict__ bng, const float* __restrict__ bnb,
               const float* __restrict__ bnm, const float* __restrict__ bnv,
               float* __restrict__ out, int OC)
{
    extern __shared__ uint32_t smem2[];

    const int bb  = blockIdx.z;
    const int ocT = blockIdx.y;
    const int p0  = blockIdx.x * 256;
    const int t   = threadIdx.x;
    const int warp = t >> 5, lane = t & 31;
    const int g = lane >> 2, tg = lane & 3;
    const int wm = warp >> 2;
    const int wn = warp & 3;

    const __half2* in2 = reinterpret_cast<const __half2*>(in) + (size_t)bb * 128 * HW;

    auto load = [&](int s, int ic0) {
        uint32_t* sX = smem2 + s * GEM_STG2;
        uint32_t* sW = sX + GEM_XF2;
        int cp0 = ic0 >> 1;
#pragma unroll
        for (int j = 0; j < 4; j++) {
            int idx = j * 256 + t;
            int icp = idx >> 6, px4 = idx & 63;
            cp16(&sX[icp * XSTR2 + px4 * 4], in2 + (cp0 + icp) * HW + p0 + px4 * 4);
        }
        {
            int oc = t >> 2, icq = t & 3;
            cp16(&sW[oc * WSTR2 + icq * 4],
                 w + (size_t)(ocT * 64 + oc) * CDIM + ic0 + icq * 8);
        }
    };

    float acc[2][8][4];
#pragma unroll
    for (int i = 0; i < 2; i++)
#pragma unroll
        for (int j = 0; j < 8; j++)
#pragma unroll
            for (int c = 0; c < 4; c++) acc[i][j][c] = 0.f;

    load(0, 0);
    cp_commit();

    for (int ic0 = 0; ic0 < CDIM; ic0 += 32) {
        int cur = (ic0 >> 5) & 1;
        if (ic0 + 32 < CDIM) load(cur ^ 1, ic0 + 32);
        cp_commit();
        cp_wait1();
        __syncthreads();

        uint32_t* sX = smem2 + cur * GEM_STG2;
        uint32_t* sW = sX + GEM_XF2;
#pragma unroll
        for (int ks = 0; ks < 2; ks++) {
            int kb = ks * 8;
            uint32_t a[2][4];
#pragma unroll
            for (int i = 0; i < 2; i++) {
                int row = wm * 32 + i * 16 + g;
                a[i][0] = sW[row * WSTR2 + kb + tg];
                a[i][1] = sW[(row + 8) * WSTR2 + kb + tg];
                a[i][2] = sW[row * WSTR2 + kb + tg + 4];
                a[i][3] = sW[(row + 8) * WSTR2 + kb + tg + 4];
            }
#pragma unroll
            for (int j = 0; j < 8; j++) {
                int px = wn * 64 + j * 8 + g;
                uint32_t b0 = sX[(kb + tg) * XSTR2 + px];
                uint32_t b1 = sX[(kb + tg + 4) * XSTR2 + px];
                mma_f16(acc[0][j], a[0][0], a[0][1], a[0][2], a[0][3], b0, b1);
                mma_f16(acc[1][j], a[1][0], a[1][1], a[1][2], a[1][3], b0, b1);
            }
        }
        __syncthreads();
    }

#pragma unroll
    for (int i = 0; i < 2; i++) {
        int oc_lo = ocT * 64 + wm * 32 + i * 16 + g;
        int oc_hi = oc_lo + 8;
        float sc0 = 1.f, sh0 = 0.f, sc1 = 1.f, sh1 = 0.f;
        if (bng) {
            sc0 = bng[oc_lo] * rsqrtf(bnv[oc_lo] + EPS); sh0 = bnb[oc_lo] - bnm[oc_lo] * sc0;
            sc1 = bng[oc_hi] * rsqrtf(bnv[oc_hi] + EPS); sh1 = bnb[oc_hi] - bnm[oc_hi] * sc1;
        }
#pragma unroll
        for (int j = 0; j < 8; j++) {
            int px = p0 + wn * 64 + j * 8 + 2 * tg;
            float* o0 = &out[((size_t)bb * OC + oc_lo) * HW + px];
            float* o1 = &out[((size_t)bb * OC + oc_hi) * HW + px];
            o0[0] = acc[i][j][0] * sc0 + sh0;
            o0[1] = acc[i][j][1] * sc0 + sh0;
            o1[0] = acc[i][j][2] * sc1 + sh1;
            o1[1] = acc[i][j][3] * sc1 + sh1;
        }
    }
}

// ---------------- KxK conv via fp16 MMA, double-buffered ---------------------
// input half2 interleaved; weights [chunk16][tap][64oc][16ic] half.
template<int KS, bool ADD_HIGH>
__global__ __launch_bounds__(256, (KS == 3 ? 2 : 1))
void conv_h(const __half* __restrict__ in, const __half* __restrict__ wt,
            const float* __restrict__ bng, const float* __restrict__ bnb,
            const float* __restrict__ bnm, const float* __restrict__ bnv,
            float* __restrict__ out,
            const float* __restrict__ khbuf, float* __restrict__ out2)
{
    constexpr int PAD = KS / 2;
    constexpr int PH = 8 + KS - 1;
    constexpr int PW = 32 + KS - 1;
    constexpr int PWS2 = (KS == 5) ? 38 : 36;   // icpair stride PH*PWS2 % 32 == 8
    constexpr int KKS = KS * KS;
    constexpr int PATCH2 = 8 * PH * PWS2;       // half2 units
    constexpr int WGT2 = KKS * 512;             // half2 units
    constexpr int STG2 = PATCH2 + WGT2;

    extern __shared__ uint32_t smem2[];

    const int w0 = blockIdx.x * 32;
    const int h0 = blockIdx.y * 8;
    const int bb  = blockIdx.z >> 2;
    const int ocT = blockIdx.z & 3;
    const int t = threadIdx.x;
    const int warp = t >> 5, lane = t & 31;
    const int g = lane >> 2, tg = lane & 3;
    const int wm = warp >> 2;
    const int wn = warp & 3;

    const __half2* in2 = reinterpret_cast<const __half2*>(in) + (size_t)bb * 128 * HW;

    auto load = [&](int s, int chunk) {
        uint32_t* sP = smem2 + s * STG2;
        __half* sWh = reinterpret_cast<__half*>(sP + PATCH2);
        for (int e = t; e < 8 * PH * PW; e += 256) {
            int icp = e / (PH * PW), rem = e % (PH * PW);
            int row = rem / PW, cc = rem % PW;
            int h = h0 + row - PAD, w = w0 + cc - PAD;
            bool ok = ((unsigned)h < HDIM) && ((unsigned)w < WDIM);
            cp4z(&sP[icp * PH * PWS2 + row * PWS2 + cc],
                 in2 + (chunk * 8 + icp) * HW + (ok ? h : 0) * WDIM + (ok ? w : 0), ok);
        }
        const __half* wb = wt + (size_t)(ocT * 16 + chunk) * (KKS * 1024);
        for (int e = t * 8; e < KKS * 1024; e += 2048)
            cp16(&sWh[e], &wb[e]);
    };

    float acc[2][8][4];
#pragma unroll
    for (int i = 0; i < 2; i++)
#pragma unroll
        for (int j = 0; j < 8; j++)
#pragma unroll
            for (int c = 0; c < 4; c++) acc[i][j][c] = 0.f;

    load(0, 0);
    cp_commit();

    for (int chunk = 0; chunk < 16; chunk++) {
        int cur = chunk & 1;
        if (chunk + 1 < 16) load(cur ^ 1, chunk + 1);
        cp_commit();
        cp_wait1();
        __syncthreads();

        uint32_t* sP = smem2 + cur * STG2;
        uint32_t* sW = sP + PATCH2;
#pragma unroll
        for (int ky = 0; ky < KS; ky++)
#pragma unroll
            for (int kx = 0; kx < KS; kx++) {
                const int tap = ky * KS + kx;
                uint32_t a[2][4];
#pragma unroll
                for (int i = 0; i < 2; i++) {
                    int row = wm * 32 + i * 16 + g;
                    a[i][0] = sW[tap * 512 + row * 8 + tg];
                    a[i][1] = sW[tap * 512 + (row + 8) * 8 + tg];
                    a[i][2] = sW[tap * 512 + row * 8 + tg + 4];
                    a[i][3] = sW[tap * 512 + (row + 8) * 8 + tg + 4];
                }
#pragma unroll
                for (int j = 0; j < 8; j++) {
                    int hr = wn * 2 + (j >> 2) + ky;
                    int wc = (j & 3) * 8 + kx + g;
                    uint32_t b0 = sP[tg * PH * PWS2 + hr * PWS2 + wc];
                    uint32_t b1 = sP[(tg + 4) * PH * PWS2 + hr * PWS2 + wc];
                    mma_f16(acc[0][j], a[0][0], a[0][1], a[0][2], a[0][3], b0, b1);
                    mma_f16(acc[1][j], a[1][0], a[1][1], a[1][2], a[1][3], b0, b1);
                }
            }
        __syncthreads();
    }

#pragma unroll
    for (int i = 0; i < 2; i++) {
        int oc_lo = ocT * 64 + wm * 32 + i * 16 + g;
        int oc_hi = oc_lo + 8;
        float sc0 = bng[oc_lo] * rsqrtf(bnv[oc_lo] + EPS);
        float sh0 = bnb[oc_lo] - bnm[oc_lo] * sc0;
        float sc1 = bng[oc_hi] * rsqrtf(bnv[oc_hi] + EPS);
        float sh1 = bnb[oc_hi] - bnm[oc_hi] * sc1;
#pragma unroll
        for (int j = 0; j < 8; j++) {
            int h = h0 + wn * 2 + (j >> 2);
            int w = w0 + (j & 3) * 8 + 2 * tg;
            size_t i0 = ((size_t)(bb * CDIM + oc_lo) * HDIM + h) * WDIM + w;
            size_t i1 = ((size_t)(bb * CDIM + oc_hi) * HDIM + h) * WDIM + w;
            float v00 = acc[i][j][0] * sc0 + sh0;
            float v01 = acc[i][j][1] * sc0 + sh0;
            float v10 = acc[i][j][2] * sc1 + sh1;
            float v11 = acc[i][j][3] * sc1 + sh1;
            out[i0] = v00; out[i0 + 1] = v01;
            out[i1] = v10; out[i1 + 1] = v11;
            if (ADD_HIGH) {
                out2[i0] = v00 + khbuf[i0]; out2[i0 + 1] = v01 + khbuf[i0 + 1];
                out2[i1] = v10 + khbuf[i1]; out2[i1 + 1] = v11 + khbuf[i1 + 1];
            }
        }
    }
}

// ---------------- window attention (R6 version) ------------------------------
__global__ __launch_bounds__(64)
void attn_kernel(const float* __restrict__ qkv, const float* __restrict__ qh,
                 const float* __restrict__ kh, const float* __restrict__ rel_table,
                 float* __restrict__ low)
{
    __shared__ float sQ [16 * 64];
    __shared__ float sK [16 * 64];
    __shared__ float sV [16 * 64];
    __shared__ float sQH[16 * 64];
    __shared__ float sKH[16 * 64];
    __shared__ float sRT[225];

    const int wi = blockIdx.x;
    const int head = blockIdx.y;
    const int bb = blockIdx.z;
    const int hh = wi >> 4, ww = wi & 15;
    const int n = threadIdx.x;
    const int rn = n >> 3, cn = n & 7;

    for (int u = n; u < 1280; u += 64) {
        int a = u >> 8;
        int unit = u & 255;
        int ch = unit >> 4, px4 = unit & 15;
        int row = px4 >> 1, col = (px4 & 1) * 4;
        const float* gsrc;
        if (a < 3)
            gsrc = qkv + ((size_t)(bb * 768 + a * 256 + head * 16 + ch) * HDIM + hh * 8 + row) * WDIM + ww * 8 + col;
        else if (a == 3)
            gsrc = qh  + ((size_t)(bb * CDIM + head * 16 + ch) * HDIM + hh * 8 + row) * WDIM + ww * 8 + col;
        else
            gsrc = kh  + ((size_t)(bb * CDIM + head * 16 + ch) * HDIM + hh * 8 + row) * WDIM + ww * 8 + col;
        float4 v = *reinterpret_cast<const float4*>(gsrc);
        float* dst = (a == 0) ? sQ : (a == 1) ? sK : (a == 2) ? sV : (a == 3) ? sQH : sKH;
        *reinterpret_cast<float4*>(&dst[ch * 64 + px4 * 4]) = v;
    }
    for (int i = n; i < 225; i += 64) sRT[i] = rel_table[i * NHEAD + head];
    __syncthreads();

    float qr[16], qhr[16];
#pragma unroll
    for (int d = 0; d < 16; d++) {
        qr[d]  = sQ [d * 64 + n];
        qhr[d] = sQH[d * 64 + n];
    }

    const float scale = 0.25f;
    float dots[64];
#pragma unroll
    for (int m = 0; m < 64; m++) dots[m] = 0.f;
#pragma unroll
    for (int d = 0; d < 16; d++) {
        float qd = qr[d], qhd = qhr[d];
        const float4* k4  = reinterpret_cast<const float4*>(&sK [d * 64]);
        const float4* kh4 = reinterpret_cast<const float4*>(&sKH[d * 64]);
#pragma unroll
        for (int m4 = 0; m4 < 16; m4++) {
            float4 kv = k4[m4], khv = kh4[m4];
            dots[m4 * 4 + 0] += qd * kv.x + qhd * khv.x;
            dots[m4 * 4 + 1] += qd * kv.y + qhd * khv.y;
            dots[m4 * 4 + 2] += qd * kv.z + qhd * khv.z;
            dots[m4 * 4 + 3] += qd * kv.w + qhd * khv.w;
        }
    }
#pragma unroll
    for (int m = 0; m < 64; m++) {
        int rm = m >> 3, cm = m & 7;
        int idx = (rn - rm + 7) * 15 + (cn - cm + 7);
        dots[m] = dots[m] * scale + sRT[idx];
    }
    float mx = -1e30f;
#pragma unroll
    for (int m = 0; m < 64; m++) mx = fmaxf(mx, dots[m]);
    float sum = 0.f;
#pragma unroll
    for (int m = 0; m < 64; m++) { float e = __expf(dots[m] - mx); sum += e; dots[m] = e; }
    float inv = 1.f / sum;
#pragma unroll
    for (int m = 0; m < 64; m++) dots[m] *= inv;

    float o[16];
#pragma unroll
    for (int d = 0; d < 16; d++) {
        const float4* v4 = reinterpret_cast<const float4*>(&sV[d * 64]);
        float a0 = 0.f;
#pragma unroll
        for (int m4 = 0; m4 < 16; m4++) {
            float4 vv = v4[m4];
            a0 += dots[m4 * 4 + 0] * vv.x + dots[m4 * 4 + 1] * vv.y
                + dots[m4 * 4 + 2] * vv.z + dots[m4 * 4 + 3] * vv.w;
        }
        o[d] = a0;
    }

    __syncthreads();
#pragma unroll
    for (int d = 0; d < 16; d++) sQ[d * 64 + n] = o[d];
    __syncthreads();
    for (int u = n; u < 256; u += 64) {
        int ch = u >> 4, px4 = u & 15;
        int row = px4 >> 1, col = (px4 & 1) * 4;
        float4 v = *reinterpret_cast<const float4*>(&sQ[ch * 64 + px4 * 4]);
        *reinterpret_cast<float4*>(
            &low[((size_t)(bb * CDIM + head * 16 + ch) * HDIM + hh * 8 + row) * WDIM + ww * 8 + col]) = v;
    }
}

// ---------------- channel mean/max pool --------------------------------------
__global__ void pool_kernel(const float* __restrict__ low, const float* __restrict__ high,
                            float* __restrict__ pool)
{
    int p = blockIdx.x * 256 + threadIdx.x;
    int bb = blockIdx.y;
    const float* lb = low  + (size_t)bb * CDIM * HW;
    const float* hb = high + (size_t)bb * CDIM * HW;
    float s = 0.f, mx = -1e30f;
    for (int c = 0; c < CDIM; c++) {
        float v = lb[c * HW + p] + hb[c * HW + p];
        s += v; mx = fmaxf(mx, v);
    }
    pool[(bb * 2 + 0) * HW + p] = s * (1.f / 256.f);
    pool[(bb * 2 + 1) * HW + p] = mx;
}

// ---------------- hybrid 7x7 conv (2->2) + sigmoid ---------------------------
__global__ void hybrid_kernel(const float* __restrict__ pool, const float* __restrict__ hw,
                              const float* __restrict__ hb, float* __restrict__ sig)
{
    __shared__ float sw[196];
    __shared__ float sb[2];
    int t = threadIdx.x;
    if (t < 196) sw[t] = hw[t];
    if (t < 2) sb[t] = hb[t];
    __syncthreads();
    int p = blockIdx.x * 256 + t;
    int bb = blockIdx.y;
    int h = p >> 7, w = p & 127;
#pragma unroll
    for (int oc = 0; oc < 2; oc++) {
        float acc = sb[oc];
#pragma unroll
        for (int ic = 0; ic < 2; ic++)
            for (int ky = 0; ky < 7; ky++) {
                int hy = h + ky - 3;
                if (hy < 0 || hy >= HDIM) continue;
                for (int kx = 0; kx < 7; kx++) {
                    int wx = w + kx - 3;
                    if (wx < 0 || wx >= WDIM) continue;
                    acc += pool[(bb * 2 + ic) * HW + hy * WDIM + wx] * sw[((oc * 2 + ic) * 7 + ky) * 7 + kx];
                }
            }
        sig[(bb * 2 + oc) * HW + p] = 1.f / (1.f + __expf(-acc));
    }
}

// ---------------- mix -> half2 interleaved (feeds conv5) ---------------------
__global__ void mix_h(const float* __restrict__ low, const float* __restrict__ high,
                      const float* __restrict__ sig, __half* __restrict__ out)
{
    int i = blockIdx.x * 256 + threadIdx.x;            // over BDIM*128*HW
    int p = i & (HW - 1);
    int rest = i >> 14;
    int cp = rest & 127;
    int b = rest >> 7;
    float s0 = sig[(b * 2 + 0) * HW + p];
    float s1 = sig[(b * 2 + 1) * HW + p];
    size_t base = ((size_t)(b * CDIM + 2 * cp)) * HW + p;
    float m0 = low[base] * s0 + high[base] * s1;
    float m1 = low[base + HW] * s0 + high[base + HW] * s1;
    reinterpret_cast<__half2*>(out)[i] = __floats2half2_rn(m0, m1);
}

// ---------------- depthwise 7x7 + BN -> half interleaved (feeds pw GEMM) -----
__global__ void dw_kernel(const float* __restrict__ in, const float* __restrict__ w,
                          const float* __restrict__ bng, const float* __restrict__ bnb,
                          const float* __restrict__ bnm, const float* __restrict__ bnv,
                          __half* __restrict__ out)
{
    __shared__ float sT[14 * 38];
    __shared__ float sWc[49];
    const int w0 = blockIdx.x * 32;
    const int h0 = blockIdx.y * 8;
    const int bc = blockIdx.z;
    const int b = bc >> 8, c = bc & 255;
    const int tx = threadIdx.x, ty = threadIdx.y;
    const int t = ty * 32 + tx;
    if (t < 49) sWc[t] = w[c * 49 + t];
    const float* inb = in + (size_t)bc * HW;
    for (int e = t; e < 14 * 38; e += 256) {
        int row = e / 38, cc = e % 38;
        int h = h0 + row - 3, ww = w0 + cc - 3;
        float v = 0.f;
        if (h >= 0 && h < HDIM && ww >= 0 && ww < WDIM) v = inb[h * WDIM + ww];
        sT[e] = v;
    }
    __syncthreads();
    float acc = 0.f;
#pragma unroll
    for (int ky = 0; ky < 7; ky++)
#pragma unroll
        for (int kx = 0; kx < 7; kx++)
            acc += sT[(ty + ky) * 38 + tx + kx] * sWc[ky * 7 + kx];
    float sc = bng[c] * rsqrtf(bnv[c] + EPS);
    float sh = bnb[c] - bnm[c] * sc;
    int pix = (h0 + ty) * WDIM + w0 + tx;
    out[((size_t)(b * 128 + (c >> 1)) * HW + pix) * 2 + (c & 1)] = __float2half_rn(acc * sc + sh);
}

// ---------------- launch ------------------------------------------------------
extern "C" void kernel_launch(void* const* d_in, const int* in_sizes, int n_in,
                              void* d_out, int out_size)
{
    const float* x        = (const float*)d_in[0];
    const float* qkv_w    = (const float*)d_in[1];
    const float* local1_w = (const float*)d_in[2];
    const float* l1g = (const float*)d_in[3];
    const float* l1b = (const float*)d_in[4];
    const float* l1m = (const float*)d_in[5];
    const float* l1v = (const float*)d_in[6];
    const float* local2_w = (const float*)d_in[7];
    const float* l2g = (const float*)d_in[8];
    const float* l2b = (const float*)d_in[9];
    const float* l2m = (const float*)d_in[10];
    const float* l2v = (const float*)d_in[11];
    const float* rel_table = (const float*)d_in[12];
    const float* hybrid_w  = (const float*)d_in[13];
    const float* hybrid_b  = (const float*)d_in[14];
    const float* smooth_w  = (const float*)d_in[15];
    const float* smg = (const float*)d_in[16];
    const float* smb = (const float*)d_in[17];
    const float* smm = (const float*)d_in[18];
    const float* smv = (const float*)d_in[19];
    const float* proj_dw_w = (const float*)d_in[20];
    const float* prg = (const float*)d_in[21];
    const float* prb = (const float*)d_in[22];
    const float* prm = (const float*)d_in[23];
    const float* prv = (const float*)d_in[24];
    const float* proj_pw_w = (const float*)d_in[25];

    float *p_qh, *p_kh, *p_high, *p_qkv, *p_low, *p_sm, *p_pool, *p_sig;
    __half *p_xh, *p_mixh, *p_dwh, *p_w5t, *p_w3t, *p_wq, *p_w2, *p_wp;
    cudaGetSymbolAddress((void**)&p_qh,   g_qh);
    cudaGetSymbolAddress((void**)&p_kh,   g_kh);
    cudaGetSymbolAddress((void**)&p_high, g_high);
    cudaGetSymbolAddress((void**)&p_qkv,  g_qkv);
    cudaGetSymbolAddress((void**)&p_low,  g_low);
    cudaGetSymbolAddress((void**)&p_sm,   g_sm);
    cudaGetSymbolAddress((void**)&p_pool, g_pool);
    cudaGetSymbolAddress((void**)&p_sig,  g_sig);
    cudaGetSymbolAddress((void**)&p_xh,   g_xh);
    cudaGetSymbolAddress((void**)&p_mixh, g_mixh);
    cudaGetSymbolAddress((void**)&p_dwh,  g_dwh);
    cudaGetSymbolAddress((void**)&p_w5t,  g_w5t);
    cudaGetSymbolAddress((void**)&p_w3t,  g_w3t);
    cudaGetSymbolAddress((void**)&p_wq,   g_wq);
    cudaGetSymbolAddress((void**)&p_w2,   g_w2);
    cudaGetSymbolAddress((void**)&p_wp,   g_wp);

    // smem sizes (bytes): conv stage = PATCH2 + WGT2 half2 units
    const int smem3 = 2 * (8 * 10 * 36 + 9  * 512) * 4;   // 59904 B
    const int smem5 = 2 * (8 * 12 * 38 + 25 * 512) * 4;   // 131584 B
    const int smemG = 2 * GEM_STG2 * 4;                   // 44032 B
    cudaFuncSetAttribute(conv_h<5, false>, cudaFuncAttributeMaxDynamicSharedMemorySize, smem5);
    cudaFuncSetAttribute(conv_h<3, true>,  cudaFuncAttributeMaxDynamicSharedMemorySize, smem3);
    cudaFuncSetAttribute(gemm1x1_h,        cudaFuncAttributeMaxDynamicSharedMemorySize, smemG);

    // ---- pre-pass ----
    interleave_h<<<BDIM * 128 * HW / 256, 256>>>(x, p_xh);
    roundw_h<<<(3 * CDIM * CDIM + 255) / 256, 256>>>(qkv_w, p_wq, 3 * CDIM * CDIM);
    roundw_h<<<(CDIM * CDIM + 255) / 256, 256>>>(local2_w, p_w2, CDIM * CDIM);
    roundw_h<<<(CDIM * CDIM + 255) / 256, 256>>>(proj_pw_w, p_wp, CDIM * CDIM);
    wtransform_h<9><<<(CDIM * CDIM * 9 + 255) / 256, 256>>>(local1_w, p_w3t);
    wtransform_h<25><<<(CDIM * CDIM * 25 + 255) / 256, 256>>>(smooth_w, p_w5t);

    // ---- main chain ----
    gemm1x1_h<<<dim3(64, 12, 4), 256, smemG>>>(p_xh, p_wq, nullptr, nullptr, nullptr, nullptr, p_qkv, 768);
    gemm1x1_h<<<dim3(64, 4, 4), 256, smemG>>>(p_xh, p_w2, l2g, l2b, l2m, l2v, p_kh, 256);
    conv_h<3, true><<<dim3(4, 16, 16), 256, smem3>>>(p_xh, p_w3t, l1g, l1b, l1m, l1v,
                                                     p_qh, p_kh, p_high);
    attn_kernel<<<dim3(256, 16, 4), 64>>>(p_qkv, p_qh, p_kh, rel_table, p_low);
    pool_kernel<<<dim3(64, 4), 256>>>(p_low, p_high, p_pool);
    hybrid_kernel<<<dim3(64, 4), 256>>>(p_pool, hybrid_w, hybrid_b, p_sig);
    mix_h<<<BDIM * 128 * HW / 256, 256>>>(p_low, p_high, p_sig, p_mixh);
    conv_h<5, false><<<dim3(4, 16, 16), 256, smem5>>>(p_mixh, p_w5t, smg, smb, smm, smv,
                                                      p_sm, nullptr, nullptr);
    dw_kernel<<<dim3(4, 16, 1024), dim3(32, 8)>>>(p_sm, proj_dw_w, prg, prb, prm, prv, p_dwh);
    gemm1x1_h<<<dim3(64, 4, 4), 256, smemG>>>(p_dwh, p_wp, nullptr, nullptr, nullptr, nullptr,
                                              (float*)d_out, 256);
}

// round 13
// speedup vs baseline: 1.9264x; 1.1725x over previous
#include <cuda_runtime.h>
#include <cuda_fp16.h>
#include <math.h>
#include <stdint.h>

#define HDIM 128
#define WDIM 128
#define HW (HDIM*WDIM)
#define CDIM 256
#define BDIM 4
#define NHEAD 16
#define EPS 1e-5f

// ---------------- scratch ----------------------------------------------------
__device__ float  g_qh  [BDIM*CDIM*HW];
__device__ float  g_kh  [BDIM*CDIM*HW];
__device__ float  g_high[BDIM*CDIM*HW];
__device__ float  g_qkv [BDIM*3*CDIM*HW];
__device__ float  g_low [BDIM*CDIM*HW];
__device__ float  g_sm  [BDIM*CDIM*HW];
__device__ float  g_pool[BDIM*2*HW];
__device__ float  g_sig [BDIM*2*HW];
// half activations (channel-pair interleaved [C/2][H][W][2])
__device__ __half g_xh  [BDIM*CDIM*HW];
__device__ __half g_mixh[BDIM*CDIM*HW];
__device__ __half g_dwh [BDIM*CDIM*HW];
// half weights
__device__ __half g_w5t [CDIM*CDIM*25];
__device__ __half g_w3t [CDIM*CDIM*9];
__device__ __half g_wq  [3*CDIM*CDIM];
__device__ __half g_w2  [CDIM*CDIM];
__device__ __half g_wp  [CDIM*CDIM];

// ---------------- helpers ----------------------------------------------------
__device__ __forceinline__ void cp16(void* dst, const void* src) {
    uint32_t d = (uint32_t)__cvta_generic_to_shared(dst);
    asm volatile("cp.async.cg.shared.global [%0], [%1], 16;" :: "r"(d), "l"(src));
}
__device__ __forceinline__ void cp4z(void* dst, const void* src, bool pred) {
    uint32_t d = (uint32_t)__cvta_generic_to_shared(dst);
    int sz = pred ? 4 : 0;
    asm volatile("cp.async.ca.shared.global [%0], [%1], 4, %2;" :: "r"(d), "l"(src), "r"(sz));
}
__device__ __forceinline__ void cp_commit() { asm volatile("cp.async.commit_group;"); }
__device__ __forceinline__ void cp_wait1()  { asm volatile("cp.async.wait_group 1;"); }

__device__ __forceinline__ void mma_f16(float* d, uint32_t a0, uint32_t a1,
                                        uint32_t a2, uint32_t a3,
                                        uint32_t b0, uint32_t b1) {
    asm volatile(
        "mma.sync.aligned.m16n8k16.row.col.f32.f16.f16.f32 "
        "{%0,%1,%2,%3}, {%4,%5,%6,%7}, {%8,%9}, {%0,%1,%2,%3};"
        : "+f"(d[0]), "+f"(d[1]), "+f"(d[2]), "+f"(d[3])
        : "r"(a0), "r"(a1), "r"(a2), "r"(a3), "r"(b0), "r"(b1));
}

__device__ __forceinline__ uint32_t h2u(__half2 h) {
    return *reinterpret_cast<uint32_t*>(&h);
}

// ---------------- pre-pass kernels -------------------------------------------
__global__ void interleave_h(const float* __restrict__ in, __half* __restrict__ out)
{
    int i = blockIdx.x * 256 + threadIdx.x;
    int p = i & (HW - 1);
    int rest = i >> 14;
    int cp = rest & 127;
    int b = rest >> 7;
    const float* base = in + ((size_t)(b * CDIM + 2 * cp)) * HW + p;
    reinterpret_cast<__half2*>(out)[i] = __floats2half2_rn(base[0], base[HW]);
}

__global__ void roundw_h(const float* __restrict__ in, __half* __restrict__ out, int n)
{
    int i = blockIdx.x * 256 + threadIdx.x;
    if (i < n) out[i] = __float2half_rn(in[i]);
}

template<int KKS>
__global__ void wtransform_h(const float* __restrict__ wgt, __half* __restrict__ dst)
{
    int tid = blockIdx.x * 256 + threadIdx.x;
    int total = 4 * 16 * KKS * 1024;
    if (tid >= total) return;
    int ic  = tid & 15;
    int oc  = (tid >> 4) & 63;
    int tap = (tid >> 10) % KKS;
    int ics = (tid / (1024 * KKS)) & 15;
    int ocT = tid / (1024 * KKS * 16);
    dst[tid] = __float2half_rn(wgt[((size_t)((ocT * 64 + oc) * 256 + ics * 16 + ic)) * KKS + tap]);
}

// ---------------- 1x1 conv as fp16 GEMM, cp.async double-buffered ------------
#define XSTR2 264
#define WSTR2 20
#define GEM_XF2 (16*XSTR2)
#define GEM_WF2 (64*WSTR2)
#define GEM_STG2 (GEM_XF2+GEM_WF2)

__global__ __launch_bounds__(256, 2)
void gemm1x1_h(const __half* __restrict__ in, const __half* __restrict__ w,
               const float* __restrict__ bng, const float* __restrict__ bnb,
               const float* __restrict__ bnm, const float* __restrict__ bnv,
               float* __restrict__ out, int OC)
{
    extern __shared__ uint32_t smem2[];

    const int bb  = blockIdx.z;
    const int ocT = blockIdx.y;
    const int p0  = blockIdx.x * 256;
    const int t   = threadIdx.x;
    const int warp = t >> 5, lane = t & 31;
    const int g = lane >> 2, tg = lane & 3;
    const int wm = warp >> 2;
    const int wn = warp & 3;

    const __half2* in2 = reinterpret_cast<const __half2*>(in) + (size_t)bb * 128 * HW;

    auto load = [&](int s, int ic0) {
        uint32_t* sX = smem2 + s * GEM_STG2;
        uint32_t* sW = sX + GEM_XF2;
        int cp0 = ic0 >> 1;
#pragma unroll
        for (int j = 0; j < 4; j++) {
            int idx = j * 256 + t;
            int icp = idx >> 6, px4 = idx & 63;
            cp16(&sX[icp * XSTR2 + px4 * 4], in2 + (cp0 + icp) * HW + p0 + px4 * 4);
        }
        {
            int oc = t >> 2, icq = t & 3;
            cp16(&sW[oc * WSTR2 + icq * 4],
                 w + (size_t)(ocT * 64 + oc) * CDIM + ic0 + icq * 8);
        }
    };

    float acc[2][8][4];
#pragma unroll
    for (int i = 0; i < 2; i++)
#pragma unroll
        for (int j = 0; j < 8; j++)
#pragma unroll
            for (int c = 0; c < 4; c++) acc[i][j][c] = 0.f;

    load(0, 0);
    cp_commit();

    for (int ic0 = 0; ic0 < CDIM; ic0 += 32) {
        int cur = (ic0 >> 5) & 1;
        if (ic0 + 32 < CDIM) load(cur ^ 1, ic0 + 32);
        cp_commit();
        cp_wait1();
        __syncthreads();

        uint32_t* sX = smem2 + cur * GEM_STG2;
        uint32_t* sW = sX + GEM_XF2;
#pragma unroll
        for (int ks = 0; ks < 2; ks++) {
            int kb = ks * 8;
            uint32_t a[2][4];
#pragma unroll
            for (int i = 0; i < 2; i++) {
                int row = wm * 32 + i * 16 + g;
                a[i][0] = sW[row * WSTR2 + kb + tg];
                a[i][1] = sW[(row + 8) * WSTR2 + kb + tg];
                a[i][2] = sW[row * WSTR2 + kb + tg + 4];
                a[i][3] = sW[(row + 8) * WSTR2 + kb + tg + 4];
            }
#pragma unroll
            for (int j = 0; j < 8; j++) {
                int px = wn * 64 + j * 8 + g;
                uint32_t b0 = sX[(kb + tg) * XSTR2 + px];
                uint32_t b1 = sX[(kb + tg + 4) * XSTR2 + px];
                mma_f16(acc[0][j], a[0][0], a[0][1], a[0][2], a[0][3], b0, b1);
                mma_f16(acc[1][j], a[1][0], a[1][1], a[1][2], a[1][3], b0, b1);
            }
        }
        __syncthreads();
    }

#pragma unroll
    for (int i = 0; i < 2; i++) {
        int oc_lo = ocT * 64 + wm * 32 + i * 16 + g;
        int oc_hi = oc_lo + 8;
        float sc0 = 1.f, sh0 = 0.f, sc1 = 1.f, sh1 = 0.f;
        if (bng) {
            sc0 = bng[oc_lo] * rsqrtf(bnv[oc_lo] + EPS); sh0 = bnb[oc_lo] - bnm[oc_lo] * sc0;
            sc1 = bng[oc_hi] * rsqrtf(bnv[oc_hi] + EPS); sh1 = bnb[oc_hi] - bnm[oc_hi] * sc1;
        }
#pragma unroll
        for (int j = 0; j < 8; j++) {
            int px = p0 + wn * 64 + j * 8 + 2 * tg;
            float* o0 = &out[((size_t)bb * OC + oc_lo) * HW + px];
            float* o1 = &out[((size_t)bb * OC + oc_hi) * HW + px];
            o0[0] = acc[i][j][0] * sc0 + sh0;
            o0[1] = acc[i][j][1] * sc0 + sh0;
            o1[0] = acc[i][j][2] * sc1 + sh1;
            o1[1] = acc[i][j][3] * sc1 + sh1;
        }
    }
}

// ---------------- KxK conv via fp16 MMA, double-buffered ---------------------
template<int KS, bool ADD_HIGH>
__global__ __launch_bounds__(256, (KS == 3 ? 2 : 1))
void conv_h(const __half* __restrict__ in, const __half* __restrict__ wt,
            const float* __restrict__ bng, const float* __restrict__ bnb,
            const float* __restrict__ bnm, const float* __restrict__ bnv,
            float* __restrict__ out,
            const float* __restrict__ khbuf, float* __restrict__ out2)
{
    constexpr int PAD = KS / 2;
    constexpr int PH = 8 + KS - 1;
    constexpr int PW = 32 + KS - 1;
    constexpr int PWS2 = (KS == 5) ? 38 : 36;
    constexpr int KKS = KS * KS;
    constexpr int PATCH2 = 8 * PH * PWS2;
    constexpr int WGT2 = KKS * 512;
    constexpr int STG2 = PATCH2 + WGT2;

    extern __shared__ uint32_t smem2[];

    const int w0 = blockIdx.x * 32;
    const int h0 = blockIdx.y * 8;
    const int bb  = blockIdx.z >> 2;
    const int ocT = blockIdx.z & 3;
    const int t = threadIdx.x;
    const int warp = t >> 5, lane = t & 31;
    const int g = lane >> 2, tg = lane & 3;
    const int wm = warp >> 2;
    const int wn = warp & 3;

    const __half2* in2 = reinterpret_cast<const __half2*>(in) + (size_t)bb * 128 * HW;

    auto load = [&](int s, int chunk) {
        uint32_t* sP = smem2 + s * STG2;
        __half* sWh = reinterpret_cast<__half*>(sP + PATCH2);
        for (int e = t; e < 8 * PH * PW; e += 256) {
            int icp = e / (PH * PW), rem = e % (PH * PW);
            int row = rem / PW, cc = rem % PW;
            int h = h0 + row - PAD, w = w0 + cc - PAD;
            bool ok = ((unsigned)h < HDIM) && ((unsigned)w < WDIM);
            cp4z(&sP[icp * PH * PWS2 + row * PWS2 + cc],
                 in2 + (chunk * 8 + icp) * HW + (ok ? h : 0) * WDIM + (ok ? w : 0), ok);
        }
        const __half* wb = wt + (size_t)(ocT * 16 + chunk) * (KKS * 1024);
        for (int e = t * 8; e < KKS * 1024; e += 2048)
            cp16(&sWh[e], &wb[e]);
    };

    float acc[2][8][4];
#pragma unroll
    for (int i = 0; i < 2; i++)
#pragma unroll
        for (int j = 0; j < 8; j++)
#pragma unroll
            for (int c = 0; c < 4; c++) acc[i][j][c] = 0.f;

    load(0, 0);
    cp_commit();

    for (int chunk = 0; chunk < 16; chunk++) {
        int cur = chunk & 1;
        if (chunk + 1 < 16) load(cur ^ 1, chunk + 1);
        cp_commit();
        cp_wait1();
        __syncthreads();

        uint32_t* sP = smem2 + cur * STG2;
        uint32_t* sW = sP + PATCH2;
#pragma unroll
        for (int ky = 0; ky < KS; ky++)
#pragma unroll
            for (int kx = 0; kx < KS; kx++) {
                const int tap = ky * KS + kx;
                uint32_t a[2][4];
#pragma unroll
                for (int i = 0; i < 2; i++) {
                    int row = wm * 32 + i * 16 + g;
                    a[i][0] = sW[tap * 512 + row * 8 + tg];
                    a[i][1] = sW[tap * 512 + (row + 8) * 8 + tg];
                    a[i][2] = sW[tap * 512 + row * 8 + tg + 4];
                    a[i][3] = sW[tap * 512 + (row + 8) * 8 + tg + 4];
                }
#pragma unroll
                for (int j = 0; j < 8; j++) {
                    int hr = wn * 2 + (j >> 2) + ky;
                    int wc = (j & 3) * 8 + kx + g;
                    uint32_t b0 = sP[tg * PH * PWS2 + hr * PWS2 + wc];
                    uint32_t b1 = sP[(tg + 4) * PH * PWS2 + hr * PWS2 + wc];
                    mma_f16(acc[0][j], a[0][0], a[0][1], a[0][2], a[0][3], b0, b1);
                    mma_f16(acc[1][j], a[1][0], a[1][1], a[1][2], a[1][3], b0, b1);
                }
            }
        __syncthreads();
    }

#pragma unroll
    for (int i = 0; i < 2; i++) {
        int oc_lo = ocT * 64 + wm * 32 + i * 16 + g;
        int oc_hi = oc_lo + 8;
        float sc0 = bng[oc_lo] * rsqrtf(bnv[oc_lo] + EPS);
        float sh0 = bnb[oc_lo] - bnm[oc_lo] * sc0;
        float sc1 = bng[oc_hi] * rsqrtf(bnv[oc_hi] + EPS);
        float sh1 = bnb[oc_hi] - bnm[oc_hi] * sc1;
#pragma unroll
        for (int j = 0; j < 8; j++) {
            int h = h0 + wn * 2 + (j >> 2);
            int w = w0 + (j & 3) * 8 + 2 * tg;
            size_t i0 = ((size_t)(bb * CDIM + oc_lo) * HDIM + h) * WDIM + w;
            size_t i1 = ((size_t)(bb * CDIM + oc_hi) * HDIM + h) * WDIM + w;
            float v00 = acc[i][j][0] * sc0 + sh0;
            float v01 = acc[i][j][1] * sc0 + sh0;
            float v10 = acc[i][j][2] * sc1 + sh1;
            float v11 = acc[i][j][3] * sc1 + sh1;
            out[i0] = v00; out[i0 + 1] = v01;
            out[i1] = v10; out[i1 + 1] = v11;
            if (ADD_HIGH) {
                out2[i0] = v00 + khbuf[i0]; out2[i0 + 1] = v01 + khbuf[i0 + 1];
                out2[i1] = v10 + khbuf[i1]; out2[i1 + 1] = v11 + khbuf[i1 + 1];
            }
        }
    }
}

// ---------------- window attention via fp16 tensor cores ---------------------
// Block = (window, head), 4 warps; warp w handles query rows 16w..16w+15.
// SINGLE aligned smem pool; all sections at 16B-aligned uint32 offsets.
#define AQ_OFF  0       // Q : 64 tok x 9 half2   (576 u32)
#define AK_OFF  576     // K
#define AQH_OFF 1152    // QH
#define AKH_OFF 1728    // KH
#define AVT_OFF 2304    // V^T: 16 d x 36 half2   (576 u32)
#define ART_OFF 2880    // rel bias: 225 floats (pad 228)
#define AO_OFF  3108    // O: 16 d x 68 floats    (1088 u32)
#define APOOL_SZ 4196

__global__ __launch_bounds__(128)
void attn_mma(const float* __restrict__ qkv, const float* __restrict__ qh,
              const float* __restrict__ kh, const float* __restrict__ rel_table,
              float* __restrict__ low)
{
    __shared__ __align__(16) uint32_t sPool[APOOL_SZ];

    const int wi = blockIdx.x;
    const int head = blockIdx.y;
    const int bb = blockIdx.z;
    const int hh = wi >> 4, ww = wi & 15;
    const int t = threadIdx.x;
    const int warp = t >> 5, lane = t & 31;
    const int g = lane >> 2, tg = lane & 3;

    float* sRT = reinterpret_cast<float*>(sPool + ART_OFF);
    float* sO  = reinterpret_cast<float*>(sPool + AO_OFF);

    // ---- staging: float gmem -> half smem (transposed layouts) ----
    for (int u = t; u < 1280; u += 128) {
        int a = u >> 8;
        int unit = u & 255;
        int ch = unit >> 4, px4 = unit & 15;
        int row = px4 >> 1, col = (px4 & 1) * 4;
        const float* gsrc;
        if (a < 3)
            gsrc = qkv + ((size_t)(bb * 768 + a * 256 + head * 16 + ch) * HDIM + hh * 8 + row) * WDIM + ww * 8 + col;
        else if (a == 3)
            gsrc = qh  + ((size_t)(bb * CDIM + head * 16 + ch) * HDIM + hh * 8 + row) * WDIM + ww * 8 + col;
        else
            gsrc = kh  + ((size_t)(bb * CDIM + head * 16 + ch) * HDIM + hh * 8 + row) * WDIM + ww * 8 + col;
        float4 v = *reinterpret_cast<const float4*>(gsrc);
        if (a == 2) {           // V -> transposed [d][tok]
            __half2* d2 = reinterpret_cast<__half2*>(sPool + AVT_OFF);
            int base = ch * 36 + (row * 8 + col) / 2;
            d2[base]     = __floats2half2_rn(v.x, v.y);
            d2[base + 1] = __floats2half2_rn(v.z, v.w);
        } else {
            int off = (a == 0) ? AQ_OFF : (a == 1) ? AK_OFF : (a == 3) ? AQH_OFF : AKH_OFF;
            __half* dst = reinterpret_cast<__half*>(sPool + off);
            int tok = row * 8 + col;
            dst[(tok + 0) * 18 + ch] = __float2half_rn(v.x);
            dst[(tok + 1) * 18 + ch] = __float2half_rn(v.y);
            dst[(tok + 2) * 18 + ch] = __float2half_rn(v.z);
            dst[(tok + 3) * 18 + ch] = __float2half_rn(v.w);
        }
    }
    for (int i = t; i < 225; i += 128) sRT[i] = rel_table[i * NHEAD + head];
    __syncthreads();

    const int qb = warp * 16;
    const uint32_t* q2  = sPool + AQ_OFF;
    const uint32_t* k2  = sPool + AK_OFF;
    const uint32_t* qh2 = sPool + AQH_OFF;
    const uint32_t* kh2 = sPool + AKH_OFF;
    const uint32_t* vt2 = sPool + AVT_OFF;

    // A fragments for Q and QH (k = 16 dims, one chunk)
    uint32_t aq[4], ah[4];
    aq[0] = q2[(qb + g) * 9 + tg];      aq[1] = q2[(qb + 8 + g) * 9 + tg];
    aq[2] = q2[(qb + g) * 9 + tg + 4];  aq[3] = q2[(qb + 8 + g) * 9 + tg + 4];
    ah[0] = qh2[(qb + g) * 9 + tg];     ah[1] = qh2[(qb + 8 + g) * 9 + tg];
    ah[2] = qh2[(qb + g) * 9 + tg + 4]; ah[3] = qh2[(qb + 8 + g) * 9 + tg + 4];

    // S = Q K^T + QH KH^T : 8 n-tiles of 8 key tokens
    float s[8][4];
#pragma unroll
    for (int n = 0; n < 8; n++) { s[n][0] = s[n][1] = s[n][2] = s[n][3] = 0.f; }
#pragma unroll
    for (int n = 0; n < 8; n++) {
        int kt = n * 8 + g;
        uint32_t b0 = k2[kt * 9 + tg],  b1 = k2[kt * 9 + tg + 4];
        mma_f16(s[n], aq[0], aq[1], aq[2], aq[3], b0, b1);
        b0 = kh2[kt * 9 + tg]; b1 = kh2[kt * 9 + tg + 4];
        mma_f16(s[n], ah[0], ah[1], ah[2], ah[3], b0, b1);
    }

    // scale + relative bias
    const int rq0 = qb + g, rq1 = qb + g + 8;
    const int r0h = rq0 >> 3, r0l = rq0 & 7;
    const int r1h = rq1 >> 3, r1l = rq1 & 7;
#pragma unroll
    for (int n = 0; n < 8; n++)
#pragma unroll
        for (int c = 0; c < 2; c++) {
            int m = n * 8 + 2 * tg + c;
            int mh = m >> 3, ml = m & 7;
            s[n][c]     = s[n][c]     * 0.25f + sRT[(r0h - mh + 7) * 15 + (r0l - ml + 7)];
            s[n][2 + c] = s[n][2 + c] * 0.25f + sRT[(r1h - mh + 7) * 15 + (r1l - ml + 7)];
        }

    // softmax over 64 cols; rows rq0 -> (c0,c1), rq1 -> (c2,c3); 4 lanes per row
    float mx0 = -1e30f, mx1 = -1e30f;
#pragma unroll
    for (int n = 0; n < 8; n++) {
        mx0 = fmaxf(mx0, fmaxf(s[n][0], s[n][1]));
        mx1 = fmaxf(mx1, fmaxf(s[n][2], s[n][3]));
    }
    mx0 = fmaxf(mx0, __shfl_xor_sync(0xffffffffu, mx0, 1));
    mx0 = fmaxf(mx0, __shfl_xor_sync(0xffffffffu, mx0, 2));
    mx1 = fmaxf(mx1, __shfl_xor_sync(0xffffffffu, mx1, 1));
    mx1 = fmaxf(mx1, __shfl_xor_sync(0xffffffffu, mx1, 2));
    float sum0 = 0.f, sum1 = 0.f;
#pragma unroll
    for (int n = 0; n < 8; n++) {
        s[n][0] = __expf(s[n][0] - mx0); s[n][1] = __expf(s[n][1] - mx0);
        s[n][2] = __expf(s[n][2] - mx1); s[n][3] = __expf(s[n][3] - mx1);
        sum0 += s[n][0] + s[n][1];
        sum1 += s[n][2] + s[n][3];
    }
    sum0 += __shfl_xor_sync(0xffffffffu, sum0, 1);
    sum0 += __shfl_xor_sync(0xffffffffu, sum0, 2);
    sum1 += __shfl_xor_sync(0xffffffffu, sum1, 1);
    sum1 += __shfl_xor_sync(0xffffffffu, sum1, 2);
    float inv0 = 1.f / sum0, inv1 = 1.f / sum1;
#pragma unroll
    for (int n = 0; n < 8; n++) {
        s[n][0] *= inv0; s[n][1] *= inv0;
        s[n][2] *= inv1; s[n][3] *= inv1;
    }

    // O = P V : P fragments built register-resident from S
    float o[2][4];
    o[0][0] = o[0][1] = o[0][2] = o[0][3] = 0.f;
    o[1][0] = o[1][1] = o[1][2] = o[1][3] = 0.f;
#pragma unroll
    for (int kc = 0; kc < 4; kc++) {
        uint32_t a0 = h2u(__floats2half2_rn(s[2 * kc][0],     s[2 * kc][1]));
        uint32_t a1 = h2u(__floats2half2_rn(s[2 * kc][2],     s[2 * kc][3]));
        uint32_t a2 = h2u(__floats2half2_rn(s[2 * kc + 1][0], s[2 * kc + 1][1]));
        uint32_t a3 = h2u(__floats2half2_rn(s[2 * kc + 1][2], s[2 * kc + 1][3]));
#pragma unroll
        for (int ot = 0; ot < 2; ot++) {
            uint32_t b0 = vt2[(8 * ot + g) * 36 + 8 * kc + tg];
            uint32_t b1 = vt2[(8 * ot + g) * 36 + 8 * kc + tg + 4];
            mma_f16(o[ot], a0, a1, a2, a3, b0, b1);
        }
    }

    // transpose O through smem, then coalesced float4 stores
#pragma unroll
    for (int ot = 0; ot < 2; ot++) {
        int d0 = 8 * ot + 2 * tg;
        sO[d0 * 68 + qb + g]           = o[ot][0];
        sO[(d0 + 1) * 68 + qb + g]     = o[ot][1];
        sO[d0 * 68 + qb + 8 + g]       = o[ot][2];
        sO[(d0 + 1) * 68 + qb + 8 + g] = o[ot][3];
    }
    __syncthreads();
    for (int u = t; u < 256; u += 128) {
        int ch = u >> 4, px4 = u & 15;
        int row = px4 >> 1, col = (px4 & 1) * 4;
        float4 v = *reinterpret_cast<const float4*>(&sO[ch * 68 + row * 8 + col]);
        *reinterpret_cast<float4*>(
            &low[((size_t)(bb * CDIM + head * 16 + ch) * HDIM + hh * 8 + row) * WDIM + ww * 8 + col]) = v;
    }
}

// ---------------- channel mean/max pool --------------------------------------
__global__ void pool_kernel(const float* __restrict__ low, const float* __restrict__ high,
                            float* __restrict__ pool)
{
    int p = blockIdx.x * 256 + threadIdx.x;
    int bb = blockIdx.y;
    const float* lb = low  + (size_t)bb * CDIM * HW;
    const float* hb = high + (size_t)bb * CDIM * HW;
    float s = 0.f, mx = -1e30f;
    for (int c = 0; c < CDIM; c++) {
        float v = lb[c * HW + p] + hb[c * HW + p];
        s += v; mx = fmaxf(mx, v);
    }
    pool[(bb * 2 + 0) * HW + p] = s * (1.f / 256.f);
    pool[(bb * 2 + 1) * HW + p] = mx;
}

// ---------------- hybrid 7x7 conv (2->2) + sigmoid ---------------------------
__global__ void hybrid_kernel(const float* __restrict__ pool, const float* __restrict__ hw,
                              const float* __restrict__ hb, float* __restrict__ sig)
{
    __shared__ float sw[196];
    __shared__ float sb[2];
    int t = threadIdx.x;
    if (t < 196) sw[t] = hw[t];
    if (t < 2) sb[t] = hb[t];
    __syncthreads();
    int p = blockIdx.x * 256 + t;
    int bb = blockIdx.y;
    int h = p >> 7, w = p & 127;
#pragma unroll
    for (int oc = 0; oc < 2; oc++) {
        float acc = sb[oc];
#pragma unroll
        for (int ic = 0; ic < 2; ic++)
            for (int ky = 0; ky < 7; ky++) {
                int hy = h + ky - 3;
                if (hy < 0 || hy >= HDIM) continue;
                for (int kx = 0; kx < 7; kx++) {
                    int wx = w + kx - 3;
                    if (wx < 0 || wx >= WDIM) continue;
                    acc += pool[(bb * 2 + ic) * HW + hy * WDIM + wx] * sw[((oc * 2 + ic) * 7 + ky) * 7 + kx];
                }
            }
        sig[(bb * 2 + oc) * HW + p] = 1.f / (1.f + __expf(-acc));
    }
}

// ---------------- mix -> half2 interleaved (feeds conv5) ---------------------
__global__ void mix_h(const float* __restrict__ low, const float* __restrict__ high,
                      const float* __restrict__ sig, __half* __restrict__ out)
{
    int i = blockIdx.x * 256 + threadIdx.x;
    int p = i & (HW - 1);
    int rest = i >> 14;
    int cp = rest & 127;
    int b = rest >> 7;
    float s0 = sig[(b * 2 + 0) * HW + p];
    float s1 = sig[(b * 2 + 1) * HW + p];
    size_t base = ((size_t)(b * CDIM + 2 * cp)) * HW + p;
    float m0 = low[base] * s0 + high[base] * s1;
    float m1 = low[base + HW] * s0 + high[base + HW] * s1;
    reinterpret_cast<__half2*>(out)[i] = __floats2half2_rn(m0, m1);
}

// ---------------- depthwise 7x7 + BN -> half interleaved ---------------------
__global__ void dw_kernel(const float* __restrict__ in, const float* __restrict__ w,
                          const float* __restrict__ bng, const float* __restrict__ bnb,
                          const float* __restrict__ bnm, const float* __restrict__ bnv,
                          __half* __restrict__ out)
{
    __shared__ float sT[14 * 38];
    __shared__ float sWc[49];
    const int w0 = blockIdx.x * 32;
    const int h0 = blockIdx.y * 8;
    const int bc = blockIdx.z;
    const int b = bc >> 8, c = bc & 255;
    const int tx = threadIdx.x, ty = threadIdx.y;
    const int t = ty * 32 + tx;
    if (t < 49) sWc[t] = w[c * 49 + t];
    const float* inb = in + (size_t)bc * HW;
    for (int e = t; e < 14 * 38; e += 256) {
        int row = e / 38, cc = e % 38;
        int h = h0 + row - 3, ww = w0 + cc - 3;
        float v = 0.f;
        if (h >= 0 && h < HDIM && ww >= 0 && ww < WDIM) v = inb[h * WDIM + ww];
        sT[e] = v;
    }
    __syncthreads();
    float acc = 0.f;
#pragma unroll
    for (int ky = 0; ky < 7; ky++)
#pragma unroll
        for (int kx = 0; kx < 7; kx++)
            acc += sT[(ty + ky) * 38 + tx + kx] * sWc[ky * 7 + kx];
    float sc = bng[c] * rsqrtf(bnv[c] + EPS);
    float sh = bnb[c] - bnm[c] * sc;
    int pix = (h0 + ty) * WDIM + w0 + tx;
    out[((size_t)(b * 128 + (c >> 1)) * HW + pix) * 2 + (c & 1)] = __float2half_rn(acc * sc + sh);
}

// ---------------- launch ------------------------------------------------------
extern "C" void kernel_launch(void* const* d_in, const int* in_sizes, int n_in,
                              void* d_out, int out_size)
{
    const float* x        = (const float*)d_in[0];
    const float* qkv_w    = (const float*)d_in[1];
    const float* local1_w = (const float*)d_in[2];
    const float* l1g = (const float*)d_in[3];
    const float* l1b = (const float*)d_in[4];
    const float* l1m = (const float*)d_in[5];
    const float* l1v = (const float*)d_in[6];
    const float* local2_w = (const float*)d_in[7];
    const float* l2g = (const float*)d_in[8];
    const float* l2b = (const float*)d_in[9];
    const float* l2m = (const float*)d_in[10];
    const float* l2v = (const float*)d_in[11];
    const float* rel_table = (const float*)d_in[12];
    const float* hybrid_w  = (const float*)d_in[13];
    const float* hybrid_b  = (const float*)d_in[14];
    const float* smooth_w  = (const float*)d_in[15];
    const float* smg = (const float*)d_in[16];
    const float* smb = (const float*)d_in[17];
    const float* smm = (const float*)d_in[18];
    const float* smv = (const float*)d_in[19];
    const float* proj_dw_w = (const float*)d_in[20];
    const float* prg = (const float*)d_in[21];
    const float* prb = (const float*)d_in[22];
    const float* prm = (const float*)d_in[23];
    const float* prv = (const float*)d_in[24];
    const float* proj_pw_w = (const float*)d_in[25];

    float *p_qh, *p_kh, *p_high, *p_qkv, *p_low, *p_sm, *p_pool, *p_sig;
    __half *p_xh, *p_mixh, *p_dwh, *p_w5t, *p_w3t, *p_wq, *p_w2, *p_wp;
    cudaGetSymbolAddress((void**)&p_qh,   g_qh);
    cudaGetSymbolAddress((void**)&p_kh,   g_kh);
    cudaGetSymbolAddress((void**)&p_high, g_high);
    cudaGetSymbolAddress((void**)&p_qkv,  g_qkv);
    cudaGetSymbolAddress((void**)&p_low,  g_low);
    cudaGetSymbolAddress((void**)&p_sm,   g_sm);
    cudaGetSymbolAddress((void**)&p_pool, g_pool);
    cudaGetSymbolAddress((void**)&p_sig,  g_sig);
    cudaGetSymbolAddress((void**)&p_xh,   g_xh);
    cudaGetSymbolAddress((void**)&p_mixh, g_mixh);
    cudaGetSymbolAddress((void**)&p_dwh,  g_dwh);
    cudaGetSymbolAddress((void**)&p_w5t,  g_w5t);
    cudaGetSymbolAddress((void**)&p_w3t,  g_w3t);
    cudaGetSymbolAddress((void**)&p_wq,   g_wq);
    cudaGetSymbolAddress((void**)&p_w2,   g_w2);
    cudaGetSymbolAddress((void**)&p_wp,   g_wp);

    const int smem3 = 2 * (8 * 10 * 36 + 9  * 512) * 4;   // 59904 B
    const int smem5 = 2 * (8 * 12 * 38 + 25 * 512) * 4;   // 131584 B
    const int smemG = 2 * GEM_STG2 * 4;                   // 44032 B
    cudaFuncSetAttribute(conv_h<5, false>, cudaFuncAttributeMaxDynamicSharedMemorySize, smem5);
    cudaFuncSetAttribute(conv_h<3, true>,  cudaFuncAttributeMaxDynamicSharedMemorySize, smem3);
    cudaFuncSetAttribute(gemm1x1_h,        cudaFuncAttributeMaxDynamicSharedMemorySize, smemG);

    // ---- pre-pass ----
    interleave_h<<<BDIM * 128 * HW / 256, 256>>>(x, p_xh);
    roundw_h<<<(3 * CDIM * CDIM + 255) / 256, 256>>>(qkv_w, p_wq, 3 * CDIM * CDIM);
    roundw_h<<<(CDIM * CDIM + 255) / 256, 256>>>(local2_w, p_w2, CDIM * CDIM);
    roundw_h<<<(CDIM * CDIM + 255) / 256, 256>>>(proj_pw_w, p_wp, CDIM * CDIM);
    wtransform_h<9><<<(CDIM * CDIM * 9 + 255) / 256, 256>>>(local1_w, p_w3t);
    wtransform_h<25><<<(CDIM * CDIM * 25 + 255) / 256, 256>>>(smooth_w, p_w5t);

    // ---- main chain ----
    gemm1x1_h<<<dim3(64, 12, 4), 256, smemG>>>(p_xh, p_wq, nullptr, nullptr, nullptr, nullptr, p_qkv, 768);
    gemm1x1_h<<<dim3(64, 4, 4), 256, smemG>>>(p_xh, p_w2, l2g, l2b, l2m, l2v, p_kh, 256);
    conv_h<3, true><<<dim3(4, 16, 16), 256, smem3>>>(p_xh, p_w3t, l1g, l1b, l1m, l1v,
                                                     p_qh, p_kh, p_high);
    attn_mma<<<dim3(256, 16, 4), 128>>>(p_qkv, p_qh, p_kh, rel_table, p_low);
    pool_kernel<<<dim3(64, 4), 256>>>(p_low, p_high, p_pool);
    hybrid_kernel<<<dim3(64, 4), 256>>>(p_pool, hybrid_w, hybrid_b, p_sig);
    mix_h<<<BDIM * 128 * HW / 256, 256>>>(p_low, p_high, p_sig, p_mixh);
    conv_h<5, false><<<dim3(4, 16, 16), 256, smem5>>>(p_mixh, p_w5t, smg, smb, smm, smv,
                                                      p_sm, nullptr, nullptr);
    dw_kernel<<<dim3(4, 16, 1024), dim3(32, 8)>>>(p_sm, proj_dw_w, prg, prb, prm, prv, p_dwh);
    gemm1x1_h<<<dim3(64, 4, 4), 256, smemG>>>(p_dwh, p_wp, nullptr, nullptr, nullptr, nullptr,
                                              (float*)d_out, 256);
}

// round 14
// speedup vs baseline: 1.9737x; 1.0246x over previous
#include <cuda_runtime.h>
#include <cuda_fp16.h>
#include <math.h>
#include <stdint.h>

#define HDIM 128
#define WDIM 128
#define HW (HDIM*WDIM)
#define CDIM 256
#define BDIM 4
#define NHEAD 16
#define EPS 1e-5f

// ---------------- scratch ----------------------------------------------------
__device__ float  g_kh  [BDIM*CDIM*HW];
__device__ float  g_high[BDIM*CDIM*HW];
__device__ float  g_low [BDIM*CDIM*HW];
__device__ float  g_sm  [BDIM*CDIM*HW];
__device__ float  g_pool[BDIM*2*HW];
__device__ float  g_sig [BDIM*2*HW];
// half activations
__device__ __half g_xh  [BDIM*CDIM*HW];   // channel-pair interleaved
__device__ __half g_mixh[BDIM*CDIM*HW];   // channel-pair interleaved
__device__ __half g_dwh [BDIM*CDIM*HW];   // channel-pair interleaved
__device__ __half g_qkvh[BDIM*3*CDIM*HW]; // planar [768][HW] half
__device__ __half g_qhh [BDIM*CDIM*HW];   // planar [256][HW] half
// half weights
__device__ __half g_w5t [CDIM*CDIM*25];
__device__ __half g_w3t [CDIM*CDIM*9];
__device__ __half g_wq  [3*CDIM*CDIM];
__device__ __half g_w2  [CDIM*CDIM];
__device__ __half g_wp  [CDIM*CDIM];

// ---------------- helpers ----------------------------------------------------
__device__ __forceinline__ void cp16(void* dst, const void* src) {
    uint32_t d = (uint32_t)__cvta_generic_to_shared(dst);
    asm volatile("cp.async.cg.shared.global [%0], [%1], 16;" :: "r"(d), "l"(src));
}
__device__ __forceinline__ void cp4z(void* dst, const void* src, bool pred) {
    uint32_t d = (uint32_t)__cvta_generic_to_shared(dst);
    int sz = pred ? 4 : 0;
    asm volatile("cp.async.ca.shared.global [%0], [%1], 4, %2;" :: "r"(d), "l"(src), "r"(sz));
}
__device__ __forceinline__ void cp_commit() { asm volatile("cp.async.commit_group;"); }
__device__ __forceinline__ void cp_wait1()  { asm volatile("cp.async.wait_group 1;"); }

__device__ __forceinline__ void mma_f16(float* d, uint32_t a0, uint32_t a1,
                                        uint32_t a2, uint32_t a3,
                                        uint32_t b0, uint32_t b1) {
    asm volatile(
        "mma.sync.aligned.m16n8k16.row.col.f32.f16.f16.f32 "
        "{%0,%1,%2,%3}, {%4,%5,%6,%7}, {%8,%9}, {%0,%1,%2,%3};"
        : "+f"(d[0]), "+f"(d[1]), "+f"(d[2]), "+f"(d[3])
        : "r"(a0), "r"(a1), "r"(a2), "r"(a3), "r"(b0), "r"(b1));
}

__device__ __forceinline__ uint32_t h2u(__half2 h) {
    return *reinterpret_cast<uint32_t*>(&h);
}

// ---------------- pre-pass kernels -------------------------------------------
__global__ void interleave_h(const float* __restrict__ in, __half* __restrict__ out)
{
    int i = blockIdx.x * 256 + threadIdx.x;
    int p = i & (HW - 1);
    int rest = i >> 14;
    int cp = rest & 127;
    int b = rest >> 7;
    const float* base = in + ((size_t)(b * CDIM + 2 * cp)) * HW + p;
    reinterpret_cast<__half2*>(out)[i] = __floats2half2_rn(base[0], base[HW]);
}

__global__ void roundw_h(const float* __restrict__ in, __half* __restrict__ out, int n)
{
    int i = blockIdx.x * 256 + threadIdx.x;
    if (i < n) out[i] = __float2half_rn(in[i]);
}

template<int KKS>
__global__ void wtransform_h(const float* __restrict__ wgt, __half* __restrict__ dst)
{
    int tid = blockIdx.x * 256 + threadIdx.x;
    int total = 4 * 16 * KKS * 1024;
    if (tid >= total) return;
    int ic  = tid & 15;
    int oc  = (tid >> 4) & 63;
    int tap = (tid >> 10) % KKS;
    int ics = (tid / (1024 * KKS)) & 15;
    int ocT = tid / (1024 * KKS * 16);
    dst[tid] = __float2half_rn(wgt[((size_t)((ocT * 64 + oc) * 256 + ics * 16 + ic)) * KKS + tap]);
}

// ---------------- 1x1 conv as fp16 GEMM, cp.async double-buffered ------------
#define XSTR2 264
#define WSTR2 20
#define GEM_XF2 (16*XSTR2)
#define GEM_WF2 (64*WSTR2)
#define GEM_STG2 (GEM_XF2+GEM_WF2)

template<bool OUTH>
__global__ __launch_bounds__(256, 2)
void gemm1x1_h(const __half* __restrict__ in, const __half* __restrict__ w,
               const float* __restrict__ bng, const float* __restrict__ bnb,
               const float* __restrict__ bnm, const float* __restrict__ bnv,
               void* __restrict__ outv, int OC)
{
    extern __shared__ uint32_t smem2[];

    const int bb  = blockIdx.z;
    const int ocT = blockIdx.y;
    const int p0  = blockIdx.x * 256;
    const int t   = threadIdx.x;
    const int warp = t >> 5, lane = t & 31;
    const int g = lane >> 2, tg = lane & 3;
    const int wm = warp >> 2;
    const int wn = warp & 3;

    const __half2* in2 = reinterpret_cast<const __half2*>(in) + (size_t)bb * 128 * HW;

    auto load = [&](int s, int ic0) {
        uint32_t* sX = smem2 + s * GEM_STG2;
        uint32_t* sW = sX + GEM_XF2;
        int cp0 = ic0 >> 1;
#pragma unroll
        for (int j = 0; j < 4; j++) {
            int idx = j * 256 + t;
            int icp = idx >> 6, px4 = idx & 63;
            cp16(&sX[icp * XSTR2 + px4 * 4], in2 + (cp0 + icp) * HW + p0 + px4 * 4);
        }
        {
            int oc = t >> 2, icq = t & 3;
            cp16(&sW[oc * WSTR2 + icq * 4],
                 w + (size_t)(ocT * 64 + oc) * CDIM + ic0 + icq * 8);
        }
    };

    float acc[2][8][4];
#pragma unroll
    for (int i = 0; i < 2; i++)
#pragma unroll
        for (int j = 0; j < 8; j++)
#pragma unroll
            for (int c = 0; c < 4; c++) acc[i][j][c] = 0.f;

    load(0, 0);
    cp_commit();

    for (int ic0 = 0; ic0 < CDIM; ic0 += 32) {
        int cur = (ic0 >> 5) & 1;
        if (ic0 + 32 < CDIM) load(cur ^ 1, ic0 + 32);
        cp_commit();
        cp_wait1();
        __syncthreads();

        uint32_t* sX = smem2 + cur * GEM_STG2;
        uint32_t* sW = sX + GEM_XF2;
#pragma unroll
        for (int ks = 0; ks < 2; ks++) {
            int kb = ks * 8;
            uint32_t a[2][4];
#pragma unroll
            for (int i = 0; i < 2; i++) {
                int row = wm * 32 + i * 16 + g;
                a[i][0] = sW[row * WSTR2 + kb + tg];
                a[i][1] = sW[(row + 8) * WSTR2 + kb + tg];
                a[i][2] = sW[row * WSTR2 + kb + tg + 4];
                a[i][3] = sW[(row + 8) * WSTR2 + kb + tg + 4];
            }
#pragma unroll
            for (int j = 0; j < 8; j++) {
                int px = wn * 64 + j * 8 + g;
                uint32_t b0 = sX[(kb + tg) * XSTR2 + px];
                uint32_t b1 = sX[(kb + tg + 4) * XSTR2 + px];
                mma_f16(acc[0][j], a[0][0], a[0][1], a[0][2], a[0][3], b0, b1);
                mma_f16(acc[1][j], a[1][0], a[1][1], a[1][2], a[1][3], b0, b1);
            }
        }
        __syncthreads();
    }

#pragma unroll
    for (int i = 0; i < 2; i++) {
        int oc_lo = ocT * 64 + wm * 32 + i * 16 + g;
        int oc_hi = oc_lo + 8;
        float sc0 = 1.f, sh0 = 0.f, sc1 = 1.f, sh1 = 0.f;
        if (bng) {
            sc0 = bng[oc_lo] * rsqrtf(bnv[oc_lo] + EPS); sh0 = bnb[oc_lo] - bnm[oc_lo] * sc0;
            sc1 = bng[oc_hi] * rsqrtf(bnv[oc_hi] + EPS); sh1 = bnb[oc_hi] - bnm[oc_hi] * sc1;
        }
#pragma unroll
        for (int j = 0; j < 8; j++) {
            int px = p0 + wn * 64 + j * 8 + 2 * tg;
            float v00 = acc[i][j][0] * sc0 + sh0;
            float v01 = acc[i][j][1] * sc0 + sh0;
            float v10 = acc[i][j][2] * sc1 + sh1;
            float v11 = acc[i][j][3] * sc1 + sh1;
            if (OUTH) {
                __half* oh = (__half*)outv;
                *reinterpret_cast<__half2*>(&oh[((size_t)bb * OC + oc_lo) * HW + px]) =
                    __floats2half2_rn(v00, v01);
                *reinterpret_cast<__half2*>(&oh[((size_t)bb * OC + oc_hi) * HW + px]) =
                    __floats2half2_rn(v10, v11);
            } else {
                float* of = (float*)outv;
                float* o0 = &of[((size_t)bb * OC + oc_lo) * HW + px];
                float* o1 = &of[((size_t)bb * OC + oc_hi) * HW + px];
                o0[0] = v00; o0[1] = v01;
                o1[0] = v10; o1[1] = v11;
            }
        }
    }
}

// ---------------- KxK conv via fp16 MMA, double-buffered ---------------------
// ADD_HIGH: out = half (qh planar), out2 = float (high = qh+kh)
template<int KS, bool ADD_HIGH>
__global__ __launch_bounds__(256, (KS == 3 ? 2 : 1))
void conv_h(const __half* __restrict__ in, const __half* __restrict__ wt,
            const float* __restrict__ bng, const float* __restrict__ bnb,
            const float* __restrict__ bnm, const float* __restrict__ bnv,
            void* __restrict__ outv,
            const float* __restrict__ khbuf, float* __restrict__ out2)
{
    constexpr int PAD = KS / 2;
    constexpr int PH = 8 + KS - 1;
    constexpr int PW = 32 + KS - 1;
    constexpr int PWS2 = (KS == 5) ? 38 : 36;
    constexpr int KKS = KS * KS;
    constexpr int PATCH2 = 8 * PH * PWS2;
    constexpr int WGT2 = KKS * 512;
    constexpr int STG2 = PATCH2 + WGT2;

    extern __shared__ uint32_t smem2[];

    const int w0 = blockIdx.x * 32;
    const int h0 = blockIdx.y * 8;
    const int bb  = blockIdx.z >> 2;
    const int ocT = blockIdx.z & 3;
    const int t = threadIdx.x;
    const int warp = t >> 5, lane = t & 31;
    const int g = lane >> 2, tg = lane & 3;
    const int wm = warp >> 2;
    const int wn = warp & 3;

    const __half2* in2 = reinterpret_cast<const __half2*>(in) + (size_t)bb * 128 * HW;

    auto load = [&](int s, int chunk) {
        uint32_t* sP = smem2 + s * STG2;
        __half* sWh = reinterpret_cast<__half*>(sP + PATCH2);
        for (int e = t; e < 8 * PH * PW; e += 256) {
            int icp = e / (PH * PW), rem = e % (PH * PW);
            int row = rem / PW, cc = rem % PW;
            int h = h0 + row - PAD, w = w0 + cc - PAD;
            bool ok = ((unsigned)h < HDIM) && ((unsigned)w < WDIM);
            cp4z(&sP[icp * PH * PWS2 + row * PWS2 + cc],
                 in2 + (chunk * 8 + icp) * HW + (ok ? h : 0) * WDIM + (ok ? w : 0), ok);
        }
        const __half* wb = wt + (size_t)(ocT * 16 + chunk) * (KKS * 1024);
        for (int e = t * 8; e < KKS * 1024; e += 2048)
            cp16(&sWh[e], &wb[e]);
    };

    float acc[2][8][4];
#pragma unroll
    for (int i = 0; i < 2; i++)
#pragma unroll
        for (int j = 0; j < 8; j++)
#pragma unroll
            for (int c = 0; c < 4; c++) acc[i][j][c] = 0.f;

    load(0, 0);
    cp_commit();

    for (int chunk = 0; chunk < 16; chunk++) {
        int cur = chunk & 1;
        if (chunk + 1 < 16) load(cur ^ 1, chunk + 1);
        cp_commit();
        cp_wait1();
        __syncthreads();

        uint32_t* sP = smem2 + cur * STG2;
        uint32_t* sW = sP + PATCH2;
#pragma unroll
        for (int ky = 0; ky < KS; ky++)
#pragma unroll
            for (int kx = 0; kx < KS; kx++) {
                const int tap = ky * KS + kx;
                uint32_t a[2][4];
#pragma unroll
                for (int i = 0; i < 2; i++) {
                    int row = wm * 32 + i * 16 + g;
                    a[i][0] = sW[tap * 512 + row * 8 + tg];
                    a[i][1] = sW[tap * 512 + (row + 8) * 8 + tg];
                    a[i][2] = sW[tap * 512 + row * 8 + tg + 4];
                    a[i][3] = sW[tap * 512 + (row + 8) * 8 + tg + 4];
                }
#pragma unroll
                for (int j = 0; j < 8; j++) {
                    int hr = wn * 2 + (j >> 2) + ky;
                    int wc = (j & 3) * 8 + kx + g;
                    uint32_t b0 = sP[tg * PH * PWS2 + hr * PWS2 + wc];
                    uint32_t b1 = sP[(tg + 4) * PH * PWS2 + hr * PWS2 + wc];
                    mma_f16(acc[0][j], a[0][0], a[0][1], a[0][2], a[0][3], b0, b1);
                    mma_f16(acc[1][j], a[1][0], a[1][1], a[1][2], a[1][3], b0, b1);
                }
            }
        __syncthreads();
    }

#pragma unroll
    for (int i = 0; i < 2; i++) {
        int oc_lo = ocT * 64 + wm * 32 + i * 16 + g;
        int oc_hi = oc_lo + 8;
        float sc0 = bng[oc_lo] * rsqrtf(bnv[oc_lo] + EPS);
        float sh0 = bnb[oc_lo] - bnm[oc_lo] * sc0;
        float sc1 = bng[oc_hi] * rsqrtf(bnv[oc_hi] + EPS);
        float sh1 = bnb[oc_hi] - bnm[oc_hi] * sc1;
#pragma unroll
        for (int j = 0; j < 8; j++) {
            int h = h0 + wn * 2 + (j >> 2);
            int w = w0 + (j & 3) * 8 + 2 * tg;
            size_t i0 = ((size_t)(bb * CDIM + oc_lo) * HDIM + h) * WDIM + w;
            size_t i1 = ((size_t)(bb * CDIM + oc_hi) * HDIM + h) * WDIM + w;
            float v00 = acc[i][j][0] * sc0 + sh0;
            float v01 = acc[i][j][1] * sc0 + sh0;
            float v10 = acc[i][j][2] * sc1 + sh1;
            float v11 = acc[i][j][3] * sc1 + sh1;
            if (ADD_HIGH) {
                __half* oh = (__half*)outv;
                *reinterpret_cast<__half2*>(&oh[i0]) = __floats2half2_rn(v00, v01);
                *reinterpret_cast<__half2*>(&oh[i1]) = __floats2half2_rn(v10, v11);
                out2[i0] = v00 + khbuf[i0]; out2[i0 + 1] = v01 + khbuf[i0 + 1];
                out2[i1] = v10 + khbuf[i1]; out2[i1 + 1] = v11 + khbuf[i1 + 1];
            } else {
                float* of = (float*)outv;
                of[i0] = v00; of[i0 + 1] = v01;
                of[i1] = v10; of[i1 + 1] = v11;
            }
        }
    }
}

// ---------------- window attention via fp16 tensor cores ---------------------
// Block = (window, head), 4 warps; warp w handles query rows 16w..16w+15.
// qkv/qh arrive pre-rounded half (bit-identical to rounding here); kh float.
#define AQ_OFF  0
#define AK_OFF  576
#define AQH_OFF 1152
#define AKH_OFF 1728
#define AVT_OFF 2304
#define ART_OFF 2880
#define AO_OFF  3108
#define APOOL_SZ 4196

__global__ __launch_bounds__(128)
void attn_mma(const __half* __restrict__ qkvh, const __half* __restrict__ qhh,
              const float* __restrict__ kh, const float* __restrict__ rel_table,
              float* __restrict__ low)
{
    __shared__ __align__(16) uint32_t sPool[APOOL_SZ];

    const int wi = blockIdx.x;
    const int head = blockIdx.y;
    const int bb = blockIdx.z;
    const int hh = wi >> 4, ww = wi & 15;
    const int t = threadIdx.x;
    const int warp = t >> 5, lane = t & 31;
    const int g = lane >> 2, tg = lane & 3;

    float* sRT = reinterpret_cast<float*>(sPool + ART_OFF);
    float* sO  = reinterpret_cast<float*>(sPool + AO_OFF);

    // ---- staging ----
    for (int u = t; u < 1280; u += 128) {
        int a = u >> 8;
        int unit = u & 255;
        int ch = unit >> 4, px4 = unit & 15;
        int row = px4 >> 1, col = (px4 & 1) * 4;
        int tok = row * 8 + col;
        if (a == 4) {  // KH from float
            const float* gsrc = kh + ((size_t)(bb * CDIM + head * 16 + ch) * HDIM + hh * 8 + row) * WDIM + ww * 8 + col;
            float4 v = *reinterpret_cast<const float4*>(gsrc);
            __half* dst = reinterpret_cast<__half*>(sPool + AKH_OFF);
            dst[(tok + 0) * 18 + ch] = __float2half_rn(v.x);
            dst[(tok + 1) * 18 + ch] = __float2half_rn(v.y);
            dst[(tok + 2) * 18 + ch] = __float2half_rn(v.z);
            dst[(tok + 3) * 18 + ch] = __float2half_rn(v.w);
        } else {       // Q/K/V/QH from half
            const __half* gsrc = (a < 3)
                ? qkvh + ((size_t)(bb * 768 + a * 256 + head * 16 + ch) * HDIM + hh * 8 + row) * WDIM + ww * 8 + col
                : qhh  + ((size_t)(bb * CDIM + head * 16 + ch) * HDIM + hh * 8 + row) * WDIM + ww * 8 + col;
            uint2 v = *reinterpret_cast<const uint2*>(gsrc);
            if (a == 2) {  // V -> transposed [d][tok], raw half2 copies
                uint32_t* d2 = sPool + AVT_OFF;
                int base = ch * 36 + tok / 2;
                d2[base] = v.x; d2[base + 1] = v.y;
            } else {
                int off = (a == 0) ? AQ_OFF : (a == 1) ? AK_OFF : AQH_OFF;
                __half* dst = reinterpret_cast<__half*>(sPool + off);
                const __half* hv = reinterpret_cast<const __half*>(&v);
                dst[(tok + 0) * 18 + ch] = hv[0];
                dst[(tok + 1) * 18 + ch] = hv[1];
                dst[(tok + 2) * 18 + ch] = hv[2];
                dst[(tok + 3) * 18 + ch] = hv[3];
            }
        }
    }
    for (int i = t; i < 225; i += 128) sRT[i] = rel_table[i * NHEAD + head];
    __syncthreads();

    const int qb = warp * 16;
    const uint32_t* q2  = sPool + AQ_OFF;
    const uint32_t* k2  = sPool + AK_OFF;
    const uint32_t* qh2 = sPool + AQH_OFF;
    const uint32_t* kh2 = sPool + AKH_OFF;
    const uint32_t* vt2 = sPool + AVT_OFF;

    uint32_t aq[4], ah[4];
    aq[0] = q2[(qb + g) * 9 + tg];      aq[1] = q2[(qb + 8 + g) * 9 + tg];
    aq[2] = q2[(qb + g) * 9 + tg + 4];  aq[3] = q2[(qb + 8 + g) * 9 + tg + 4];
    ah[0] = qh2[(qb + g) * 9 + tg];     ah[1] = qh2[(qb + 8 + g) * 9 + tg];
    ah[2] = qh2[(qb + g) * 9 + tg + 4]; ah[3] = qh2[(qb + 8 + g) * 9 + tg + 4];

    float s[8][4];
#pragma unroll
    for (int n = 0; n < 8; n++) { s[n][0] = s[n][1] = s[n][2] = s[n][3] = 0.f; }
#pragma unroll
    for (int n = 0; n < 8; n++) {
        int kt = n * 8 + g;
        uint32_t b0 = k2[kt * 9 + tg],  b1 = k2[kt * 9 + tg + 4];
        mma_f16(s[n], aq[0], aq[1], aq[2], aq[3], b0, b1);
        b0 = kh2[kt * 9 + tg]; b1 = kh2[kt * 9 + tg + 4];
        mma_f16(s[n], ah[0], ah[1], ah[2], ah[3], b0, b1);
    }

    const int rq0 = qb + g, rq1 = qb + g + 8;
    const int r0h = rq0 >> 3, r0l = rq0 & 7;
    const int r1h = rq1 >> 3, r1l = rq1 & 7;
#pragma unroll
    for (int n = 0; n < 8; n++)
#pragma unroll
        for (int c = 0; c < 2; c++) {
            int m = n * 8 + 2 * tg + c;
            int mh = m >> 3, ml = m & 7;
            s[n][c]     = s[n][c]     * 0.25f + sRT[(r0h - mh + 7) * 15 + (r0l - ml + 7)];
            s[n][2 + c] = s[n][2 + c] * 0.25f + sRT[(r1h - mh + 7) * 15 + (r1l - ml + 7)];
        }

    float mx0 = -1e30f, mx1 = -1e30f;
#pragma unroll
    for (int n = 0; n < 8; n++) {
        mx0 = fmaxf(mx0, fmaxf(s[n][0], s[n][1]));
        mx1 = fmaxf(mx1, fmaxf(s[n][2], s[n][3]));
    }
    mx0 = fmaxf(mx0, __shfl_xor_sync(0xffffffffu, mx0, 1));
    mx0 = fmaxf(mx0, __shfl_xor_sync(0xffffffffu, mx0, 2));
    mx1 = fmaxf(mx1, __shfl_xor_sync(0xffffffffu, mx1, 1));
    mx1 = fmaxf(mx1, __shfl_xor_sync(0xffffffffu, mx1, 2));
    float sum0 = 0.f, sum1 = 0.f;
#pragma unroll
    for (int n = 0; n < 8; n++) {
        s[n][0] = __expf(s[n][0] - mx0); s[n][1] = __expf(s[n][1] - mx0);
        s[n][2] = __expf(s[n][2] - mx1); s[n][3] = __expf(s[n][3] - mx1);
        sum0 += s[n][0] + s[n][1];
        sum1 += s[n][2] + s[n][3];
    }
    sum0 += __shfl_xor_sync(0xffffffffu, sum0, 1);
    sum0 += __shfl_xor_sync(0xffffffffu, sum0, 2);
    sum1 += __shfl_xor_sync(0xffffffffu, sum1, 1);
    sum1 += __shfl_xor_sync(0xffffffffu, sum1, 2);
    float inv0 = 1.f / sum0, inv1 = 1.f / sum1;
#pragma unroll
    for (int n = 0; n < 8; n++) {
        s[n][0] *= inv0; s[n][1] *= inv0;
        s[n][2] *= inv1; s[n][3] *= inv1;
    }

    float o[2][4];
    o[0][0] = o[0][1] = o[0][2] = o[0][3] = 0.f;
    o[1][0] = o[1][1] = o[1][2] = o[1][3] = 0.f;
#pragma unroll
    for (int kc = 0; kc < 4; kc++) {
        uint32_t a0 = h2u(__floats2half2_rn(s[2 * kc][0],     s[2 * kc][1]));
        uint32_t a1 = h2u(__floats2half2_rn(s[2 * kc][2],     s[2 * kc][3]));
        uint32_t a2 = h2u(__floats2half2_rn(s[2 * kc + 1][0], s[2 * kc + 1][1]));
        uint32_t a3 = h2u(__floats2half2_rn(s[2 * kc + 1][2], s[2 * kc + 1][3]));
#pragma unroll
        for (int ot = 0; ot < 2; ot++) {
            uint32_t b0 = vt2[(8 * ot + g) * 36 + 8 * kc + tg];
            uint32_t b1 = vt2[(8 * ot + g) * 36 + 8 * kc + tg + 4];
            mma_f16(o[ot], a0, a1, a2, a3, b0, b1);
        }
    }

#pragma unroll
    for (int ot = 0; ot < 2; ot++) {
        int d0 = 8 * ot + 2 * tg;
        sO[d0 * 68 + qb + g]           = o[ot][0];
        sO[(d0 + 1) * 68 + qb + g]     = o[ot][1];
        sO[d0 * 68 + qb + 8 + g]       = o[ot][2];
        sO[(d0 + 1) * 68 + qb + 8 + g] = o[ot][3];
    }
    __syncthreads();
    for (int u = t; u < 256; u += 128) {
        int ch = u >> 4, px4 = u & 15;
        int row = px4 >> 1, col = (px4 & 1) * 4;
        float4 v = *reinterpret_cast<const float4*>(&sO[ch * 68 + row * 8 + col]);
        *reinterpret_cast<float4*>(
            &low[((size_t)(bb * CDIM + head * 16 + ch) * HDIM + hh * 8 + row) * WDIM + ww * 8 + col]) = v;
    }
}

// ---------------- channel mean/max pool --------------------------------------
__global__ void pool_kernel(const float* __restrict__ low, const float* __restrict__ high,
                            float* __restrict__ pool)
{
    int p = blockIdx.x * 256 + threadIdx.x;
    int bb = blockIdx.y;
    const float* lb = low  + (size_t)bb * CDIM * HW;
    const float* hb = high + (size_t)bb * CDIM * HW;
    float s = 0.f, mx = -1e30f;
    for (int c = 0; c < CDIM; c++) {
        float v = lb[c * HW + p] + hb[c * HW + p];
        s += v; mx = fmaxf(mx, v);
    }
    pool[(bb * 2 + 0) * HW + p] = s * (1.f / 256.f);
    pool[(bb * 2 + 1) * HW + p] = mx;
}

// ---------------- hybrid 7x7 conv (2->2) + sigmoid ---------------------------
__global__ void hybrid_kernel(const float* __restrict__ pool, const float* __restrict__ hw,
                              const float* __restrict__ hb, float* __restrict__ sig)
{
    __shared__ float sw[196];
    __shared__ float sb[2];
    int t = threadIdx.x;
    if (t < 196) sw[t] = hw[t];
    if (t < 2) sb[t] = hb[t];
    __syncthreads();
    int p = blockIdx.x * 256 + t;
    int bb = blockIdx.y;
    int h = p >> 7, w = p & 127;
#pragma unroll
    for (int oc = 0; oc < 2; oc++) {
        float acc = sb[oc];
#pragma unroll
        for (int ic = 0; ic < 2; ic++)
            for (int ky = 0; ky < 7; ky++) {
                int hy = h + ky - 3;
                if (hy < 0 || hy >= HDIM) continue;
                for (int kx = 0; kx < 7; kx++) {
                    int wx = w + kx - 3;
                    if (wx < 0 || wx >= WDIM) continue;
                    acc += pool[(bb * 2 + ic) * HW + hy * WDIM + wx] * sw[((oc * 2 + ic) * 7 + ky) * 7 + kx];
                }
            }
        sig[(bb * 2 + oc) * HW + p] = 1.f / (1.f + __expf(-acc));
    }
}

// ---------------- mix -> half2 interleaved (feeds conv5) ---------------------
__global__ void mix_h(const float* __restrict__ low, const float* __restrict__ high,
                      const float* __restrict__ sig, __half* __restrict__ out)
{
    int i = blockIdx.x * 256 + threadIdx.x;
    int p = i & (HW - 1);
    int rest = i >> 14;
    int cp = rest & 127;
    int b = rest >> 7;
    float s0 = sig[(b * 2 + 0) * HW + p];
    float s1 = sig[(b * 2 + 1) * HW + p];
    size_t base = ((size_t)(b * CDIM + 2 * cp)) * HW + p;
    float m0 = low[base] * s0 + high[base] * s1;
    float m1 = low[base + HW] * s0 + high[base + HW] * s1;
    reinterpret_cast<__half2*>(out)[i] = __floats2half2_rn(m0, m1);
}

// ---------------- depthwise 7x7 + BN -> half interleaved ---------------------
__global__ void dw_kernel(const float* __restrict__ in, const float* __restrict__ w,
                          const float* __restrict__ bng, const float* __restrict__ bnb,
                          const float* __restrict__ bnm, const float* __restrict__ bnv,
                          __half* __restrict__ out)
{
    __shared__ float sT[14 * 38];
    __shared__ float sWc[49];
    const int w0 = blockIdx.x * 32;
    const int h0 = blockIdx.y * 8;
    const int bc = blockIdx.z;
    const int b = bc >> 8, c = bc & 255;
    const int tx = threadIdx.x, ty = threadIdx.y;
    const int t = ty * 32 + tx;
    if (t < 49) sWc[t] = w[c * 49 + t];
    const float* inb = in + (size_t)bc * HW;
    for (int e = t; e < 14 * 38; e += 256) {
        int row = e / 38, cc = e % 38;
        int h = h0 + row - 3, ww = w0 + cc - 3;
        float v = 0.f;
        if (h >= 0 && h < HDIM && ww >= 0 && ww < WDIM) v = inb[h * WDIM + ww];
        sT[e] = v;
    }
    __syncthreads();
    float acc = 0.f;
#pragma unroll
    for (int ky = 0; ky < 7; ky++)
#pragma unroll
        for (int kx = 0; kx < 7; kx++)
            acc += sT[(ty + ky) * 38 + tx + kx] * sWc[ky * 7 + kx];
    float sc = bng[c] * rsqrtf(bnv[c] + EPS);
    float sh = bnb[c] - bnm[c] * sc;
    int pix = (h0 + ty) * WDIM + w0 + tx;
    out[((size_t)(b * 128 + (c >> 1)) * HW + pix) * 2 + (c & 1)] = __float2half_rn(acc * sc + sh);
}

// ---------------- launch ------------------------------------------------------
extern "C" void kernel_launch(void* const* d_in, const int* in_sizes, int n_in,
                              void* d_out, int out_size)
{
    const float* x        = (const float*)d_in[0];
    const float* qkv_w    = (const float*)d_in[1];
    const float* local1_w = (const float*)d_in[2];
    const float* l1g = (const float*)d_in[3];
    const float* l1b = (const float*)d_in[4];
    const float* l1m = (const float*)d_in[5];
    const float* l1v = (const float*)d_in[6];
    const float* local2_w = (const float*)d_in[7];
    const float* l2g = (const float*)d_in[8];
    const float* l2b = (const float*)d_in[9];
    const float* l2m = (const float*)d_in[10];
    const float* l2v = (const float*)d_in[11];
    const float* rel_table = (const float*)d_in[12];
    const float* hybrid_w  = (const float*)d_in[13];
    const float* hybrid_b  = (const float*)d_in[14];
    const float* smooth_w  = (const float*)d_in[15];
    const float* smg = (const float*)d_in[16];
    const float* smb = (const float*)d_in[17];
    const float* smm = (const float*)d_in[18];
    const float* smv = (const float*)d_in[19];
    const float* proj_dw_w = (const float*)d_in[20];
    const float* prg = (const float*)d_in[21];
    const float* prb = (const float*)d_in[22];
    const float* prm = (const float*)d_in[23];
    const float* prv = (const float*)d_in[24];
    const float* proj_pw_w = (const float*)d_in[25];

    float *p_kh, *p_high, *p_low, *p_sm, *p_pool, *p_sig;
    __half *p_xh, *p_mixh, *p_dwh, *p_qkvh, *p_qhh, *p_w5t, *p_w3t, *p_wq, *p_w2, *p_wp;
    cudaGetSymbolAddress((void**)&p_kh,   g_kh);
    cudaGetSymbolAddress((void**)&p_high, g_high);
    cudaGetSymbolAddress((void**)&p_low,  g_low);
    cudaGetSymbolAddress((void**)&p_sm,   g_sm);
    cudaGetSymbolAddress((void**)&p_pool, g_pool);
    cudaGetSymbolAddress((void**)&p_sig,  g_sig);
    cudaGetSymbolAddress((void**)&p_xh,   g_xh);
    cudaGetSymbolAddress((void**)&p_mixh, g_mixh);
    cudaGetSymbolAddress((void**)&p_dwh,  g_dwh);
    cudaGetSymbolAddress((void**)&p_qkvh, g_qkvh);
    cudaGetSymbolAddress((void**)&p_qhh,  g_qhh);
    cudaGetSymbolAddress((void**)&p_w5t,  g_w5t);
    cudaGetSymbolAddress((void**)&p_w3t,  g_w3t);
    cudaGetSymbolAddress((void**)&p_wq,   g_wq);
    cudaGetSymbolAddress((void**)&p_w2,   g_w2);
    cudaGetSymbolAddress((void**)&p_wp,   g_wp);

    const int smem3 = 2 * (8 * 10 * 36 + 9  * 512) * 4;   // 59904 B
    const int smem5 = 2 * (8 * 12 * 38 + 25 * 512) * 4;   // 131584 B
    const int smemG = 2 * GEM_STG2 * 4;                   // 44032 B
    cudaFuncSetAttribute(conv_h<5, false>, cudaFuncAttributeMaxDynamicSharedMemorySize, smem5);
    cudaFuncSetAttribute(conv_h<3, true>,  cudaFuncAttributeMaxDynamicSharedMemorySize, smem3);
    cudaFuncSetAttribute(gemm1x1_h<true>,  cudaFuncAttributeMaxDynamicSharedMemorySize, smemG);
    cudaFuncSetAttribute(gemm1x1_h<false>, cudaFuncAttributeMaxDynamicSharedMemorySize, smemG);

    // ---- pre-pass ----
    interleave_h<<<BDIM * 128 * HW / 256, 256>>>(x, p_xh);
    roundw_h<<<(3 * CDIM * CDIM + 255) / 256, 256>>>(qkv_w, p_wq, 3 * CDIM * CDIM);
    roundw_h<<<(CDIM * CDIM + 255) / 256, 256>>>(local2_w, p_w2, CDIM * CDIM);
    roundw_h<<<(CDIM * CDIM + 255) / 256, 256>>>(proj_pw_w, p_wp, CDIM * CDIM);
    wtransform_h<9><<<(CDIM * CDIM * 9 + 255) / 256, 256>>>(local1_w, p_w3t);
    wtransform_h<25><<<(CDIM * CDIM * 25 + 255) / 256, 256>>>(smooth_w, p_w5t);

    // ---- main chain ----
    gemm1x1_h<true><<<dim3(64, 12, 4), 256, smemG>>>(p_xh, p_wq, nullptr, nullptr, nullptr, nullptr,
                                                     p_qkvh, 768);
    gemm1x1_h<false><<<dim3(64, 4, 4), 256, smemG>>>(p_xh, p_w2, l2g, l2b, l2m, l2v, p_kh, 256);
    conv_h<3, true><<<dim3(4, 16, 16), 256, smem3>>>(p_xh, p_w3t, l1g, l1b, l1m, l1v,
                                                     p_qhh, p_kh, p_high);
    attn_mma<<<dim3(256, 16, 4), 128>>>(p_qkvh, p_qhh, p_kh, rel_table, p_low);
    pool_kernel<<<dim3(64, 4), 256>>>(p_low, p_high, p_pool);
    hybrid_kernel<<<dim3(64, 4), 256>>>(p_pool, hybrid_w, hybrid_b, p_sig);
    mix_h<<<BDIM * 128 * HW / 256, 256>>>(p_low, p_high, p_sig, p_mixh);
    conv_h<5, false><<<dim3(4, 16, 16), 256, smem5>>>(p_mixh, p_w5t, smg, smb, smm, smv,
                                                      p_sm, nullptr, nullptr);
    dw_kernel<<<dim3(4, 16, 1024), dim3(32, 8)>>>(p_sm, proj_dw_w, prg, prb, prm, prv, p_dwh);
    gemm1x1_h<false><<<dim3(64, 4, 4), 256, smemG>>>(p_dwh, p_wp, nullptr, nullptr, nullptr, nullptr,
                                                     (float*)d_out, 256);
}

// round 15
// speedup vs baseline: 2.0366x; 1.0319x over previous
#include <cuda_runtime.h>
#include <cuda_fp16.h>
#include <math.h>
#include <stdint.h>

#define HDIM 128
#define WDIM 128
#define HW (HDIM*WDIM)
#define CDIM 256
#define BDIM 4
#define NHEAD 16
#define EPS 1e-5f

// ---------------- scratch ----------------------------------------------------
__device__ float  g_kh  [BDIM*CDIM*HW];
__device__ float  g_pool[BDIM*2*HW];
__device__ float  g_sig [BDIM*2*HW];
// half activations
__device__ __half g_xh  [BDIM*CDIM*HW];   // channel-pair interleaved
__device__ __half g_mixh[BDIM*CDIM*HW];   // channel-pair interleaved
__device__ __half g_dwh [BDIM*CDIM*HW];   // channel-pair interleaved
__device__ __half g_qkvh[BDIM*3*CDIM*HW]; // planar half
__device__ __half g_qhh [BDIM*CDIM*HW];   // planar half
__device__ __half g_lowh[BDIM*CDIM*HW];   // planar half
__device__ __half g_highh[BDIM*CDIM*HW];  // planar half
__device__ __half g_smh [BDIM*CDIM*HW];   // planar half
// half weights
__device__ __half g_w5t [CDIM*CDIM*25];
__device__ __half g_w3t [CDIM*CDIM*9];
__device__ __half g_wq  [3*CDIM*CDIM];
__device__ __half g_w2  [CDIM*CDIM];
__device__ __half g_wp  [CDIM*CDIM];

// ---------------- helpers ----------------------------------------------------
__device__ __forceinline__ void cp16(void* dst, const void* src) {
    uint32_t d = (uint32_t)__cvta_generic_to_shared(dst);
    asm volatile("cp.async.cg.shared.global [%0], [%1], 16;" :: "r"(d), "l"(src));
}
__device__ __forceinline__ void cp4z(void* dst, const void* src, bool pred) {
    uint32_t d = (uint32_t)__cvta_generic_to_shared(dst);
    int sz = pred ? 4 : 0;
    asm volatile("cp.async.ca.shared.global [%0], [%1], 4, %2;" :: "r"(d), "l"(src), "r"(sz));
}
__device__ __forceinline__ void cp_commit() { asm volatile("cp.async.commit_group;"); }
__device__ __forceinline__ void cp_wait1()  { asm volatile("cp.async.wait_group 1;"); }

__device__ __forceinline__ void mma_f16(float* d, uint32_t a0, uint32_t a1,
                                        uint32_t a2, uint32_t a3,
                                        uint32_t b0, uint32_t b1) {
    asm volatile(
        "mma.sync.aligned.m16n8k16.row.col.f32.f16.f16.f32 "
        "{%0,%1,%2,%3}, {%4,%5,%6,%7}, {%8,%9}, {%0,%1,%2,%3};"
        : "+f"(d[0]), "+f"(d[1]), "+f"(d[2]), "+f"(d[3])
        : "r"(a0), "r"(a1), "r"(a2), "r"(a3), "r"(b0), "r"(b1));
}

__device__ __forceinline__ uint32_t h2u(__half2 h) {
    return *reinterpret_cast<uint32_t*>(&h);
}

// ---------------- pre-pass kernels -------------------------------------------
__global__ void interleave_h(const float* __restrict__ in, __half* __restrict__ out)
{
    int i = blockIdx.x * 256 + threadIdx.x;
    int p = i & (HW - 1);
    int rest = i >> 14;
    int cp = rest & 127;
    int b = rest >> 7;
    const float* base = in + ((size_t)(b * CDIM + 2 * cp)) * HW + p;
    reinterpret_cast<__half2*>(out)[i] = __floats2half2_rn(base[0], base[HW]);
}

__global__ void roundw_h(const float* __restrict__ in, __half* __restrict__ out, int n)
{
    int i = blockIdx.x * 256 + threadIdx.x;
    if (i < n) out[i] = __float2half_rn(in[i]);
}

template<int KKS>
__global__ void wtransform_h(const float* __restrict__ wgt, __half* __restrict__ dst)
{
    int tid = blockIdx.x * 256 + threadIdx.x;
    int total = 4 * 16 * KKS * 1024;
    if (tid >= total) return;
    int ic  = tid & 15;
    int oc  = (tid >> 4) & 63;
    int tap = (tid >> 10) % KKS;
    int ics = (tid / (1024 * KKS)) & 15;
    int ocT = tid / (1024 * KKS * 16);
    dst[tid] = __float2half_rn(wgt[((size_t)((ocT * 64 + oc) * 256 + ics * 16 + ic)) * KKS + tap]);
}

// ---------------- 1x1 conv as fp16 GEMM, cp.async double-buffered ------------
#define XSTR2 264
#define WSTR2 20
#define GEM_XF2 (16*XSTR2)
#define GEM_WF2 (64*WSTR2)
#define GEM_STG2 (GEM_XF2+GEM_WF2)

template<bool OUTH>
__global__ __launch_bounds__(256, 2)
void gemm1x1_h(const __half* __restrict__ in, const __half* __restrict__ w,
               const float* __restrict__ bng, const float* __restrict__ bnb,
               const float* __restrict__ bnm, const float* __restrict__ bnv,
               void* __restrict__ outv, int OC)
{
    extern __shared__ uint32_t smem2[];

    const int bb  = blockIdx.z;
    const int ocT = blockIdx.y;
    const int p0  = blockIdx.x * 256;
    const int t   = threadIdx.x;
    const int warp = t >> 5, lane = t & 31;
    const int g = lane >> 2, tg = lane & 3;
    const int wm = warp >> 2;
    const int wn = warp & 3;

    const __half2* in2 = reinterpret_cast<const __half2*>(in) + (size_t)bb * 128 * HW;

    auto load = [&](int s, int ic0) {
        uint32_t* sX = smem2 + s * GEM_STG2;
        uint32_t* sW = sX + GEM_XF2;
        int cp0 = ic0 >> 1;
#pragma unroll
        for (int j = 0; j < 4; j++) {
            int idx = j * 256 + t;
            int icp = idx >> 6, px4 = idx & 63;
            cp16(&sX[icp * XSTR2 + px4 * 4], in2 + (cp0 + icp) * HW + p0 + px4 * 4);
        }
        {
            int oc = t >> 2, icq = t & 3;
            cp16(&sW[oc * WSTR2 + icq * 4],
                 w + (size_t)(ocT * 64 + oc) * CDIM + ic0 + icq * 8);
        }
    };

    float acc[2][8][4];
#pragma unroll
    for (int i = 0; i < 2; i++)
#pragma unroll
        for (int j = 0; j < 8; j++)
#pragma unroll
            for (int c = 0; c < 4; c++) acc[i][j][c] = 0.f;

    load(0, 0);
    cp_commit();

    for (int ic0 = 0; ic0 < CDIM; ic0 += 32) {
        int cur = (ic0 >> 5) & 1;
        if (ic0 + 32 < CDIM) load(cur ^ 1, ic0 + 32);
        cp_commit();
        cp_wait1();
        __syncthreads();

        uint32_t* sX = smem2 + cur * GEM_STG2;
        uint32_t* sW = sX + GEM_XF2;
#pragma unroll
        for (int ks = 0; ks < 2; ks++) {
            int kb = ks * 8;
            uint32_t a[2][4];
#pragma unroll
            for (int i = 0; i < 2; i++) {
                int row = wm * 32 + i * 16 + g;
                a[i][0] = sW[row * WSTR2 + kb + tg];
                a[i][1] = sW[(row + 8) * WSTR2 + kb + tg];
                a[i][2] = sW[row * WSTR2 + kb + tg + 4];
                a[i][3] = sW[(row + 8) * WSTR2 + kb + tg + 4];
            }
#pragma unroll
            for (int j = 0; j < 8; j++) {
                int px = wn * 64 + j * 8 + g;
                uint32_t b0 = sX[(kb + tg) * XSTR2 + px];
                uint32_t b1 = sX[(kb + tg + 4) * XSTR2 + px];
                mma_f16(acc[0][j], a[0][0], a[0][1], a[0][2], a[0][3], b0, b1);
                mma_f16(acc[1][j], a[1][0], a[1][1], a[1][2], a[1][3], b0, b1);
            }
        }
        __syncthreads();
    }

#pragma unroll
    for (int i = 0; i < 2; i++) {
        int oc_lo = ocT * 64 + wm * 32 + i * 16 + g;
        int oc_hi = oc_lo + 8;
        float sc0 = 1.f, sh0 = 0.f, sc1 = 1.f, sh1 = 0.f;
        if (bng) {
            sc0 = bng[oc_lo] * rsqrtf(bnv[oc_lo] + EPS); sh0 = bnb[oc_lo] - bnm[oc_lo] * sc0;
            sc1 = bng[oc_hi] * rsqrtf(bnv[oc_hi] + EPS); sh1 = bnb[oc_hi] - bnm[oc_hi] * sc1;
        }
#pragma unroll
        for (int j = 0; j < 8; j++) {
            int px = p0 + wn * 64 + j * 8 + 2 * tg;
            float v00 = acc[i][j][0] * sc0 + sh0;
            float v01 = acc[i][j][1] * sc0 + sh0;
            float v10 = acc[i][j][2] * sc1 + sh1;
            float v11 = acc[i][j][3] * sc1 + sh1;
            if (OUTH) {
                __half* oh = (__half*)outv;
                *reinterpret_cast<__half2*>(&oh[((size_t)bb * OC + oc_lo) * HW + px]) =
                    __floats2half2_rn(v00, v01);
                *reinterpret_cast<__half2*>(&oh[((size_t)bb * OC + oc_hi) * HW + px]) =
                    __floats2half2_rn(v10, v11);
            } else {
                float* of = (float*)outv;
                float* o0 = &of[((size_t)bb * OC + oc_lo) * HW + px];
                float* o1 = &of[((size_t)bb * OC + oc_hi) * HW + px];
                o0[0] = v00; o0[1] = v01;
                o1[0] = v10; o1[1] = v11;
            }
        }
    }
}

// ---------------- KxK conv via fp16 MMA, double-buffered ---------------------
// ADD_HIGH: outv = half qh planar, out2v = half high planar (khbuf float)
// OUTH (and !ADD_HIGH): outv = half planar
template<int KS, bool ADD_HIGH, bool OUTH>
__global__ __launch_bounds__(256, (KS == 3 ? 2 : 1))
void conv_h(const __half* __restrict__ in, const __half* __restrict__ wt,
            const float* __restrict__ bng, const float* __restrict__ bnb,
            const float* __restrict__ bnm, const float* __restrict__ bnv,
            void* __restrict__ outv,
            const float* __restrict__ khbuf, void* __restrict__ out2v)
{
    constexpr int PAD = KS / 2;
    constexpr int PH = 8 + KS - 1;
    constexpr int PW = 32 + KS - 1;
    constexpr int PWS2 = (KS == 5) ? 38 : 36;
    constexpr int KKS = KS * KS;
    constexpr int PATCH2 = 8 * PH * PWS2;
    constexpr int WGT2 = KKS * 512;
    constexpr int STG2 = PATCH2 + WGT2;

    extern __shared__ uint32_t smem2[];

    const int w0 = blockIdx.x * 32;
    const int h0 = blockIdx.y * 8;
    const int bb  = blockIdx.z >> 2;
    const int ocT = blockIdx.z & 3;
    const int t = threadIdx.x;
    const int warp = t >> 5, lane = t & 31;
    const int g = lane >> 2, tg = lane & 3;
    const int wm = warp >> 2;
    const int wn = warp & 3;

    const __half2* in2 = reinterpret_cast<const __half2*>(in) + (size_t)bb * 128 * HW;

    auto load = [&](int s, int chunk) {
        uint32_t* sP = smem2 + s * STG2;
        __half* sWh = reinterpret_cast<__half*>(sP + PATCH2);
        for (int e = t; e < 8 * PH * PW; e += 256) {
            int icp = e / (PH * PW), rem = e % (PH * PW);
            int row = rem / PW, cc = rem % PW;
            int h = h0 + row - PAD, w = w0 + cc - PAD;
            bool ok = ((unsigned)h < HDIM) && ((unsigned)w < WDIM);
            cp4z(&sP[icp * PH * PWS2 + row * PWS2 + cc],
                 in2 + (chunk * 8 + icp) * HW + (ok ? h : 0) * WDIM + (ok ? w : 0), ok);
        }
        const __half* wb = wt + (size_t)(ocT * 16 + chunk) * (KKS * 1024);
        for (int e = t * 8; e < KKS * 1024; e += 2048)
            cp16(&sWh[e], &wb[e]);
    };

    float acc[2][8][4];
#pragma unroll
    for (int i = 0; i < 2; i++)
#pragma unroll
        for (int j = 0; j < 8; j++)
#pragma unroll
            for (int c = 0; c < 4; c++) acc[i][j][c] = 0.f;

    load(0, 0);
    cp_commit();

    for (int chunk = 0; chunk < 16; chunk++) {
        int cur = chunk & 1;
        if (chunk + 1 < 16) load(cur ^ 1, chunk + 1);
        cp_commit();
        cp_wait1();
        __syncthreads();

        uint32_t* sP = smem2 + cur * STG2;
        uint32_t* sW = sP + PATCH2;
#pragma unroll
        for (int ky = 0; ky < KS; ky++)
#pragma unroll
            for (int kx = 0; kx < KS; kx++) {
                const int tap = ky * KS + kx;
                uint32_t a[2][4];
#pragma unroll
                for (int i = 0; i < 2; i++) {
                    int row = wm * 32 + i * 16 + g;
                    a[i][0] = sW[tap * 512 + row * 8 + tg];
                    a[i][1] = sW[tap * 512 + (row + 8) * 8 + tg];
                    a[i][2] = sW[tap * 512 + row * 8 + tg + 4];
                    a[i][3] = sW[tap * 512 + (row + 8) * 8 + tg + 4];
                }
#pragma unroll
                for (int j = 0; j < 8; j++) {
                    int hr = wn * 2 + (j >> 2) + ky;
                    int wc = (j & 3) * 8 + kx + g;
                    uint32_t b0 = sP[tg * PH * PWS2 + hr * PWS2 + wc];
                    uint32_t b1 = sP[(tg + 4) * PH * PWS2 + hr * PWS2 + wc];
                    mma_f16(acc[0][j], a[0][0], a[0][1], a[0][2], a[0][3], b0, b1);
                    mma_f16(acc[1][j], a[1][0], a[1][1], a[1][2], a[1][3], b0, b1);
                }
            }
        __syncthreads();
    }

#pragma unroll
    for (int i = 0; i < 2; i++) {
        int oc_lo = ocT * 64 + wm * 32 + i * 16 + g;
        int oc_hi = oc_lo + 8;
        float sc0 = bng[oc_lo] * rsqrtf(bnv[oc_lo] + EPS);
        float sh0 = bnb[oc_lo] - bnm[oc_lo] * sc0;
        float sc1 = bng[oc_hi] * rsqrtf(bnv[oc_hi] + EPS);
        float sh1 = bnb[oc_hi] - bnm[oc_hi] * sc1;
#pragma unroll
        for (int j = 0; j < 8; j++) {
            int h = h0 + wn * 2 + (j >> 2);
            int w = w0 + (j & 3) * 8 + 2 * tg;
            size_t i0 = ((size_t)(bb * CDIM + oc_lo) * HDIM + h) * WDIM + w;
            size_t i1 = ((size_t)(bb * CDIM + oc_hi) * HDIM + h) * WDIM + w;
            float v00 = acc[i][j][0] * sc0 + sh0;
            float v01 = acc[i][j][1] * sc0 + sh0;
            float v10 = acc[i][j][2] * sc1 + sh1;
            float v11 = acc[i][j][3] * sc1 + sh1;
            if (ADD_HIGH) {
                __half* oh = (__half*)outv;
                __half* o2 = (__half*)out2v;
                *reinterpret_cast<__half2*>(&oh[i0]) = __floats2half2_rn(v00, v01);
                *reinterpret_cast<__half2*>(&oh[i1]) = __floats2half2_rn(v10, v11);
                *reinterpret_cast<__half2*>(&o2[i0]) =
                    __floats2half2_rn(v00 + khbuf[i0], v01 + khbuf[i0 + 1]);
                *reinterpret_cast<__half2*>(&o2[i1]) =
                    __floats2half2_rn(v10 + khbuf[i1], v11 + khbuf[i1 + 1]);
            } else if (OUTH) {
                __half* oh = (__half*)outv;
                *reinterpret_cast<__half2*>(&oh[i0]) = __floats2half2_rn(v00, v01);
                *reinterpret_cast<__half2*>(&oh[i1]) = __floats2half2_rn(v10, v11);
            } else {
                float* of = (float*)outv;
                of[i0] = v00; of[i0 + 1] = v01;
                of[i1] = v10; of[i1 + 1] = v11;
            }
        }
    }
}

// ---------------- window attention via fp16 tensor cores ---------------------
#define AQ_OFF  0
#define AK_OFF  576
#define AQH_OFF 1152
#define AKH_OFF 1728
#define AVT_OFF 2304
#define ART_OFF 2880
#define AO_OFF  3108
#define APOOL_SZ 4196

__global__ __launch_bounds__(128)
void attn_mma(const __half* __restrict__ qkvh, const __half* __restrict__ qhh,
              const float* __restrict__ kh, const float* __restrict__ rel_table,
              __half* __restrict__ low)
{
    __shared__ __align__(16) uint32_t sPool[APOOL_SZ];

    const int wi = blockIdx.x;
    const int head = blockIdx.y;
    const int bb = blockIdx.z;
    const int hh = wi >> 4, ww = wi & 15;
    const int t = threadIdx.x;
    const int warp = t >> 5, lane = t & 31;
    const int g = lane >> 2, tg = lane & 3;

    float* sRT = reinterpret_cast<float*>(sPool + ART_OFF);
    float* sO  = reinterpret_cast<float*>(sPool + AO_OFF);

    for (int u = t; u < 1280; u += 128) {
        int a = u >> 8;
        int unit = u & 255;
        int ch = unit >> 4, px4 = unit & 15;
        int row = px4 >> 1, col = (px4 & 1) * 4;
        int tok = row * 8 + col;
        if (a == 4) {
            const float* gsrc = kh + ((size_t)(bb * CDIM + head * 16 + ch) * HDIM + hh * 8 + row) * WDIM + ww * 8 + col;
            float4 v = *reinterpret_cast<const float4*>(gsrc);
            __half* dst = reinterpret_cast<__half*>(sPool + AKH_OFF);
            dst[(tok + 0) * 18 + ch] = __float2half_rn(v.x);
            dst[(tok + 1) * 18 + ch] = __float2half_rn(v.y);
            dst[(tok + 2) * 18 + ch] = __float2half_rn(v.z);
            dst[(tok + 3) * 18 + ch] = __float2half_rn(v.w);
        } else {
            const __half* gsrc = (a < 3)
                ? qkvh + ((size_t)(bb * 768 + a * 256 + head * 16 + ch) * HDIM + hh * 8 + row) * WDIM + ww * 8 + col
                : qhh  + ((size_t)(bb * CDIM + head * 16 + ch) * HDIM + hh * 8 + row) * WDIM + ww * 8 + col;
            uint2 v = *reinterpret_cast<const uint2*>(gsrc);
            if (a == 2) {
                uint32_t* d2 = sPool + AVT_OFF;
                int base = ch * 36 + tok / 2;
                d2[base] = v.x; d2[base + 1] = v.y;
            } else {
                int off = (a == 0) ? AQ_OFF : (a == 1) ? AK_OFF : AQH_OFF;
                __half* dst = reinterpret_cast<__half*>(sPool + off);
                const __half* hv = reinterpret_cast<const __half*>(&v);
                dst[(tok + 0) * 18 + ch] = hv[0];
                dst[(tok + 1) * 18 + ch] = hv[1];
                dst[(tok + 2) * 18 + ch] = hv[2];
                dst[(tok + 3) * 18 + ch] = hv[3];
            }
        }
    }
    for (int i = t; i < 225; i += 128) sRT[i] = rel_table[i * NHEAD + head];
    __syncthreads();

    const int qb = warp * 16;
    const uint32_t* q2  = sPool + AQ_OFF;
    const uint32_t* k2  = sPool + AK_OFF;
    const uint32_t* qh2 = sPool + AQH_OFF;
    const uint32_t* kh2 = sPool + AKH_OFF;
    const uint32_t* vt2 = sPool + AVT_OFF;

    uint32_t aq[4], ah[4];
    aq[0] = q2[(qb + g) * 9 + tg];      aq[1] = q2[(qb + 8 + g) * 9 + tg];
    aq[2] = q2[(qb + g) * 9 + tg + 4];  aq[3] = q2[(qb + 8 + g) * 9 + tg + 4];
    ah[0] = qh2[(qb + g) * 9 + tg];     ah[1] = qh2[(qb + 8 + g) * 9 + tg];
    ah[2] = qh2[(qb + g) * 9 + tg + 4]; ah[3] = qh2[(qb + 8 + g) * 9 + tg + 4];

    float s[8][4];
#pragma unroll
    for (int n = 0; n < 8; n++) { s[n][0] = s[n][1] = s[n][2] = s[n][3] = 0.f; }
#pragma unroll
    for (int n = 0; n < 8; n++) {
        int kt = n * 8 + g;
        uint32_t b0 = k2[kt * 9 + tg],  b1 = k2[kt * 9 + tg + 4];
        mma_f16(s[n], aq[0], aq[1], aq[2], aq[3], b0, b1);
        b0 = kh2[kt * 9 + tg]; b1 = kh2[kt * 9 + tg + 4];
        mma_f16(s[n], ah[0], ah[1], ah[2], ah[3], b0, b1);
    }

    const int rq0 = qb + g, rq1 = qb + g + 8;
    const int r0h = rq0 >> 3, r0l = rq0 & 7;
    const int r1h = rq1 >> 3, r1l = rq1 & 7;
#pragma unroll
    for (int n = 0; n < 8; n++)
#pragma unroll
        for (int c = 0; c < 2; c++) {
            int m = n * 8 + 2 * tg + c;
            int mh = m >> 3, ml = m & 7;
            s[n][c]     = s[n][c]     * 0.25f + sRT[(r0h - mh + 7) * 15 + (r0l - ml + 7)];
            s[n][2 + c] = s[n][2 + c] * 0.25f + sRT[(r1h - mh + 7) * 15 + (r1l - ml + 7)];
        }

    float mx0 = -1e30f, mx1 = -1e30f;
#pragma unroll
    for (int n = 0; n < 8; n++) {
        mx0 = fmaxf(mx0, fmaxf(s[n][0], s[n][1]));
        mx1 = fmaxf(mx1, fmaxf(s[n][2], s[n][3]));
    }
    mx0 = fmaxf(mx0, __shfl_xor_sync(0xffffffffu, mx0, 1));
    mx0 = fmaxf(mx0, __shfl_xor_sync(0xffffffffu, mx0, 2));
    mx1 = fmaxf(mx1, __shfl_xor_sync(0xffffffffu, mx1, 1));
    mx1 = fmaxf(mx1, __shfl_xor_sync(0xffffffffu, mx1, 2));
    float sum0 = 0.f, sum1 = 0.f;
#pragma unroll
    for (int n = 0; n < 8; n++) {
        s[n][0] = __expf(s[n][0] - mx0); s[n][1] = __expf(s[n][1] - mx0);
        s[n][2] = __expf(s[n][2] - mx1); s[n][3] = __expf(s[n][3] - mx1);
        sum0 += s[n][0] + s[n][1];
        sum1 += s[n][2] + s[n][3];
    }
    sum0 += __shfl_xor_sync(0xffffffffu, sum0, 1);
    sum0 += __shfl_xor_sync(0xffffffffu, sum0, 2);
    sum1 += __shfl_xor_sync(0xffffffffu, sum1, 1);
    sum1 += __shfl_xor_sync(0xffffffffu, sum1, 2);
    float inv0 = 1.f / sum0, inv1 = 1.f / sum1;
#pragma unroll
    for (int n = 0; n < 8; n++) {
        s[n][0] *= inv0; s[n][1] *= inv0;
        s[n][2] *= inv1; s[n][3] *= inv1;
    }

    float o[2][4];
    o[0][0] = o[0][1] = o[0][2] = o[0][3] = 0.f;
    o[1][0] = o[1][1] = o[1][2] = o[1][3] = 0.f;
#pragma unroll
    for (int kc = 0; kc < 4; kc++) {
        uint32_t a0 = h2u(__floats2half2_rn(s[2 * kc][0],     s[2 * kc][1]));
        uint32_t a1 = h2u(__floats2half2_rn(s[2 * kc][2],     s[2 * kc][3]));
        uint32_t a2 = h2u(__floats2half2_rn(s[2 * kc + 1][0], s[2 * kc + 1][1]));
        uint32_t a3 = h2u(__floats2half2_rn(s[2 * kc + 1][2], s[2 * kc + 1][3]));
#pragma unroll
        for (int ot = 0; ot < 2; ot++) {
            uint32_t b0 = vt2[(8 * ot + g) * 36 + 8 * kc + tg];
            uint32_t b1 = vt2[(8 * ot + g) * 36 + 8 * kc + tg + 4];
            mma_f16(o[ot], a0, a1, a2, a3, b0, b1);
        }
    }

#pragma unroll
    for (int ot = 0; ot < 2; ot++) {
        int d0 = 8 * ot + 2 * tg;
        sO[d0 * 68 + qb + g]           = o[ot][0];
        sO[(d0 + 1) * 68 + qb + g]     = o[ot][1];
        sO[d0 * 68 + qb + 8 + g]       = o[ot][2];
        sO[(d0 + 1) * 68 + qb + 8 + g] = o[ot][3];
    }
    __syncthreads();
    for (int u = t; u < 256; u += 128) {
        int ch = u >> 4, px4 = u & 15;
        int row = px4 >> 1, col = (px4 & 1) * 4;
        float4 v = *reinterpret_cast<const float4*>(&sO[ch * 68 + row * 8 + col]);
        uint2 st;
        st.x = h2u(__floats2half2_rn(v.x, v.y));
        st.y = h2u(__floats2half2_rn(v.z, v.w));
        *reinterpret_cast<uint2*>(
            &low[((size_t)(bb * CDIM + head * 16 + ch) * HDIM + hh * 8 + row) * WDIM + ww * 8 + col]) = st;
    }
}

// ---------------- channel mean/max pool (half in, 4-way channel split) -------
__global__ void pool_kernel(const __half* __restrict__ low, const __half* __restrict__ high,
                            float* __restrict__ pool)
{
    int t = threadIdx.x;
    int px = blockIdx.x * 64 + (t >> 2);
    int cg = t & 3;
    int bb = blockIdx.y;
    const __half* lb = low  + (size_t)bb * CDIM * HW + px;
    const __half* hb = high + (size_t)bb * CDIM * HW + px;
    float s = 0.f, mx = -1e30f;
    for (int c = cg * 64; c < cg * 64 + 64; c++) {
        float v = __half2float(lb[(size_t)c * HW]) + __half2float(hb[(size_t)c * HW]);
        s += v; mx = fmaxf(mx, v);
    }
    s += __shfl_xor_sync(0xffffffffu, s, 1);
    s += __shfl_xor_sync(0xffffffffu, s, 2);
    mx = fmaxf(mx, __shfl_xor_sync(0xffffffffu, mx, 1));
    mx = fmaxf(mx, __shfl_xor_sync(0xffffffffu, mx, 2));
    if (cg == 0) {
        pool[(bb * 2 + 0) * HW + px] = s * (1.f / 256.f);
        pool[(bb * 2 + 1) * HW + px] = mx;
    }
}

// ---------------- hybrid 7x7 conv (2->2) + sigmoid ---------------------------
__global__ void hybrid_kernel(const float* __restrict__ pool, const float* __restrict__ hw,
                              const float* __restrict__ hb, float* __restrict__ sig)
{
    __shared__ float sw[196];
    __shared__ float sb[2];
    int t = threadIdx.x;
    if (t < 196) sw[t] = hw[t];
    if (t < 2) sb[t] = hb[t];
    __syncthreads();
    int p = blockIdx.x * 256 + t;
    int bb = blockIdx.y;
    int h = p >> 7, w = p & 127;
#pragma unroll
    for (int oc = 0; oc < 2; oc++) {
        float acc = sb[oc];
#pragma unroll
        for (int ic = 0; ic < 2; ic++)
            for (int ky = 0; ky < 7; ky++) {
                int hy = h + ky - 3;
                if (hy < 0 || hy >= HDIM) continue;
                for (int kx = 0; kx < 7; kx++) {
                    int wx = w + kx - 3;
                    if (wx < 0 || wx >= WDIM) continue;
                    acc += pool[(bb * 2 + ic) * HW + hy * WDIM + wx] * sw[((oc * 2 + ic) * 7 + ky) * 7 + kx];
                }
            }
        sig[(bb * 2 + oc) * HW + p] = 1.f / (1.f + __expf(-acc));
    }
}

// ---------------- mix (half in) -> half2 interleaved -------------------------
__global__ void mix_h(const __half* __restrict__ low, const __half* __restrict__ high,
                      const float* __restrict__ sig, __half* __restrict__ out)
{
    int i = blockIdx.x * 256 + threadIdx.x;
    int p = i & (HW - 1);
    int rest = i >> 14;
    int cp = rest & 127;
    int b = rest >> 7;
    float s0 = sig[(b * 2 + 0) * HW + p];
    float s1 = sig[(b * 2 + 1) * HW + p];
    size_t base = ((size_t)(b * CDIM + 2 * cp)) * HW + p;
    float m0 = __half2float(low[base]) * s0 + __half2float(high[base]) * s1;
    float m1 = __half2float(low[base + HW]) * s0 + __half2float(high[base + HW]) * s1;
    reinterpret_cast<__half2*>(out)[i] = __floats2half2_rn(m0, m1);
}

// ---------------- depthwise 7x7 + BN (half in) -> half interleaved -----------
__global__ void dw_kernel(const __half* __restrict__ in, const float* __restrict__ w,
                          const float* __restrict__ bng, const float* __restrict__ bnb,
                          const float* __restrict__ bnm, const float* __restrict__ bnv,
                          __half* __restrict__ out)
{
    __shared__ float sT[14 * 38];
    __shared__ float sWc[49];
    const int w0 = blockIdx.x * 32;
    const int h0 = blockIdx.y * 8;
    const int bc = blockIdx.z;
    const int b = bc >> 8, c = bc & 255;
    const int tx = threadIdx.x, ty = threadIdx.y;
    const int t = ty * 32 + tx;
    if (t < 49) sWc[t] = w[c * 49 + t];
    const __half* inb = in + (size_t)bc * HW;
    for (int e = t; e < 14 * 38; e += 256) {
        int row = e / 38, cc = e % 38;
        int h = h0 + row - 3, ww = w0 + cc - 3;
        float v = 0.f;
        if (h >= 0 && h < HDIM && ww >= 0 && ww < WDIM) v = __half2float(inb[h * WDIM + ww]);
        sT[e] = v;
    }
    __syncthreads();
    float acc = 0.f;
#pragma unroll
    for (int ky = 0; ky < 7; ky++)
#pragma unroll
        for (int kx = 0; kx < 7; kx++)
            acc += sT[(ty + ky) * 38 + tx + kx] * sWc[ky * 7 + kx];
    float sc = bng[c] * rsqrtf(bnv[c] + EPS);
    float sh = bnb[c] - bnm[c] * sc;
    int pix = (h0 + ty) * WDIM + w0 + tx;
    out[((size_t)(b * 128 + (c >> 1)) * HW + pix) * 2 + (c & 1)] = __float2half_rn(acc * sc + sh);
}

// ---------------- launch ------------------------------------------------------
extern "C" void kernel_launch(void* const* d_in, const int* in_sizes, int n_in,
                              void* d_out, int out_size)
{
    const float* x        = (const float*)d_in[0];
    const float* qkv_w    = (const float*)d_in[1];
    const float* local1_w = (const float*)d_in[2];
    const float* l1g = (const float*)d_in[3];
    const float* l1b = (const float*)d_in[4];
    const float* l1m = (const float*)d_in[5];
    const float* l1v = (const float*)d_in[6];
    const float* local2_w = (const float*)d_in[7];
    const float* l2g = (const float*)d_in[8];
    const float* l2b = (const float*)d_in[9];
    const float* l2m = (const float*)d_in[10];
    const float* l2v = (const float*)d_in[11];
    const float* rel_table = (const float*)d_in[12];
    const float* hybrid_w  = (const float*)d_in[13];
    const float* hybrid_b  = (const float*)d_in[14];
    const float* smooth_w  = (const float*)d_in[15];
    const float* smg = (const float*)d_in[16];
    const float* smb = (const float*)d_in[17];
    const float* smm = (const float*)d_in[18];
    const float* smv = (const float*)d_in[19];
    const float* proj_dw_w = (const float*)d_in[20];
    const float* prg = (const float*)d_in[21];
    const float* prb = (const float*)d_in[22];
    const float* prm = (const float*)d_in[23];
    const float* prv = (const float*)d_in[24];
    const float* proj_pw_w = (const float*)d_in[25];

    float *p_kh, *p_pool, *p_sig;
    __half *p_xh, *p_mixh, *p_dwh, *p_qkvh, *p_qhh, *p_lowh, *p_highh, *p_smh;
    __half *p_w5t, *p_w3t, *p_wq, *p_w2, *p_wp;
    cudaGetSymbolAddress((void**)&p_kh,   g_kh);
    cudaGetSymbolAddress((void**)&p_pool, g_pool);
    cudaGetSymbolAddress((void**)&p_sig,  g_sig);
    cudaGetSymbolAddress((void**)&p_xh,   g_xh);
    cudaGetSymbolAddress((void**)&p_mixh, g_mixh);
    cudaGetSymbolAddress((void**)&p_dwh,  g_dwh);
    cudaGetSymbolAddress((void**)&p_qkvh, g_qkvh);
    cudaGetSymbolAddress((void**)&p_qhh,  g_qhh);
    cudaGetSymbolAddress((void**)&p_lowh, g_lowh);
    cudaGetSymbolAddress((void**)&p_highh,g_highh);
    cudaGetSymbolAddress((void**)&p_smh,  g_smh);
    cudaGetSymbolAddress((void**)&p_w5t,  g_w5t);
    cudaGetSymbolAddress((void**)&p_w3t,  g_w3t);
    cudaGetSymbolAddress((void**)&p_wq,   g_wq);
    cudaGetSymbolAddress((void**)&p_w2,   g_w2);
    cudaGetSymbolAddress((void**)&p_wp,   g_wp);

    const int smem3 = 2 * (8 * 10 * 36 + 9  * 512) * 4;   // 59904 B
    const int smem5 = 2 * (8 * 12 * 38 + 25 * 512) * 4;   // 131584 B
    const int smemG = 2 * GEM_STG2 * 4;                   // 44032 B
    cudaFuncSetAttribute(conv_h<5, false, true>, cudaFuncAttributeMaxDynamicSharedMemorySize, smem5);
    cudaFuncSetAttribute(conv_h<3, true, false>, cudaFuncAttributeMaxDynamicSharedMemorySize, smem3);
    cudaFuncSetAttribute(gemm1x1_h<true>,  cudaFuncAttributeMaxDynamicSharedMemorySize, smemG);
    cudaFuncSetAttribute(gemm1x1_h<false>, cudaFuncAttributeMaxDynamicSharedMemorySize, smemG);

    // ---- pre-pass ----
    interleave_h<<<BDIM * 128 * HW / 256, 256>>>(x, p_xh);
    roundw_h<<<(3 * CDIM * CDIM + 255) / 256, 256>>>(qkv_w, p_wq, 3 * CDIM * CDIM);
    roundw_h<<<(CDIM * CDIM + 255) / 256, 256>>>(local2_w, p_w2, CDIM * CDIM);
    roundw_h<<<(CDIM * CDIM + 255) / 256, 256>>>(proj_pw_w, p_wp, CDIM * CDIM);
    wtransform_h<9><<<(CDIM * CDIM * 9 + 255) / 256, 256>>>(local1_w, p_w3t);
    wtransform_h<25><<<(CDIM * CDIM * 25 + 255) / 256, 256>>>(smooth_w, p_w5t);

    // ---- main chain ----
    gemm1x1_h<true><<<dim3(64, 12, 4), 256, smemG>>>(p_xh, p_wq, nullptr, nullptr, nullptr, nullptr,
                                                     p_qkvh, 768);
    gemm1x1_h<false><<<dim3(64, 4, 4), 256, smemG>>>(p_xh, p_w2, l2g, l2b, l2m, l2v, p_kh, 256);
    conv_h<3, true, false><<<dim3(4, 16, 16), 256, smem3>>>(p_xh, p_w3t, l1g, l1b, l1m, l1v,
                                                            p_qhh, p_kh, p_highh);
    attn_mma<<<dim3(256, 16, 4), 128>>>(p_qkvh, p_qhh, p_kh, rel_table, p_lowh);
    pool_kernel<<<dim3(256, 4), 256>>>(p_lowh, p_highh, p_pool);
    hybrid_kernel<<<dim3(64, 4), 256>>>(p_pool, hybrid_w, hybrid_b, p_sig);
    mix_h<<<BDIM * 128 * HW / 256, 256>>>(p_lowh, p_highh, p_sig, p_mixh);
    conv_h<5, false, true><<<dim3(4, 16, 16), 256, smem5>>>(p_mixh, p_w5t, smg, smb, smm, smv,
                                                            p_smh, nullptr, nullptr);
    dw_kernel<<<dim3(4, 16, 1024), dim3(32, 8)>>>(p_smh, proj_dw_w, prg, prb, prm, prv, p_dwh);
    gemm1x1_h<false><<<dim3(64, 4, 4), 256, smemG>>>(p_dwh, p_wp, nullptr, nullptr, nullptr, nullptr,
                                                     (float*)d_out, 256);
}

// round 16
// speedup vs baseline: 2.0741x; 1.0184x over previous
#include <cuda_runtime.h>
#include <cuda_fp16.h>
#include <math.h>
#include <stdint.h>

#define HDIM 128
#define WDIM 128
#define HW (HDIM*WDIM)
#define CDIM 256
#define BDIM 4
#define NHEAD 16
#define EPS 1e-5f

// ---------------- scratch ----------------------------------------------------
__device__ float  g_pool[BDIM*2*HW];
__device__ float  g_sig [BDIM*2*HW];
// half activations
__device__ __half g_xh  [BDIM*CDIM*HW];   // channel-pair interleaved
__device__ __half g_mixh[BDIM*CDIM*HW];   // channel-pair interleaved
__device__ __half g_dwh [BDIM*CDIM*HW];   // channel-pair interleaved
__device__ __half g_qkvh[BDIM*3*CDIM*HW]; // planar half
__device__ __half g_qhh [BDIM*CDIM*HW];   // planar half
__device__ __half g_khh [BDIM*CDIM*HW];   // planar half
__device__ __half g_lowh[BDIM*CDIM*HW];   // planar half
__device__ __half g_highh[BDIM*CDIM*HW];  // planar half
__device__ __half g_smh [BDIM*CDIM*HW];   // planar half
// half weights
__device__ __half g_w5t [CDIM*CDIM*25];
__device__ __half g_w3t [CDIM*CDIM*9];
__device__ __half g_wq  [3*CDIM*CDIM];
__device__ __half g_w2  [CDIM*CDIM];
__device__ __half g_wp  [CDIM*CDIM];

// ---------------- helpers ----------------------------------------------------
__device__ __forceinline__ void cp16(void* dst, const void* src) {
    uint32_t d = (uint32_t)__cvta_generic_to_shared(dst);
    asm volatile("cp.async.cg.shared.global [%0], [%1], 16;" :: "r"(d), "l"(src));
}
__device__ __forceinline__ void cp4z(void* dst, const void* src, bool pred) {
    uint32_t d = (uint32_t)__cvta_generic_to_shared(dst);
    int sz = pred ? 4 : 0;
    asm volatile("cp.async.ca.shared.global [%0], [%1], 4, %2;" :: "r"(d), "l"(src), "r"(sz));
}
__device__ __forceinline__ void cp_commit() { asm volatile("cp.async.commit_group;"); }
__device__ __forceinline__ void cp_wait1()  { asm volatile("cp.async.wait_group 1;"); }

__device__ __forceinline__ void mma_f16(float* d, uint32_t a0, uint32_t a1,
                                        uint32_t a2, uint32_t a3,
                                        uint32_t b0, uint32_t b1) {
    asm volatile(
        "mma.sync.aligned.m16n8k16.row.col.f32.f16.f16.f32 "
        "{%0,%1,%2,%3}, {%4,%5,%6,%7}, {%8,%9}, {%0,%1,%2,%3};"
        : "+f"(d[0]), "+f"(d[1]), "+f"(d[2]), "+f"(d[3])
        : "r"(a0), "r"(a1), "r"(a2), "r"(a3), "r"(b0), "r"(b1));
}

__device__ __forceinline__ uint32_t h2u(__half2 h) {
    return *reinterpret_cast<uint32_t*>(&h);
}

// ---------------- pre-pass kernels -------------------------------------------
__global__ void interleave_h(const float* __restrict__ in, __half* __restrict__ out)
{
    int i = blockIdx.x * 256 + threadIdx.x;
    int p = i & (HW - 1);
    int rest = i >> 14;
    int cp = rest & 127;
    int b = rest >> 7;
    const float* base = in + ((size_t)(b * CDIM + 2 * cp)) * HW + p;
    reinterpret_cast<__half2*>(out)[i] = __floats2half2_rn(base[0], base[HW]);
}

__global__ void roundw_h(const float* __restrict__ in, __half* __restrict__ out, int n)
{
    int i = blockIdx.x * 256 + threadIdx.x;
    if (i < n) out[i] = __float2half_rn(in[i]);
}

template<int KKS>
__global__ void wtransform_h(const float* __restrict__ wgt, __half* __restrict__ dst)
{
    int tid = blockIdx.x * 256 + threadIdx.x;
    int total = 4 * 16 * KKS * 1024;
    if (tid >= total) return;
    int ic  = tid & 15;
    int oc  = (tid >> 4) & 63;
    int tap = (tid >> 10) % KKS;
    int ics = (tid / (1024 * KKS)) & 15;
    int ocT = tid / (1024 * KKS * 16);
    dst[tid] = __float2half_rn(wgt[((size_t)((ocT * 64 + oc) * 256 + ics * 16 + ic)) * KKS + tap]);
}

// ---------------- 1x1 conv as fp16 GEMM, cp.async double-buffered ------------
#define XSTR2 264
#define WSTR2 20
#define GEM_XF2 (16*XSTR2)
#define GEM_WF2 (64*WSTR2)
#define GEM_STG2 (GEM_XF2+GEM_WF2)

template<bool OUTH>
__global__ __launch_bounds__(256, 2)
void gemm1x1_h(const __half* __restrict__ in, const __half* __restrict__ w,
               const float* __restrict__ bng, const float* __restrict__ bnb,
               const float* __restrict__ bnm, const float* __restrict__ bnv,
               void* __restrict__ outv, int OC)
{
    extern __shared__ uint32_t smem2[];

    const int bb  = blockIdx.z;
    const int ocT = blockIdx.y;
    const int p0  = blockIdx.x * 256;
    const int t   = threadIdx.x;
    const int warp = t >> 5, lane = t & 31;
    const int g = lane >> 2, tg = lane & 3;
    const int wm = warp >> 2;
    const int wn = warp & 3;

    const __half2* in2 = reinterpret_cast<const __half2*>(in) + (size_t)bb * 128 * HW;

    auto load = [&](int s, int ic0) {
        uint32_t* sX = smem2 + s * GEM_STG2;
        uint32_t* sW = sX + GEM_XF2;
        int cp0 = ic0 >> 1;
#pragma unroll
        for (int j = 0; j < 4; j++) {
            int idx = j * 256 + t;
            int icp = idx >> 6, px4 = idx & 63;
            cp16(&sX[icp * XSTR2 + px4 * 4], in2 + (cp0 + icp) * HW + p0 + px4 * 4);
        }
        {
            int oc = t >> 2, icq = t & 3;
            cp16(&sW[oc * WSTR2 + icq * 4],
                 w + (size_t)(ocT * 64 + oc) * CDIM + ic0 + icq * 8);
        }
    };

    float acc[2][8][4];
#pragma unroll
    for (int i = 0; i < 2; i++)
#pragma unroll
        for (int j = 0; j < 8; j++)
#pragma unroll
            for (int c = 0; c < 4; c++) acc[i][j][c] = 0.f;

    load(0, 0);
    cp_commit();

    for (int ic0 = 0; ic0 < CDIM; ic0 += 32) {
        int cur = (ic0 >> 5) & 1;
        if (ic0 + 32 < CDIM) load(cur ^ 1, ic0 + 32);
        cp_commit();
        cp_wait1();
        __syncthreads();

        uint32_t* sX = smem2 + cur * GEM_STG2;
        uint32_t* sW = sX + GEM_XF2;
#pragma unroll
        for (int ks = 0; ks < 2; ks++) {
            int kb = ks * 8;
            uint32_t a[2][4];
#pragma unroll
            for (int i = 0; i < 2; i++) {
                int row = wm * 32 + i * 16 + g;
                a[i][0] = sW[row * WSTR2 + kb + tg];
                a[i][1] = sW[(row + 8) * WSTR2 + kb + tg];
                a[i][2] = sW[row * WSTR2 + kb + tg + 4];
                a[i][3] = sW[(row + 8) * WSTR2 + kb + tg + 4];
            }
#pragma unroll
            for (int j = 0; j < 8; j++) {
                int px = wn * 64 + j * 8 + g;
                uint32_t b0 = sX[(kb + tg) * XSTR2 + px];
                uint32_t b1 = sX[(kb + tg + 4) * XSTR2 + px];
                mma_f16(acc[0][j], a[0][0], a[0][1], a[0][2], a[0][3], b0, b1);
                mma_f16(acc[1][j], a[1][0], a[1][1], a[1][2], a[1][3], b0, b1);
            }
        }
        __syncthreads();
    }

#pragma unroll
    for (int i = 0; i < 2; i++) {
        int oc_lo = ocT * 64 + wm * 32 + i * 16 + g;
        int oc_hi = oc_lo + 8;
        float sc0 = 1.f, sh0 = 0.f, sc1 = 1.f, sh1 = 0.f;
        if (bng) {
            sc0 = bng[oc_lo] * rsqrtf(bnv[oc_lo] + EPS); sh0 = bnb[oc_lo] - bnm[oc_lo] * sc0;
            sc1 = bng[oc_hi] * rsqrtf(bnv[oc_hi] + EPS); sh1 = bnb[oc_hi] - bnm[oc_hi] * sc1;
        }
#pragma unroll
        for (int j = 0; j < 8; j++) {
            int px = p0 + wn * 64 + j * 8 + 2 * tg;
            float v00 = acc[i][j][0] * sc0 + sh0;
            float v01 = acc[i][j][1] * sc0 + sh0;
            float v10 = acc[i][j][2] * sc1 + sh1;
            float v11 = acc[i][j][3] * sc1 + sh1;
            if (OUTH) {
                __half* oh = (__half*)outv;
                *reinterpret_cast<__half2*>(&oh[((size_t)bb * OC + oc_lo) * HW + px]) =
                    __floats2half2_rn(v00, v01);
                *reinterpret_cast<__half2*>(&oh[((size_t)bb * OC + oc_hi) * HW + px]) =
                    __floats2half2_rn(v10, v11);
            } else {
                float* of = (float*)outv;
                float* o0 = &of[((size_t)bb * OC + oc_lo) * HW + px];
                float* o1 = &of[((size_t)bb * OC + oc_hi) * HW + px];
                o0[0] = v00; o0[1] = v01;
                o1[0] = v10; o1[1] = v11;
            }
        }
    }
}

// ---------------- KxK conv via fp16 MMA, double-buffered ---------------------
// ADD_HIGH: outv = half qh planar, out2v = half high planar (khbuf half)
// OUTH (and !ADD_HIGH): outv = half planar
template<int KS, bool ADD_HIGH, bool OUTH>
__global__ __launch_bounds__(256, (KS == 3 ? 2 : 1))
void conv_h(const __half* __restrict__ in, const __half* __restrict__ wt,
            const float* __restrict__ bng, const float* __restrict__ bnb,
            const float* __restrict__ bnm, const float* __restrict__ bnv,
            void* __restrict__ outv,
            const __half* __restrict__ khbuf, void* __restrict__ out2v)
{
    constexpr int PAD = KS / 2;
    constexpr int PH = 8 + KS - 1;
    constexpr int PW = 32 + KS - 1;
    constexpr int PWS2 = (KS == 5) ? 38 : 36;
    constexpr int KKS = KS * KS;
    constexpr int PATCH2 = 8 * PH * PWS2;
    constexpr int WGT2 = KKS * 512;
    constexpr int STG2 = PATCH2 + WGT2;

    extern __shared__ uint32_t smem2[];

    const int w0 = blockIdx.x * 32;
    const int h0 = blockIdx.y * 8;
    const int bb  = blockIdx.z >> 2;
    const int ocT = blockIdx.z & 3;
    const int t = threadIdx.x;
    const int warp = t >> 5, lane = t & 31;
    const int g = lane >> 2, tg = lane & 3;
    const int wm = warp >> 2;
    const int wn = warp & 3;

    const __half2* in2 = reinterpret_cast<const __half2*>(in) + (size_t)bb * 128 * HW;

    auto load = [&](int s, int chunk) {
        uint32_t* sP = smem2 + s * STG2;
        __half* sWh = reinterpret_cast<__half*>(sP + PATCH2);
        for (int e = t; e < 8 * PH * PW; e += 256) {
            int icp = e / (PH * PW), rem = e % (PH * PW);
            int row = rem / PW, cc = rem % PW;
            int h = h0 + row - PAD, w = w0 + cc - PAD;
            bool ok = ((unsigned)h < HDIM) && ((unsigned)w < WDIM);
            cp4z(&sP[icp * PH * PWS2 + row * PWS2 + cc],
                 in2 + (chunk * 8 + icp) * HW + (ok ? h : 0) * WDIM + (ok ? w : 0), ok);
        }
        const __half* wb = wt + (size_t)(ocT * 16 + chunk) * (KKS * 1024);
        for (int e = t * 8; e < KKS * 1024; e += 2048)
            cp16(&sWh[e], &wb[e]);
    };

    float acc[2][8][4];
#pragma unroll
    for (int i = 0; i < 2; i++)
#pragma unroll
        for (int j = 0; j < 8; j++)
#pragma unroll
            for (int c = 0; c < 4; c++) acc[i][j][c] = 0.f;

    load(0, 0);
    cp_commit();

    for (int chunk = 0; chunk < 16; chunk++) {
        int cur = chunk & 1;
        if (chunk + 1 < 16) load(cur ^ 1, chunk + 1);
        cp_commit();
        cp_wait1();
        __syncthreads();

        uint32_t* sP = smem2 + cur * STG2;
        uint32_t* sW = sP + PATCH2;
#pragma unroll
        for (int ky = 0; ky < KS; ky++)
#pragma unroll
            for (int kx = 0; kx < KS; kx++) {
                const int tap = ky * KS + kx;
                uint32_t a[2][4];
#pragma unroll
                for (int i = 0; i < 2; i++) {
                    int row = wm * 32 + i * 16 + g;
                    a[i][0] = sW[tap * 512 + row * 8 + tg];
                    a[i][1] = sW[tap * 512 + (row + 8) * 8 + tg];
                    a[i][2] = sW[tap * 512 + row * 8 + tg + 4];
                    a[i][3] = sW[tap * 512 + (row + 8) * 8 + tg + 4];
                }
#pragma unroll
                for (int j = 0; j < 8; j++) {
                    int hr = wn * 2 + (j >> 2) + ky;
                    int wc = (j & 3) * 8 + kx + g;
                    uint32_t b0 = sP[tg * PH * PWS2 + hr * PWS2 + wc];
                    uint32_t b1 = sP[(tg + 4) * PH * PWS2 + hr * PWS2 + wc];
                    mma_f16(acc[0][j], a[0][0], a[0][1], a[0][2], a[0][3], b0, b1);
                    mma_f16(acc[1][j], a[1][0], a[1][1], a[1][2], a[1][3], b0, b1);
                }
            }
        __syncthreads();
    }

#pragma unroll
    for (int i = 0; i < 2; i++) {
        int oc_lo = ocT * 64 + wm * 32 + i * 16 + g;
        int oc_hi = oc_lo + 8;
        float sc0 = bng[oc_lo] * rsqrtf(bnv[oc_lo] + EPS);
        float sh0 = bnb[oc_lo] - bnm[oc_lo] * sc0;
        float sc1 = bng[oc_hi] * rsqrtf(bnv[oc_hi] + EPS);
        float sh1 = bnb[oc_hi] - bnm[oc_hi] * sc1;
#pragma unroll
        for (int j = 0; j < 8; j++) {
            int h = h0 + wn * 2 + (j >> 2);
            int w = w0 + (j & 3) * 8 + 2 * tg;
            size_t i0 = ((size_t)(bb * CDIM + oc_lo) * HDIM + h) * WDIM + w;
            size_t i1 = ((size_t)(bb * CDIM + oc_hi) * HDIM + h) * WDIM + w;
            float v00 = acc[i][j][0] * sc0 + sh0;
            float v01 = acc[i][j][1] * sc0 + sh0;
            float v10 = acc[i][j][2] * sc1 + sh1;
            float v11 = acc[i][j][3] * sc1 + sh1;
            if (ADD_HIGH) {
                __half* oh = (__half*)outv;
                __half* o2 = (__half*)out2v;
                *reinterpret_cast<__half2*>(&oh[i0]) = __floats2half2_rn(v00, v01);
                *reinterpret_cast<__half2*>(&oh[i1]) = __floats2half2_rn(v10, v11);
                __half2 k0 = *reinterpret_cast<const __half2*>(&khbuf[i0]);
                __half2 k1 = *reinterpret_cast<const __half2*>(&khbuf[i1]);
                *reinterpret_cast<__half2*>(&o2[i0]) =
                    __floats2half2_rn(v00 + __half2float(k0.x), v01 + __half2float(k0.y));
                *reinterpret_cast<__half2*>(&o2[i1]) =
                    __floats2half2_rn(v10 + __half2float(k1.x), v11 + __half2float(k1.y));
            } else if (OUTH) {
                __half* oh = (__half*)outv;
                *reinterpret_cast<__half2*>(&oh[i0]) = __floats2half2_rn(v00, v01);
                *reinterpret_cast<__half2*>(&oh[i1]) = __floats2half2_rn(v10, v11);
            } else {
                float* of = (float*)outv;
                of[i0] = v00; of[i0 + 1] = v01;
                of[i1] = v10; of[i1 + 1] = v11;
            }
        }
    }
}

// ---------------- window attention via fp16 tensor cores ---------------------
#define AQ_OFF  0
#define AK_OFF  576
#define AQH_OFF 1152
#define AKH_OFF 1728
#define AVT_OFF 2304
#define ART_OFF 2880
#define AO_OFF  3108
#define APOOL_SZ 4196

__global__ __launch_bounds__(128)
void attn_mma(const __half* __restrict__ qkvh, const __half* __restrict__ qhh,
              const __half* __restrict__ khh, const float* __restrict__ rel_table,
              __half* __restrict__ low)
{
    __shared__ __align__(16) uint32_t sPool[APOOL_SZ];

    const int wi = blockIdx.x;
    const int head = blockIdx.y;
    const int bb = blockIdx.z;
    const int hh = wi >> 4, ww = wi & 15;
    const int t = threadIdx.x;
    const int warp = t >> 5, lane = t & 31;
    const int g = lane >> 2, tg = lane & 3;

    float* sRT = reinterpret_cast<float*>(sPool + ART_OFF);
    float* sO  = reinterpret_cast<float*>(sPool + AO_OFF);

    for (int u = t; u < 1280; u += 128) {
        int a = u >> 8;
        int unit = u & 255;
        int ch = unit >> 4, px4 = unit & 15;
        int row = px4 >> 1, col = (px4 & 1) * 4;
        int tok = row * 8 + col;
        const __half* gsrc = (a < 3)
            ? qkvh + ((size_t)(bb * 768 + a * 256 + head * 16 + ch) * HDIM + hh * 8 + row) * WDIM + ww * 8 + col
            : (a == 3)
            ? qhh + ((size_t)(bb * CDIM + head * 16 + ch) * HDIM + hh * 8 + row) * WDIM + ww * 8 + col
            : khh + ((size_t)(bb * CDIM + head * 16 + ch) * HDIM + hh * 8 + row) * WDIM + ww * 8 + col;
        uint2 v = *reinterpret_cast<const uint2*>(gsrc);
        if (a == 2) {
            uint32_t* d2 = sPool + AVT_OFF;
            int base = ch * 36 + tok / 2;
            d2[base] = v.x; d2[base + 1] = v.y;
        } else {
            int off = (a == 0) ? AQ_OFF : (a == 1) ? AK_OFF : (a == 3) ? AQH_OFF : AKH_OFF;
            __half* dst = reinterpret_cast<__half*>(sPool + off);
            const __half* hv = reinterpret_cast<const __half*>(&v);
            dst[(tok + 0) * 18 + ch] = hv[0];
            dst[(tok + 1) * 18 + ch] = hv[1];
            dst[(tok + 2) * 18 + ch] = hv[2];
            dst[(tok + 3) * 18 + ch] = hv[3];
        }
    }
    for (int i = t; i < 225; i += 128) sRT[i] = rel_table[i * NHEAD + head];
    __syncthreads();

    const int qb = warp * 16;
    const uint32_t* q2  = sPool + AQ_OFF;
    const uint32_t* k2  = sPool + AK_OFF;
    const uint32_t* qh2 = sPool + AQH_OFF;
    const uint32_t* kh2 = sPool + AKH_OFF;
    const uint32_t* vt2 = sPool + AVT_OFF;

    uint32_t aq[4], ah[4];
    aq[0] = q2[(qb + g) * 9 + tg];      aq[1] = q2[(qb + 8 + g) * 9 + tg];
    aq[2] = q2[(qb + g) * 9 + tg + 4];  aq[3] = q2[(qb + 8 + g) * 9 + tg + 4];
    ah[0] = qh2[(qb + g) * 9 + tg];     ah[1] = qh2[(qb + 8 + g) * 9 + tg];
    ah[2] = qh2[(qb + g) * 9 + tg + 4]; ah[3] = qh2[(qb + 8 + g) * 9 + tg + 4];

    float s[8][4];
#pragma unroll
    for (int n = 0; n < 8; n++) { s[n][0] = s[n][1] = s[n][2] = s[n][3] = 0.f; }
#pragma unroll
    for (int n = 0; n < 8; n++) {
        int kt = n * 8 + g;
        uint32_t b0 = k2[kt * 9 + tg],  b1 = k2[kt * 9 + tg + 4];
        mma_f16(s[n], aq[0], aq[1], aq[2], aq[3], b0, b1);
        b0 = kh2[kt * 9 + tg]; b1 = kh2[kt * 9 + tg + 4];
        mma_f16(s[n], ah[0], ah[1], ah[2], ah[3], b0, b1);
    }

    const int rq0 = qb + g, rq1 = qb + g + 8;
    const int r0h = rq0 >> 3, r0l = rq0 & 7;
    const int r1h = rq1 >> 3, r1l = rq1 & 7;
#pragma unroll
    for (int n = 0; n < 8; n++)
#pragma unroll
        for (int c = 0; c < 2; c++) {
            int m = n * 8 + 2 * tg + c;
            int mh = m >> 3, ml = m & 7;
            s[n][c]     = s[n][c]     * 0.25f + sRT[(r0h - mh + 7) * 15 + (r0l - ml + 7)];
            s[n][2 + c] = s[n][2 + c] * 0.25f + sRT[(r1h - mh + 7) * 15 + (r1l - ml + 7)];
        }

    float mx0 = -1e30f, mx1 = -1e30f;
#pragma unroll
    for (int n = 0; n < 8; n++) {
        mx0 = fmaxf(mx0, fmaxf(s[n][0], s[n][1]));
        mx1 = fmaxf(mx1, fmaxf(s[n][2], s[n][3]));
    }
    mx0 = fmaxf(mx0, __shfl_xor_sync(0xffffffffu, mx0, 1));
    mx0 = fmaxf(mx0, __shfl_xor_sync(0xffffffffu, mx0, 2));
    mx1 = fmaxf(mx1, __shfl_xor_sync(0xffffffffu, mx1, 1));
    mx1 = fmaxf(mx1, __shfl_xor_sync(0xffffffffu, mx1, 2));
    float sum0 = 0.f, sum1 = 0.f;
#pragma unroll
    for (int n = 0; n < 8; n++) {
        s[n][0] = __expf(s[n][0] - mx0); s[n][1] = __expf(s[n][1] - mx0);
        s[n][2] = __expf(s[n][2] - mx1); s[n][3] = __expf(s[n][3] - mx1);
        sum0 += s[n][0] + s[n][1];
        sum1 += s[n][2] + s[n][3];
    }
    sum0 += __shfl_xor_sync(0xffffffffu, sum0, 1);
    sum0 += __shfl_xor_sync(0xffffffffu, sum0, 2);
    sum1 += __shfl_xor_sync(0xffffffffu, sum1, 1);
    sum1 += __shfl_xor_sync(0xffffffffu, sum1, 2);
    float inv0 = 1.f / sum0, inv1 = 1.f / sum1;
#pragma unroll
    for (int n = 0; n < 8; n++) {
        s[n][0] *= inv0; s[n][1] *= inv0;
        s[n][2] *= inv1; s[n][3] *= inv1;
    }

    float o[2][4];
    o[0][0] = o[0][1] = o[0][2] = o[0][3] = 0.f;
    o[1][0] = o[1][1] = o[1][2] = o[1][3] = 0.f;
#pragma unroll
    for (int kc = 0; kc < 4; kc++) {
        uint32_t a0 = h2u(__floats2half2_rn(s[2 * kc][0],     s[2 * kc][1]));
        uint32_t a1 = h2u(__floats2half2_rn(s[2 * kc][2],     s[2 * kc][3]));
        uint32_t a2 = h2u(__floats2half2_rn(s[2 * kc + 1][0], s[2 * kc + 1][1]));
        uint32_t a3 = h2u(__floats2half2_rn(s[2 * kc + 1][2], s[2 * kc + 1][3]));
#pragma unroll
        for (int ot = 0; ot < 2; ot++) {
            uint32_t b0 = vt2[(8 * ot + g) * 36 + 8 * kc + tg];
            uint32_t b1 = vt2[(8 * ot + g) * 36 + 8 * kc + tg + 4];
            mma_f16(o[ot], a0, a1, a2, a3, b0, b1);
        }
    }

#pragma unroll
    for (int ot = 0; ot < 2; ot++) {
        int d0 = 8 * ot + 2 * tg;
        sO[d0 * 68 + qb + g]           = o[ot][0];
        sO[(d0 + 1) * 68 + qb + g]     = o[ot][1];
        sO[d0 * 68 + qb + 8 + g]       = o[ot][2];
        sO[(d0 + 1) * 68 + qb + 8 + g] = o[ot][3];
    }
    __syncthreads();
    for (int u = t; u < 256; u += 128) {
        int ch = u >> 4, px4 = u & 15;
        int row = px4 >> 1, col = (px4 & 1) * 4;
        float4 v = *reinterpret_cast<const float4*>(&sO[ch * 68 + row * 8 + col]);
        uint2 st;
        st.x = h2u(__floats2half2_rn(v.x, v.y));
        st.y = h2u(__floats2half2_rn(v.z, v.w));
        *reinterpret_cast<uint2*>(
            &low[((size_t)(bb * CDIM + head * 16 + ch) * HDIM + hh * 8 + row) * WDIM + ww * 8 + col]) = st;
    }
}

// ---------------- channel mean/max pool (half in, 4-way channel split) -------
__global__ void pool_kernel(const __half* __restrict__ low, const __half* __restrict__ high,
                            float* __restrict__ pool)
{
    int t = threadIdx.x;
    int px = blockIdx.x * 64 + (t >> 2);
    int cg = t & 3;
    int bb = blockIdx.y;
    const __half* lb = low  + (size_t)bb * CDIM * HW + px;
    const __half* hb = high + (size_t)bb * CDIM * HW + px;
    float s = 0.f, mx = -1e30f;
    for (int c = cg * 64; c < cg * 64 + 64; c++) {
        float v = __half2float(lb[(size_t)c * HW]) + __half2float(hb[(size_t)c * HW]);
        s += v; mx = fmaxf(mx, v);
    }
    s += __shfl_xor_sync(0xffffffffu, s, 1);
    s += __shfl_xor_sync(0xffffffffu, s, 2);
    mx = fmaxf(mx, __shfl_xor_sync(0xffffffffu, mx, 1));
    mx = fmaxf(mx, __shfl_xor_sync(0xffffffffu, mx, 2));
    if (cg == 0) {
        pool[(bb * 2 + 0) * HW + px] = s * (1.f / 256.f);
        pool[(bb * 2 + 1) * HW + px] = mx;
    }
}

// ---------------- hybrid 7x7 conv (2->2) + sigmoid, smem-tiled ---------------
__global__ void hybrid_kernel(const float* __restrict__ pool, const float* __restrict__ hw,
                              const float* __restrict__ hb, float* __restrict__ sig)
{
    __shared__ float sP[2][14 * 38];
    __shared__ float sw[196];
    __shared__ float sb[2];
    const int w0 = blockIdx.x * 32;
    const int h0 = blockIdx.y * 8;
    const int bb = blockIdx.z;
    const int tx = threadIdx.x, ty = threadIdx.y;
    const int t = ty * 32 + tx;
    if (t < 196) sw[t] = hw[t];
    if (t < 2) sb[t] = hb[t];
    for (int e = t; e < 2 * 14 * 38; e += 256) {
        int ic = e / (14 * 38), rem = e % (14 * 38);
        int row = rem / 38, cc = rem % 38;
        int h = h0 + row - 3, w = w0 + cc - 3;
        float v = 0.f;
        if (h >= 0 && h < HDIM && w >= 0 && w < WDIM)
            v = pool[(bb * 2 + ic) * HW + h * WDIM + w];
        sP[ic][row * 38 + cc] = v;
    }
    __syncthreads();
    int p = (h0 + ty) * WDIM + w0 + tx;
#pragma unroll
    for (int oc = 0; oc < 2; oc++) {
        float acc = sb[oc];
#pragma unroll
        for (int ic = 0; ic < 2; ic++)
#pragma unroll
            for (int ky = 0; ky < 7; ky++)
#pragma unroll
                for (int kx = 0; kx < 7; kx++)
                    acc += sP[ic][(ty + ky) * 38 + tx + kx] * sw[((oc * 2 + ic) * 7 + ky) * 7 + kx];
        sig[(bb * 2 + oc) * HW + p] = 1.f / (1.f + __expf(-acc));
    }
}

// ---------------- mix (half in) -> half2 interleaved -------------------------
__global__ void mix_h(const __half* __restrict__ low, const __half* __restrict__ high,
                      const float* __restrict__ sig, __half* __restrict__ out)
{
    int i = blockIdx.x * 256 + threadIdx.x;
    int p = i & (HW - 1);
    int rest = i >> 14;
    int cp = rest & 127;
    int b = rest >> 7;
    float s0 = sig[(b * 2 + 0) * HW + p];
    float s1 = sig[(b * 2 + 1) * HW + p];
    size_t base = ((size_t)(b * CDIM + 2 * cp)) * HW + p;
    float m0 = __half2float(low[base]) * s0 + __half2float(high[base]) * s1;
    float m1 = __half2float(low[base + HW]) * s0 + __half2float(high[base + HW]) * s1;
    reinterpret_cast<__half2*>(out)[i] = __floats2half2_rn(m0, m1);
}

// ---------------- depthwise 7x7 + BN (half in) -> half interleaved -----------
__global__ void dw_kernel(const __half* __restrict__ in, const float* __restrict__ w,
                          const float* __restrict__ bng, const float* __restrict__ bnb,
                          const float* __restrict__ bnm, const float* __restrict__ bnv,
                          __half* __restrict__ out)
{
    __shared__ float sT[14 * 38];
    __shared__ float sWc[49];
    const int w0 = blockIdx.x * 32;
    const int h0 = blockIdx.y * 8;
    const int bc = blockIdx.z;
    const int b = bc >> 8, c = bc & 255;
    const int tx = threadIdx.x, ty = threadIdx.y;
    const int t = ty * 32 + tx;
    if (t < 49) sWc[t] = w[c * 49 + t];
    const __half* inb = in + (size_t)bc * HW;
    for (int e = t; e < 14 * 38; e += 256) {
        int row = e / 38, cc = e % 38;
        int h = h0 + row - 3, ww = w0 + cc - 3;
        float v = 0.f;
        if (h >= 0 && h < HDIM && ww >= 0 && ww < WDIM) v = __half2float(inb[h * WDIM + ww]);
        sT[e] = v;
    }
    __syncthreads();
    float acc = 0.f;
#pragma unroll
    for (int ky = 0; ky < 7; ky++)
#pragma unroll
        for (int kx = 0; kx < 7; kx++)
            acc += sT[(ty + ky) * 38 + tx + kx] * sWc[ky * 7 + kx];
    float sc = bng[c] * rsqrtf(bnv[c] + EPS);
    float sh = bnb[c] - bnm[c] * sc;
    int pix = (h0 + ty) * WDIM + w0 + tx;
    out[((size_t)(b * 128 + (c >> 1)) * HW + pix) * 2 + (c & 1)] = __float2half_rn(acc * sc + sh);
}

// ---------------- launch ------------------------------------------------------
extern "C" void kernel_launch(void* const* d_in, const int* in_sizes, int n_in,
                              void* d_out, int out_size)
{
    const float* x        = (const float*)d_in[0];
    const float* qkv_w    = (const float*)d_in[1];
    const float* local1_w = (const float*)d_in[2];
    const float* l1g = (const float*)d_in[3];
    const float* l1b = (const float*)d_in[4];
    const float* l1m = (const float*)d_in[5];
    const float* l1v = (const float*)d_in[6];
    const float* local2_w = (const float*)d_in[7];
    const float* l2g = (const float*)d_in[8];
    const float* l2b = (const float*)d_in[9];
    const float* l2m = (const float*)d_in[10];
    const float* l2v = (const float*)d_in[11];
    const float* rel_table = (const float*)d_in[12];
    const float* hybrid_w  = (const float*)d_in[13];
    const float* hybrid_b  = (const float*)d_in[14];
    const float* smooth_w  = (const float*)d_in[15];
    const float* smg = (const float*)d_in[16];
    const float* smb = (const float*)d_in[17];
    const float* smm = (const float*)d_in[18];
    const float* smv = (const float*)d_in[19];
    const float* proj_dw_w = (const float*)d_in[20];
    const float* prg = (const float*)d_in[21];
    const float* prb = (const float*)d_in[22];
    const float* prm = (const float*)d_in[23];
    const float* prv = (const float*)d_in[24];
    const float* proj_pw_w = (const float*)d_in[25];

    float *p_pool, *p_sig;
    __half *p_xh, *p_mixh, *p_dwh, *p_qkvh, *p_qhh, *p_khh, *p_lowh, *p_highh, *p_smh;
    __half *p_w5t, *p_w3t, *p_wq, *p_w2, *p_wp;
    cudaGetSymbolAddress((void**)&p_pool, g_pool);
    cudaGetSymbolAddress((void**)&p_sig,  g_sig);
    cudaGetSymbolAddress((void**)&p_xh,   g_xh);
    cudaGetSymbolAddress((void**)&p_mixh, g_mixh);
    cudaGetSymbolAddress((void**)&p_dwh,  g_dwh);
    cudaGetSymbolAddress((void**)&p_qkvh, g_qkvh);
    cudaGetSymbolAddress((void**)&p_qhh,  g_qhh);
    cudaGetSymbolAddress((void**)&p_khh,  g_khh);
    cudaGetSymbolAddress((void**)&p_lowh, g_lowh);
    cudaGetSymbolAddress((void**)&p_highh,g_highh);
    cudaGetSymbolAddress((void**)&p_smh,  g_smh);
    cudaGetSymbolAddress((void**)&p_w5t,  g_w5t);
    cudaGetSymbolAddress((void**)&p_w3t,  g_w3t);
    cudaGetSymbolAddress((void**)&p_wq,   g_wq);
    cudaGetSymbolAddress((void**)&p_w2,   g_w2);
    cudaGetSymbolAddress((void**)&p_wp,   g_wp);

    const int smem3 = 2 * (8 * 10 * 36 + 9  * 512) * 4;   // 59904 B
    const int smem5 = 2 * (8 * 12 * 38 + 25 * 512) * 4;   // 131584 B
    const int smemG = 2 * GEM_STG2 * 4;                   // 44032 B
    cudaFuncSetAttribute(conv_h<5, false, true>, cudaFuncAttributeMaxDynamicSharedMemorySize, smem5);
    cudaFuncSetAttribute(conv_h<3, true, false>, cudaFuncAttributeMaxDynamicSharedMemorySize, smem3);
    cudaFuncSetAttribute(gemm1x1_h<true>,  cudaFuncAttributeMaxDynamicSharedMemorySize, smemG);
    cudaFuncSetAttribute(gemm1x1_h<false>, cudaFuncAttributeMaxDynamicSharedMemorySize, smemG);

    // ---- pre-pass ----
    interleave_h<<<BDIM * 128 * HW / 256, 256>>>(x, p_xh);
    roundw_h<<<(3 * CDIM * CDIM + 255) / 256, 256>>>(qkv_w, p_wq, 3 * CDIM * CDIM);
    roundw_h<<<(CDIM * CDIM + 255) / 256, 256>>>(local2_w, p_w2, CDIM * CDIM);
    roundw_h<<<(CDIM * CDIM + 255) / 256, 256>>>(proj_pw_w, p_wp, CDIM * CDIM);
    wtransform_h<9><<<(CDIM * CDIM * 9 + 255) / 256, 256>>>(local1_w, p_w3t);
    wtransform_h<25><<<(CDIM * CDIM * 25 + 255) / 256, 256>>>(smooth_w, p_w5t);

    // ---- main chain ----
    gemm1x1_h<true><<<dim3(64, 12, 4), 256, smemG>>>(p_xh, p_wq, nullptr, nullptr, nullptr, nullptr,
                                                     p_qkvh, 768);
    gemm1x1_h<true><<<dim3(64, 4, 4), 256, smemG>>>(p_xh, p_w2, l2g, l2b, l2m, l2v, p_khh, 256);
    conv_h<3, true, false><<<dim3(4, 16, 16), 256, smem3>>>(p_xh, p_w3t, l1g, l1b, l1m, l1v,
                                                            p_qhh, p_khh, p_highh);
    attn_mma<<<dim3(256, 16, 4), 128>>>(p_qkvh, p_qhh, p_khh, rel_table, p_lowh);
    pool_kernel<<<dim3(256, 4), 256>>>(p_lowh, p_highh, p_pool);
    hybrid_kernel<<<dim3(4, 16, 4), dim3(32, 8)>>>(p_pool, hybrid_w, hybrid_b, p_sig);
    mix_h<<<BDIM * 128 * HW / 256, 256>>>(p_lowh, p_highh, p_sig, p_mixh);
    conv_h<5, false, true><<<dim3(4, 16, 16), 256, smem5>>>(p_mixh, p_w5t, smg, smb, smm, smv,
                                                            p_smh, nullptr, nullptr);
    dw_kernel<<<dim3(4, 16, 1024), dim3(32, 8)>>>(p_smh, proj_dw_w, prg, prb, prm, prv, p_dwh);
    gemm1x1_h<false><<<dim3(64, 4, 4), 256, smemG>>>(p_dwh, p_wp, nullptr, nullptr, nullptr, nullptr,
                                                     (float*)d_out, 256);
}